// round 2
// baseline (speedup 1.0000x reference)
#include <cuda_runtime.h>
#include <math.h>

#define Bn   4
#define Sn   2048
#define DIMn 1024
#define Hn   16
#define HDn  64
#define MBn  16
#define NMBn 128
#define NBn  11
#define NKN  15
#define EPSc 1e-6f

// ---------------- scratch (device globals; no allocation allowed) ----------------
__device__ float g_Q[Bn*Hn*Sn*HDn];     // [b,h,s,hd]
__device__ float g_K[Bn*Hn*Sn*HDn];
__device__ float g_V[Bn*Hn*Sn*HDn];
__device__ float g_eta[Bn*Hn*Sn];       // [b,h,s]  (gs folded in)
__device__ float g_y[Bn*Sn*DIMn];       // [b,s,dim]
__device__ float g_ln[Bn*Sn*DIMn];
__device__ float g_cs[Sn*32*2];         // cos/sin table
__device__ float g_co[256];             // spline poly coeffs [r][c][interval16]

// ---------------- setup: B-spline per-interval cubic polynomial coefficients ----
__global__ void coef_kernel(const float* __restrict__ knots) {
    int i = threadIdx.x;
    if (i >= 16) return;
    if (i >= 14) {   // padded intervals -> zero
        for (int r = 0; r < 4; r++)
            for (int c = 0; c < 4; c++)
                g_co[(r*4 + c)*16 + i] = 0.f;
        return;
    }
    float kn[15];
    for (int j = 0; j < 15; j++) kn[j] = knots[j];
    // symbolic dense Cox-de Boor on interval i: P[j] = poly of basis j
    float P[14][4];
    for (int j = 0; j < 14; j++)
        for (int c = 0; c < 4; c++) P[j][c] = 0.f;
    P[i][0] = 1.f;
    for (int k = 1; k <= 3; k++) {
        for (int j = 0; j + k < 14; j++) {
            float r1  = 1.f / (kn[j+k]   - kn[j]);
            float l0  = -kn[j] * r1,      l1 = r1;
            float r2i = 1.f / (kn[j+k+1] - kn[j+1]);
            float q0  = kn[j+k+1] * r2i,  q1 = -r2i;
            float nb[4];
            for (int c = 0; c < 4; c++) {
                float v = l0 * P[j][c] + q0 * P[j+1][c];
                if (c > 0) v += l1 * P[j][c-1] + q1 * P[j+1][c-1];
                nb[c] = v;
            }
            for (int c = 0; c < 4; c++) P[j][c] = nb[c];
        }
    }
    for (int r = 0; r < 4; r++) {
        int idx = i - 3 + r;
        for (int c = 0; c < 4; c++)
            g_co[(r*4 + c)*16 + i] = (idx >= 0 && idx <= 10) ? P[idx][c] : 0.f;
    }
}

// ---------------- setup: rope cos/sin table -------------------------------------
__global__ void cs_kernel(const float* __restrict__ pf) {
    int i = blockIdx.x * blockDim.x + threadIdx.x;
    if (i < Sn * 32) {
        float a = pf[i];
        g_cs[2*i]   = cosf(a);
        g_cs[2*i+1] = sinf(a);
    }
}

// ---------------- eta: per-token per-head learning rate -------------------------
__global__ void __launch_bounds__(128) eta_kernel(
    const float* __restrict__ x, const float* __restrict__ lrW,
    const float* __restrict__ lrb, const float* __restrict__ gsc)
{
    __shared__ float xs[1024];
    int t = blockIdx.x;
    const float* xr = x + (size_t)t * 1024;
    for (int i = threadIdx.x; i < 1024; i += 128) xs[i] = xr[i];
    __syncthreads();
    int w = threadIdx.x >> 5, lane = threadIdx.x & 31;
    int bb = t >> 11, s = t & 2047, k = s & 15;
    float g = 1.f / (float)(k + 1) + gsc[k];
    g = fmaxf(g, 0.f);
    for (int hh = 0; hh < 4; hh++) {
        int h = w * 4 + hh;
        const float* wr = lrW + h * 1024;
        float acc = 0.f;
        for (int j = lane; j < 1024; j += 32) acc += xs[j] * __ldg(wr + j);
        #pragma unroll
        for (int off = 16; off; off >>= 1) acc += __shfl_xor_sync(0xffffffffu, acc, off);
        if (lane == 0) {
            float v = 1.f / (1.f + __expf(-(acc + lrb[h])));
            g_eta[((size_t)(bb * Hn + h)) * Sn + s] = v * (1.f / 64.f) * g;
        }
    }
}

// ---------------- GEMM: out[t,o] = sum_d A[t,d]*W[o,d]; 128x128x8 tiles ---------
// mode 0: plain row-major write (final Wo GEMM -> d_out)
// mode 1: rope + scatter to [b,h,s,hd] layout
__global__ void __launch_bounds__(256) gemm_kernel(
    const float* __restrict__ A, const float* __restrict__ Wt,
    float* __restrict__ out, int mode)
{
    __shared__ float As[2][8][128];
    __shared__ float Bs[2][8][128];
    int tid = threadIdx.x;
    int bm = blockIdx.y, bnb = blockIdx.x;
    int lr = tid >> 1;            // 0..127 row in tile
    int lc = (tid & 1) * 4;       // k offset
    const float* Ag = A  + (size_t)(bm  * 128 + lr) * 1024 + lc;
    const float* Bg = Wt + (size_t)(bnb * 128 + lr) * 1024 + lc;
    int tx = tid & 15, ty = tid >> 4;
    float acc[8][8];
    #pragma unroll
    for (int i = 0; i < 8; i++)
        #pragma unroll
        for (int j = 0; j < 8; j++) acc[i][j] = 0.f;

    float4 a4 = *(const float4*)Ag;
    float4 b4 = *(const float4*)Bg;
    #pragma unroll
    for (int c = 0; c < 4; c++) {
        As[0][lc + c][lr] = ((float*)&a4)[c];
        Bs[0][lc + c][lr] = ((float*)&b4)[c];
    }
    __syncthreads();

    for (int kt = 0; kt < 128; kt++) {
        int nxt = kt + 1;
        float4 an, bn4;
        if (nxt < 128) {
            an  = *(const float4*)(Ag + nxt * 8);
            bn4 = *(const float4*)(Bg + nxt * 8);
        }
        int buf = kt & 1;
        #pragma unroll
        for (int kk = 0; kk < 8; kk++) {
            float av[8], bv[8];
            *(float4*)&av[0] = *(const float4*)&As[buf][kk][ty*8];
            *(float4*)&av[4] = *(const float4*)&As[buf][kk][ty*8 + 4];
            *(float4*)&bv[0] = *(const float4*)&Bs[buf][kk][tx*8];
            *(float4*)&bv[4] = *(const float4*)&Bs[buf][kk][tx*8 + 4];
            #pragma unroll
            for (int i = 0; i < 8; i++)
                #pragma unroll
                for (int j = 0; j < 8; j++)
                    acc[i][j] += av[i] * bv[j];
        }
        if (nxt < 128) {
            int nb = nxt & 1;
            #pragma unroll
            for (int c = 0; c < 4; c++) {
                As[nb][lc + c][lr] = ((float*)&an)[c];
                Bs[nb][lc + c][lr] = ((float*)&bn4)[c];
            }
        }
        __syncthreads();
    }

    if (mode == 0) {
        #pragma unroll
        for (int i = 0; i < 8; i++) {
            int t = bm * 128 + ty * 8 + i;
            #pragma unroll
            for (int j = 0; j < 8; j++) {
                int o = bnb * 128 + tx * 8 + j;
                out[(size_t)t * 1024 + o] = acc[i][j];
            }
        }
    } else {
        #pragma unroll
        for (int i = 0; i < 8; i++) {
            int t = bm * 128 + ty * 8 + i;
            int b = t >> 11, s = t & 2047;
            #pragma unroll
            for (int j = 0; j < 8; j += 2) {
                int o = bnb * 128 + tx * 8 + j;
                int h = o >> 6, hd = o & 63, jj = hd >> 1;
                float2 csv = *(const float2*)&g_cs[(s * 32 + jj) * 2];
                float v1 = acc[i][j], v2 = acc[i][j + 1];
                float* op = out + ((size_t)((b * Hn + h) * Sn + s)) * HDn + hd;
                op[0] = v1 * csv.x - v2 * csv.y;
                op[1] = v1 * csv.y + v2 * csv.x;
            }
        }
    }
}

// ---------------- scan helpers --------------------------------------------------
__device__ __forceinline__ void warpsum2(float& a, float& b) {
    #pragma unroll
    for (int off = 16; off; off >>= 1) {
        a += __shfl_xor_sync(0xffffffffu, a, off);
        b += __shfl_xor_sync(0xffffffffu, b, off);
    }
}
__device__ __forceinline__ float siluf(float x) {
    return x / (1.f + __expf(-x));
}
__device__ __forceinline__ void spline4(float x, const float* kn, const float* co,
                                        int& ib, float bas[4]) {
    int i = -1;
    #pragma unroll
    for (int j = 0; j < 15; j++) i += (x >= kn[j]) ? 1 : 0;
    bool valid = (i >= 0) && (i < 14);
    int ii = valid ? i : 0;
    float x2 = x * x, x3 = x2 * x;
    #pragma unroll
    for (int r = 0; r < 4; r++) {
        const float* c = co + r * 64 + ii;   // layout [(r*4+cidx)*16 + interval]
        float v = c[0] + c[16] * x + c[32] * x2 + c[48] * x3;
        bas[r] = valid ? v : 0.f;
    }
    ib = ii - 3;
}

// ---------------- the sequential TTT scan: 1 block per (b,h) --------------------
__global__ void __launch_bounds__(512) scan_kernel(
    const float* __restrict__ knots, const float* __restrict__ coefficients,
    const float* __restrict__ tgamma, const float* __restrict__ tbeta)
{
    __shared__ float Wsh[704];          // W[11][64]
    __shared__ float cum[16 * 704];     // tok/cumsum [m][n][d]
    __shared__ float kn[16];
    __shared__ float co[256];

    int bh = blockIdx.x;
    int b = bh >> 4, h = bh & 15;
    int tid = threadIdx.x, m = tid >> 5, lane = tid & 31;

    for (int e = tid; e < 704; e += 512) Wsh[e] = coefficients[h * 704 + e];
    if (tid < 15) kn[tid] = knots[tid];
    for (int e = tid; e < 256; e += 512) co[e] = g_co[e];

    int d0 = lane, d1 = lane + 32;
    float ga0 = tgamma[h * 64 + d0], ga1 = tgamma[h * 64 + d1];
    float be0 = tbeta[h * 64 + d0],  be1 = tbeta[h * 64 + d1];
    __syncthreads();

    const size_t bhS = (size_t)bh * Sn;

    for (int nmb = 0; nmb < NMBn; nmb++) {
        int s = nmb * 16 + m;
        size_t base = (bhS + s) * 64;
        float K0 = g_K[base + d0], K1 = g_K[base + d1];
        float V0 = g_V[base + d0], V1 = g_V[base + d1];
        float Q0 = g_Q[base + d0], Q1 = g_Q[base + d1];
        float et = g_eta[bhS + s];

        // ---- Phase A: Zk, LN-l2-bwd, tok ----
        int ib0, ib1; float bk0[4], bk1[4];
        spline4(K0, kn, co, ib0, bk0);
        spline4(K1, kn, co, ib1, bk1);
        float Zk0 = siluf(K0), Zk1 = siluf(K1);
        #pragma unroll
        for (int r = 0; r < 4; r++) {
            int i0 = min(max(ib0 + r, 0), 10);
            int i1 = min(max(ib1 + r, 0), 10);
            Zk0 += bk0[r] * Wsh[i0 * 64 + d0];
            Zk1 += bk1[r] * Wsh[i1 * 64 + d1];
        }
        float s1 = Zk0 + Zk1, s2 = Zk0 * Zk0 + Zk1 * Zk1;
        warpsum2(s1, s2);
        float mu = s1 * (1.f / 64.f);
        float var = s2 * (1.f / 64.f) - mu * mu;
        float rstd = rsqrtf(var + EPSc);
        float xh0 = (Zk0 - mu) * rstd, xh1 = (Zk1 - mu) * rstd;
        float gr0 = (ga0 * xh0 + be0 - (V0 - K0)) * ga0;
        float gr1 = (ga1 * xh1 + be1 - (V1 - K1)) * ga1;
        float t1 = gr0 + gr1, t2 = gr0 * xh0 + gr1 * xh1;
        warpsum2(t1, t2);
        float mg = t1 * (1.f / 64.f), mgx = t2 * (1.f / 64.f);
        float e0 = et * (gr0 - mg - xh0 * mgx) * rstd;
        float e1 = et * (gr1 - mg - xh1 * mgx) * rstd;

        float* cm = cum + m * 704;
        #pragma unroll
        for (int n = 0; n < 11; n++) {
            cm[n * 64 + d0] = 0.f;
            cm[n * 64 + d1] = 0.f;
        }
        #pragma unroll
        for (int r = 0; r < 4; r++) {
            int i0 = ib0 + r;
            if (i0 >= 0 && i0 <= 10) cm[i0 * 64 + d0] = bk0[r] * e0;
            int i1 = ib1 + r;
            if (i1 >= 0 && i1 <= 10) cm[i1 * 64 + d1] = bk1[r] * e1;
        }
        __syncthreads();

        // ---- Phase B: inclusive cumsum over m per (n,d) ----
        for (int e = tid; e < 704; e += 512) {
            float acc = 0.f;
            #pragma unroll
            for (int mm = 0; mm < 16; mm++) {
                acc += cum[mm * 704 + e];
                cum[mm * 704 + e] = acc;
            }
        }
        __syncthreads();

        // ---- Phase C: Zq, LN-fwd, output ----
        int iq0, iq1; float bq0[4], bq1[4];
        spline4(Q0, kn, co, iq0, bq0);
        spline4(Q1, kn, co, iq1, bq1);
        float Zq0 = siluf(Q0), Zq1 = siluf(Q1);
        #pragma unroll
        for (int r = 0; r < 4; r++) {
            int i0 = min(max(iq0 + r, 0), 10);
            int i1 = min(max(iq1 + r, 0), 10);
            Zq0 += bq0[r] * (Wsh[i0 * 64 + d0] - cm[i0 * 64 + d0]);
            Zq1 += bq1[r] * (Wsh[i1 * 64 + d1] - cm[i1 * 64 + d1]);
        }
        float u1 = Zq0 + Zq1, u2 = Zq0 * Zq0 + Zq1 * Zq1;
        warpsum2(u1, u2);
        float mu2 = u1 * (1.f / 64.f);
        float var2 = u2 * (1.f / 64.f) - mu2 * mu2;
        float rstd2 = rsqrtf(var2 + EPSc);
        float y0 = Q0 + ga0 * (Zq0 - mu2) * rstd2 + be0;
        float y1 = Q1 + ga1 * (Zq1 - mu2) * rstd2 + be1;
        float* yp = g_y + ((size_t)b * Sn + s) * DIMn + h * 64;
        yp[d0] = y0;
        yp[d1] = y1;
        __syncthreads();

        // ---- Phase D: W -= cum[15] ----
        for (int e = tid; e < 704; e += 512) Wsh[e] -= cum[15 * 704 + e];
        __syncthreads();
    }
}

// ---------------- post layernorm over DIM ---------------------------------------
__global__ void __launch_bounds__(256) postln_kernel(
    const float* __restrict__ pw, const float* __restrict__ pb)
{
    __shared__ float r1[8], r2[8];
    int t = blockIdx.x;
    const float* xr = g_y + (size_t)t * 1024;
    float* orow = g_ln + (size_t)t * 1024;
    int d = threadIdx.x * 4;
    float4 v = *(const float4*)(xr + d);
    float s1 = v.x + v.y + v.z + v.w;
    float s2 = v.x * v.x + v.y * v.y + v.z * v.z + v.w * v.w;
    #pragma unroll
    for (int off = 16; off; off >>= 1) {
        s1 += __shfl_xor_sync(0xffffffffu, s1, off);
        s2 += __shfl_xor_sync(0xffffffffu, s2, off);
    }
    int w = threadIdx.x >> 5, lane = threadIdx.x & 31;
    if (lane == 0) { r1[w] = s1; r2[w] = s2; }
    __syncthreads();
    float S1 = 0.f, S2 = 0.f;
    #pragma unroll
    for (int i = 0; i < 8; i++) { S1 += r1[i]; S2 += r2[i]; }
    float mu = S1 * (1.f / 1024.f);
    float var = S2 * (1.f / 1024.f) - mu * mu;
    float rstd = rsqrtf(var + EPSc);
    float4 w4 = *(const float4*)(pw + d);
    float4 b4 = *(const float4*)(pb + d);
    float4 o;
    o.x = (v.x - mu) * rstd * w4.x + b4.x;
    o.y = (v.y - mu) * rstd * w4.y + b4.y;
    o.z = (v.z - mu) * rstd * w4.z + b4.z;
    o.w = (v.w - mu) * rstd * w4.w + b4.w;
    *(float4*)(orow + d) = o;
}

// ---------------- launch --------------------------------------------------------
extern "C" void kernel_launch(void* const* d_in, const int* in_sizes, int n_in,
                              void* d_out, int out_size)
{
    const float* x     = (const float*)d_in[0];
    const float* pf    = (const float*)d_in[1];
    const float* Wq    = (const float*)d_in[2];
    const float* Wk    = (const float*)d_in[3];
    const float* Wv    = (const float*)d_in[4];
    const float* Wo    = (const float*)d_in[5];
    const float* lrW   = (const float*)d_in[6];
    const float* lrb   = (const float*)d_in[7];
    const float* gsc   = (const float*)d_in[8];
    const float* tg    = (const float*)d_in[9];
    const float* tb    = (const float*)d_in[10];
    const float* pw    = (const float*)d_in[11];
    const float* pb    = (const float*)d_in[12];
    const float* coefs = (const float*)d_in[13];
    const float* knots = (const float*)d_in[14];
    float* out = (float*)d_out;

    float *Qp, *Kp, *Vp, *lnp;
    cudaGetSymbolAddress((void**)&Qp,  g_Q);
    cudaGetSymbolAddress((void**)&Kp,  g_K);
    cudaGetSymbolAddress((void**)&Vp,  g_V);
    cudaGetSymbolAddress((void**)&lnp, g_ln);

    coef_kernel<<<1, 32>>>(knots);
    cs_kernel<<<(Sn * 32 + 255) / 256, 256>>>(pf);
    eta_kernel<<<Bn * Sn, 128>>>(x, lrW, lrb, gsc);

    dim3 gg(8, 64);
    gemm_kernel<<<gg, 256>>>(x, Wq, Qp, 1);
    gemm_kernel<<<gg, 256>>>(x, Wk, Kp, 1);
    gemm_kernel<<<gg, 256>>>(x, Wv, Vp, 1);

    scan_kernel<<<Bn * Hn, 512>>>(knots, coefs, tg, tb);

    postln_kernel<<<Bn * Sn, 256>>>(pw, pb);
    gemm_kernel<<<gg, 256>>>(lnp, Wo, out, 0);
}

// round 6
// speedup vs baseline: 1.8407x; 1.8407x over previous
#include <cuda_runtime.h>
#include <cuda_bf16.h>
#include <math.h>
#include <stdint.h>

#define Bn   4
#define Sn   2048
#define DIMn 1024
#define Hn   16
#define HDn  64
#define MBn  16
#define NMBn 128
#define NBn  11
#define EPSc 1e-6f
#define NTOK (Bn*Sn)              // 8192
#define NX   (Bn*Sn*DIMn)         // 8388608

// ---------------- scratch (device globals; no allocation allowed) ----------------
__device__ float g_Q[Bn*Hn*Sn*HDn];
__device__ float g_K[Bn*Hn*Sn*HDn];
__device__ float g_V[Bn*Hn*Sn*HDn];
__device__ float g_eta[Bn*Hn*Sn];
__device__ float g_y[NX];
__device__ float g_cs[Sn*32*2];
__device__ float g_co[256];
__device__ __nv_bfloat16 g_xh[NX];
__device__ __nv_bfloat16 g_xl[NX];
__device__ __nv_bfloat16 g_lh[NX];
__device__ __nv_bfloat16 g_ll[NX];
__device__ __nv_bfloat16 g_wh[4*DIMn*DIMn];
__device__ __nv_bfloat16 g_wl[4*DIMn*DIMn];

__device__ __forceinline__ uint32_t smem_u32(const void* p){
    uint32_t a;
    asm("{ .reg .u64 t; cvta.to.shared.u64 t, %1; cvt.u32.u64 %0, t; }" : "=r"(a) : "l"(p));
    return a;
}

// ---------------- setup: B-spline per-interval cubic poly coefficients ----------
__global__ void coef_kernel(const float* __restrict__ knots) {
    int i = threadIdx.x;
    if (i >= 16) return;
    if (i >= 14) {
        for (int r = 0; r < 4; r++)
            for (int c = 0; c < 4; c++)
                g_co[(r*4 + c)*16 + i] = 0.f;
        return;
    }
    float kn[15];
    for (int j = 0; j < 15; j++) kn[j] = knots[j];
    float P[14][4];
    for (int j = 0; j < 14; j++)
        for (int c = 0; c < 4; c++) P[j][c] = 0.f;
    P[i][0] = 1.f;
    for (int k = 1; k <= 3; k++) {
        for (int j = 0; j + k < 14; j++) {
            float r1  = 1.f / (kn[j+k]   - kn[j]);
            float l0  = -kn[j] * r1,      l1 = r1;
            float r2i = 1.f / (kn[j+k+1] - kn[j+1]);
            float q0  = kn[j+k+1] * r2i,  q1 = -r2i;
            float nb[4];
            for (int c = 0; c < 4; c++) {
                float v = l0 * P[j][c] + q0 * P[j+1][c];
                if (c > 0) v += l1 * P[j][c-1] + q1 * P[j+1][c-1];
                nb[c] = v;
            }
            for (int c = 0; c < 4; c++) P[j][c] = nb[c];
        }
    }
    for (int r = 0; r < 4; r++) {
        int idx = i - 3 + r;
        for (int c = 0; c < 4; c++)
            g_co[(r*4 + c)*16 + i] = (idx >= 0 && idx <= 10) ? P[idx][c] : 0.f;
    }
}

__global__ void cs_kernel(const float* __restrict__ pf) {
    int i = blockIdx.x * blockDim.x + threadIdx.x;
    if (i < Sn * 32) {
        float a = pf[i];
        g_cs[2*i]   = cosf(a);
        g_cs[2*i+1] = sinf(a);
    }
}

// ---------------- fp32 -> bf16 hi/lo split --------------------------------------
__global__ void __launch_bounds__(256) conv_kernel(
    const float* __restrict__ s, __nv_bfloat16* __restrict__ h,
    __nv_bfloat16* __restrict__ l, int n)
{
    int i = blockIdx.x * 256 + threadIdx.x;
    if (i < n) {
        float v = s[i];
        __nv_bfloat16 hh = __float2bfloat16(v);
        h[i] = hh;
        l[i] = __float2bfloat16(v - __bfloat162float(hh));
    }
}

// ---------------- eta ------------------------------------------------------------
__global__ void __launch_bounds__(128) eta_kernel(
    const float* __restrict__ x, const float* __restrict__ lrW,
    const float* __restrict__ lrb, const float* __restrict__ gsc)
{
    __shared__ float xs[1024];
    int t = blockIdx.x;
    const float* xr = x + (size_t)t * 1024;
    for (int i = threadIdx.x; i < 1024; i += 128) xs[i] = xr[i];
    __syncthreads();
    int w = threadIdx.x >> 5, lane = threadIdx.x & 31;
    int bb = t >> 11, s = t & 2047, k = s & 15;
    float g = 1.f / (float)(k + 1) + gsc[k];
    g = fmaxf(g, 0.f);
    for (int hh = 0; hh < 4; hh++) {
        int h = w * 4 + hh;
        const float* wr = lrW + h * 1024;
        float acc = 0.f;
        for (int j = lane; j < 1024; j += 32) acc += xs[j] * __ldg(wr + j);
        #pragma unroll
        for (int off = 16; off; off >>= 1) acc += __shfl_xor_sync(0xffffffffu, acc, off);
        if (lane == 0) {
            float v = 1.f / (1.f + __expf(-(acc + lrb[h])));
            g_eta[((size_t)(bb * Hn + h)) * Sn + s] = v * (1.f / 64.f) * g;
        }
    }
}

// ================= HMMA bf16x3 GEMM =============================================
// out[t,o] = sum_d A[t,d]*W[o,d] as AhBh + AhBl + AlBh in fp32 accumulators.
// 128x128 CTA tile, 8 warps (2x4 -> 64x32 warp tiles), BK=32, cp.async dbl-buf.
#define STRB   80                        // padded smem row stride bytes (40 bf16)
#define TILEB  (128*STRB)                // 10240 per tile
#define BUFB   (4*TILEB)                 // Ah,Al,Bh,Bl
#define MG_SMEM (2*BUFB)                 // 81920

__device__ __forceinline__ void ldmA(uint32_t r[4], uint32_t addr){
    asm volatile("ldmatrix.sync.aligned.m8n8.x4.shared.b16 {%0,%1,%2,%3}, [%4];"
        : "=r"(r[0]), "=r"(r[1]), "=r"(r[2]), "=r"(r[3]) : "r"(addr));
}
__device__ __forceinline__ void ldmB(uint32_t r[2], uint32_t addr){
    asm volatile("ldmatrix.sync.aligned.m8n8.x2.shared.b16 {%0,%1}, [%2];"
        : "=r"(r[0]), "=r"(r[1]) : "r"(addr));
}
__device__ __forceinline__ void mma16816(float c[4], const uint32_t a[4], const uint32_t b[2]){
    asm volatile("mma.sync.aligned.m16n8k16.row.col.f32.bf16.bf16.f32 "
        "{%0,%1,%2,%3}, {%4,%5,%6,%7}, {%8,%9}, {%0,%1,%2,%3};"
        : "+f"(c[0]), "+f"(c[1]), "+f"(c[2]), "+f"(c[3])
        : "r"(a[0]), "r"(a[1]), "r"(a[2]), "r"(a[3]), "r"(b[0]), "r"(b[1]));
}

__global__ void __launch_bounds__(256) mma_gemm(
    const __nv_bfloat16* __restrict__ Ah, const __nv_bfloat16* __restrict__ Al,
    const __nv_bfloat16* __restrict__ Bh, const __nv_bfloat16* __restrict__ Bl,
    float* __restrict__ out, int mode)
{
    extern __shared__ char sm[];
    int tid = threadIdx.x, wid = tid >> 5, lane = tid & 31;
    int bm = blockIdx.y, bn = blockIdx.x;
    int wm = wid >> 2, wn = wid & 3;

    const __nv_bfloat16* gsrc[4] = {Ah, Al, Bh, Bl};
    const int rb0 = bm * 128, rb1 = bn * 128;
    int rbase[4] = {rb0, rb0, rb1, rb1};

    float acc[4][4][4];
    #pragma unroll
    for (int mt = 0; mt < 4; mt++)
        #pragma unroll
        for (int nt = 0; nt < 4; nt++)
            #pragma unroll
            for (int k = 0; k < 4; k++) acc[mt][nt][k] = 0.f;

    // per-thread load coords: row tid>>2, 16B chunk tid&3
    int lrow = tid >> 2, lcol = tid & 3;

    uint32_t smb = smem_u32(sm);
    // A frag: threads 0-15 rows 0-15, threads 16-31 same rows +16B (k+8)
    uint32_t a_row = wm * 64 + (lane & 15);
    uint32_t a_coff = ((lane >> 4) & 1) * 16;    // bytes
    // B frag (non-trans): threads 0-7 rows n0-7 @k0-7, threads 8-15 same rows @+16B (k8-15)
    uint32_t b_row = wn * 32 + (lane & 7);
    uint32_t b_koff = ((lane >> 3) & 1) * 16;    // bytes

    #define ISSUE_LOADS(chunk, buf) do { \
        char* bufp = sm + (buf) * BUFB; \
        _Pragma("unroll") \
        for (int t4 = 0; t4 < 4; t4++) { \
            const __nv_bfloat16* src = gsrc[t4] + (size_t)(rbase[t4] + lrow) * 1024 \
                                      + (chunk) * 32 + lcol * 8; \
            uint32_t dst = smem_u32(bufp + t4 * TILEB + lrow * STRB + lcol * 16); \
            asm volatile("cp.async.cg.shared.global [%0], [%1], 16;" :: "r"(dst), "l"(src)); \
            src += 64 * 1024; \
            dst += 64 * STRB; \
            asm volatile("cp.async.cg.shared.global [%0], [%1], 16;" :: "r"(dst), "l"(src)); \
        } \
        asm volatile("cp.async.commit_group;"); \
    } while (0)

    ISSUE_LOADS(0, 0);

    for (int i = 0; i < 32; i++) {
        int buf = i & 1;
        __syncthreads();                       // everyone done with buf being refilled
        if (i + 1 < 32) {
            ISSUE_LOADS(i + 1, (i + 1) & 1);
            asm volatile("cp.async.wait_group 1;");
        } else {
            asm volatile("cp.async.wait_group 0;");
        }
        __syncthreads();                       // chunk i visible

        uint32_t base = smb + buf * BUFB;
        #pragma unroll
        for (int ks = 0; ks < 2; ks++) {
            uint32_t ahf[4][4], bhf[4][2], blf[4][2];
            #pragma unroll
            for (int mt = 0; mt < 4; mt++)
                ldmA(ahf[mt], base + (a_row + mt * 16) * STRB + ks * 32 + a_coff);
            #pragma unroll
            for (int nt = 0; nt < 4; nt++) {
                uint32_t ba = base + 2 * TILEB + (b_row + nt * 8) * STRB + ks * 32 + b_koff;
                ldmB(bhf[nt], ba);
                ldmB(blf[nt], ba + TILEB);
            }
            #pragma unroll
            for (int mt = 0; mt < 4; mt++)
                #pragma unroll
                for (int nt = 0; nt < 4; nt++) {
                    mma16816(acc[mt][nt], ahf[mt], bhf[nt]);
                    mma16816(acc[mt][nt], ahf[mt], blf[nt]);
                }
            uint32_t alf[4][4];
            #pragma unroll
            for (int mt = 0; mt < 4; mt++)
                ldmA(alf[mt], base + TILEB + (a_row + mt * 16) * STRB + ks * 32 + a_coff);
            #pragma unroll
            for (int mt = 0; mt < 4; mt++)
                #pragma unroll
                for (int nt = 0; nt < 4; nt++)
                    mma16816(acc[mt][nt], alf[mt], bhf[nt]);
        }
    }

    // -------- epilogue --------
    int r0 = lane >> 2, c0 = (lane & 3) * 2;
    #pragma unroll
    for (int mt = 0; mt < 4; mt++) {
        #pragma unroll
        for (int half = 0; half < 2; half++) {
            int t = bm * 128 + wm * 64 + mt * 16 + r0 + half * 8;
            int b = t >> 11, s = t & 2047;
            #pragma unroll
            for (int nt = 0; nt < 4; nt++) {
                float v1 = acc[mt][nt][half * 2];
                float v2 = acc[mt][nt][half * 2 + 1];
                int o = bn * 128 + wn * 32 + nt * 8 + c0;
                if (mode == 0) {
                    float2 w; w.x = v1; w.y = v2;
                    *(float2*)(out + (size_t)t * 1024 + o) = w;
                } else {
                    int h = o >> 6, hd = o & 63;
                    float2 cs = *(const float2*)&g_cs[(s * 32 + (hd >> 1)) * 2];
                    float2 w;
                    w.x = v1 * cs.x - v2 * cs.y;
                    w.y = v1 * cs.y + v2 * cs.x;
                    *(float2*)(out + ((size_t)((b * Hn + h) * Sn + s)) * 64 + hd) = w;
                }
            }
        }
    }
}

// ---------------- scan helpers --------------------------------------------------
__device__ __forceinline__ void warpsum2(float& a, float& b) {
    #pragma unroll
    for (int off = 16; off; off >>= 1) {
        a += __shfl_xor_sync(0xffffffffu, a, off);
        b += __shfl_xor_sync(0xffffffffu, b, off);
    }
}
__device__ __forceinline__ float siluf(float x) {
    return x / (1.f + __expf(-x));
}
__device__ __forceinline__ void spline4(float x, const float* kn, const float* co,
                                        int& ib, float bas[4]) {
    int i = -1;
    #pragma unroll
    for (int j = 0; j < 15; j++) i += (x >= kn[j]) ? 1 : 0;
    bool valid = (i >= 0) && (i < 14);
    int ii = valid ? i : 0;
    float x2 = x * x, x3 = x2 * x;
    #pragma unroll
    for (int r = 0; r < 4; r++) {
        const float* c = co + r * 64 + ii;
        float v = c[0] + c[16] * x + c[32] * x2 + c[48] * x3;
        bas[r] = valid ? v : 0.f;
    }
    ib = ii - 3;
}

// ---------------- sequential TTT scan: 1 block per (b,h) ------------------------
__global__ void __launch_bounds__(512) scan_kernel(
    const float* __restrict__ knots, const float* __restrict__ coefficients,
    const float* __restrict__ tgamma, const float* __restrict__ tbeta)
{
    __shared__ float Wsh[704];
    __shared__ float cum[16 * 704];
    __shared__ float kn[16];
    __shared__ float co[256];

    int bh = blockIdx.x;
    int b = bh >> 4, h = bh & 15;
    int tid = threadIdx.x, m = tid >> 5, lane = tid & 31;

    for (int e = tid; e < 704; e += 512) Wsh[e] = coefficients[h * 704 + e];
    if (tid < 15) kn[tid] = knots[tid];
    for (int e = tid; e < 256; e += 512) co[e] = g_co[e];

    int d0 = lane, d1 = lane + 32;
    float ga0 = tgamma[h * 64 + d0], ga1 = tgamma[h * 64 + d1];
    float be0 = tbeta[h * 64 + d0],  be1 = tbeta[h * 64 + d1];
    __syncthreads();

    const size_t bhS = (size_t)bh * Sn;

    for (int nmb = 0; nmb < NMBn; nmb++) {
        int s = nmb * 16 + m;
        size_t base = (bhS + s) * 64;
        float K0 = g_K[base + d0], K1 = g_K[base + d1];
        float V0 = g_V[base + d0], V1 = g_V[base + d1];
        float Q0 = g_Q[base + d0], Q1 = g_Q[base + d1];
        float et = g_eta[bhS + s];

        int ib0, ib1; float bk0[4], bk1[4];
        spline4(K0, kn, co, ib0, bk0);
        spline4(K1, kn, co, ib1, bk1);
        float Zk0 = siluf(K0), Zk1 = siluf(K1);
        #pragma unroll
        for (int r = 0; r < 4; r++) {
            int i0 = min(max(ib0 + r, 0), 10);
            int i1 = min(max(ib1 + r, 0), 10);
            Zk0 += bk0[r] * Wsh[i0 * 64 + d0];
            Zk1 += bk1[r] * Wsh[i1 * 64 + d1];
        }
        float s1 = Zk0 + Zk1, s2 = Zk0 * Zk0 + Zk1 * Zk1;
        warpsum2(s1, s2);
        float mu = s1 * (1.f / 64.f);
        float var = s2 * (1.f / 64.f) - mu * mu;
        float rstd = rsqrtf(var + EPSc);
        float xh0 = (Zk0 - mu) * rstd, xh1 = (Zk1 - mu) * rstd;
        float gr0 = (ga0 * xh0 + be0 - (V0 - K0)) * ga0;
        float gr1 = (ga1 * xh1 + be1 - (V1 - K1)) * ga1;
        float t1 = gr0 + gr1, t2 = gr0 * xh0 + gr1 * xh1;
        warpsum2(t1, t2);
        float mg = t1 * (1.f / 64.f), mgx = t2 * (1.f / 64.f);
        float e0 = et * (gr0 - mg - xh0 * mgx) * rstd;
        float e1 = et * (gr1 - mg - xh1 * mgx) * rstd;

        float* cm = cum + m * 704;
        #pragma unroll
        for (int n = 0; n < 11; n++) {
            cm[n * 64 + d0] = 0.f;
            cm[n * 64 + d1] = 0.f;
        }
        #pragma unroll
        for (int r = 0; r < 4; r++) {
            int i0 = ib0 + r;
            if (i0 >= 0 && i0 <= 10) cm[i0 * 64 + d0] = bk0[r] * e0;
            int i1 = ib1 + r;
            if (i1 >= 0 && i1 <= 10) cm[i1 * 64 + d1] = bk1[r] * e1;
        }
        __syncthreads();

        for (int e = tid; e < 704; e += 512) {
            float acc = 0.f;
            #pragma unroll
            for (int mm = 0; mm < 16; mm++) {
                acc += cum[mm * 704 + e];
                cum[mm * 704 + e] = acc;
            }
        }
        __syncthreads();

        int iq0, iq1; float bq0[4], bq1[4];
        spline4(Q0, kn, co, iq0, bq0);
        spline4(Q1, kn, co, iq1, bq1);
        float Zq0 = siluf(Q0), Zq1 = siluf(Q1);
        #pragma unroll
        for (int r = 0; r < 4; r++) {
            int i0 = min(max(iq0 + r, 0), 10);
            int i1 = min(max(iq1 + r, 0), 10);
            Zq0 += bq0[r] * (Wsh[i0 * 64 + d0] - cm[i0 * 64 + d0]);
            Zq1 += bq1[r] * (Wsh[i1 * 64 + d1] - cm[i1 * 64 + d1]);
        }
        float u1 = Zq0 + Zq1, u2 = Zq0 * Zq0 + Zq1 * Zq1;
        warpsum2(u1, u2);
        float mu2 = u1 * (1.f / 64.f);
        float var2 = u2 * (1.f / 64.f) - mu2 * mu2;
        float rstd2 = rsqrtf(var2 + EPSc);
        float y0 = Q0 + ga0 * (Zq0 - mu2) * rstd2 + be0;
        float y1 = Q1 + ga1 * (Zq1 - mu2) * rstd2 + be1;
        float* yp = g_y + ((size_t)b * Sn + s) * DIMn + h * 64;
        yp[d0] = y0;
        yp[d1] = y1;
        __syncthreads();

        for (int e = tid; e < 704; e += 512) Wsh[e] -= cum[15 * 704 + e];
        __syncthreads();
    }
}

// ---------------- post layernorm -> bf16 hi/lo ----------------------------------
__global__ void __launch_bounds__(256) postln_kernel(
    const float* __restrict__ pw, const float* __restrict__ pb)
{
    __shared__ float r1[8], r2[8];
    int t = blockIdx.x;
    const float* xr = g_y + (size_t)t * 1024;
    int d = threadIdx.x * 4;
    float4 v = *(const float4*)(xr + d);
    float s1 = v.x + v.y + v.z + v.w;
    float s2 = v.x * v.x + v.y * v.y + v.z * v.z + v.w * v.w;
    #pragma unroll
    for (int off = 16; off; off >>= 1) {
        s1 += __shfl_xor_sync(0xffffffffu, s1, off);
        s2 += __shfl_xor_sync(0xffffffffu, s2, off);
    }
    int w = threadIdx.x >> 5, lane = threadIdx.x & 31;
    if (lane == 0) { r1[w] = s1; r2[w] = s2; }
    __syncthreads();
    float S1 = 0.f, S2 = 0.f;
    #pragma unroll
    for (int i = 0; i < 8; i++) { S1 += r1[i]; S2 += r2[i]; }
    float mu = S1 * (1.f / 1024.f);
    float var = S2 * (1.f / 1024.f) - mu * mu;
    float rstd = rsqrtf(var + EPSc);
    float4 w4 = *(const float4*)(pw + d);
    float4 b4 = *(const float4*)(pb + d);
    float o[4];
    o[0] = (v.x - mu) * rstd * w4.x + b4.x;
    o[1] = (v.y - mu) * rstd * w4.y + b4.y;
    o[2] = (v.z - mu) * rstd * w4.z + b4.z;
    o[3] = (v.w - mu) * rstd * w4.w + b4.w;
    size_t ob = (size_t)t * 1024 + d;
    #pragma unroll
    for (int i = 0; i < 4; i++) {
        __nv_bfloat16 hh = __float2bfloat16(o[i]);
        g_lh[ob + i] = hh;
        g_ll[ob + i] = __float2bfloat16(o[i] - __bfloat162float(hh));
    }
}

// ---------------- launch --------------------------------------------------------
extern "C" void kernel_launch(void* const* d_in, const int* in_sizes, int n_in,
                              void* d_out, int out_size)
{
    const float* x     = (const float*)d_in[0];
    const float* pf    = (const float*)d_in[1];
    const float* Wq    = (const float*)d_in[2];
    const float* Wk    = (const float*)d_in[3];
    const float* Wv    = (const float*)d_in[4];
    const float* Wo    = (const float*)d_in[5];
    const float* lrW   = (const float*)d_in[6];
    const float* lrb   = (const float*)d_in[7];
    const float* gsc   = (const float*)d_in[8];
    const float* tg    = (const float*)d_in[9];
    const float* tb    = (const float*)d_in[10];
    const float* pw    = (const float*)d_in[11];
    const float* pb    = (const float*)d_in[12];
    const float* coefs = (const float*)d_in[13];
    const float* knots = (const float*)d_in[14];
    float* out = (float*)d_out;

    float *Qp, *Kp, *Vp;
    __nv_bfloat16 *xh, *xl, *wh, *wl, *lh, *ll;
    cudaGetSymbolAddress((void**)&Qp, g_Q);
    cudaGetSymbolAddress((void**)&Kp, g_K);
    cudaGetSymbolAddress((void**)&Vp, g_V);
    cudaGetSymbolAddress((void**)&xh, g_xh);
    cudaGetSymbolAddress((void**)&xl, g_xl);
    cudaGetSymbolAddress((void**)&wh, g_wh);
    cudaGetSymbolAddress((void**)&wl, g_wl);
    cudaGetSymbolAddress((void**)&lh, g_lh);
    cudaGetSymbolAddress((void**)&ll, g_ll);

    cudaFuncSetAttribute(mma_gemm, cudaFuncAttributeMaxDynamicSharedMemorySize,
                         MG_SMEM);

    coef_kernel<<<1, 32>>>(knots);
    cs_kernel<<<(Sn * 32 + 255) / 256, 256>>>(pf);

    conv_kernel<<<NX / 256, 256>>>(x, xh, xl, NX);
    const float* Ws[4] = {Wq, Wk, Wv, Wo};
    for (int i = 0; i < 4; i++)
        conv_kernel<<<(DIMn * DIMn) / 256, 256>>>(Ws[i], wh + (size_t)i * DIMn * DIMn,
                                                  wl + (size_t)i * DIMn * DIMn, DIMn * DIMn);

    eta_kernel<<<NTOK, 128>>>(x, lrW, lrb, gsc);

    dim3 gg(8, 64);
    mma_gemm<<<gg, 256, MG_SMEM>>>(xh, xl, wh + 0ul,                 wl + 0ul,                 Qp, 1);
    mma_gemm<<<gg, 256, MG_SMEM>>>(xh, xl, wh + (size_t)1*DIMn*DIMn, wl + (size_t)1*DIMn*DIMn, Kp, 1);
    mma_gemm<<<gg, 256, MG_SMEM>>>(xh, xl, wh + (size_t)2*DIMn*DIMn, wl + (size_t)2*DIMn*DIMn, Vp, 1);

    scan_kernel<<<Bn * Hn, 512>>>(knots, coefs, tg, tb);

    postln_kernel<<<NTOK, 256>>>(pw, pb);
    mma_gemm<<<gg, 256, MG_SMEM>>>(lh, ll, wh + (size_t)3*DIMn*DIMn,
                                   wl + (size_t)3*DIMn*DIMn, out, 0);
}

// round 9
// speedup vs baseline: 2.2080x; 1.1995x over previous
#include <cuda_runtime.h>
#include <cuda_bf16.h>
#include <math.h>
#include <stdint.h>

#define Bn   4
#define Sn   2048
#define DIMn 1024
#define Hn   16
#define HDn  64
#define MBn  16
#define NMBn 128
#define NBn  11
#define EPSc 1e-6f
#define NTOK (Bn*Sn)              // 8192
#define NX   (Bn*Sn*DIMn)         // 8388608
#define SZQ  (Bn*Hn*Sn*HDn)       // 8388608

// ---------------- scratch (device globals; no allocation allowed) ----------------
__device__ float g_QKV[3*SZQ];          // [mat][b,h,s,hd]
__device__ float g_eta[Bn*Hn*Sn];
__device__ float g_y[NX];
__device__ float g_cs[Sn*32*2];
__device__ float g_co[256];
__device__ __nv_bfloat16 g_xh[NX];
__device__ __nv_bfloat16 g_xl[NX];
__device__ __nv_bfloat16 g_lh[NX];
__device__ __nv_bfloat16 g_ll[NX];
__device__ __nv_bfloat16 g_wh[4*DIMn*DIMn];   // Wq,Wk,Wv,Wo hi
__device__ __nv_bfloat16 g_wl[4*DIMn*DIMn];   // lo

__device__ __forceinline__ uint32_t smem_u32(const void* p){
    uint32_t a;
    asm("{ .reg .u64 t; cvta.to.shared.u64 t, %1; cvt.u32.u64 %0, t; }" : "=r"(a) : "l"(p));
    return a;
}

// ---------------- setup: B-spline per-interval cubic poly coefficients ----------
__global__ void coef_kernel(const float* __restrict__ knots) {
    int i = threadIdx.x;
    if (i >= 16) return;
    if (i >= 14) {
        for (int r = 0; r < 4; r++)
            for (int c = 0; c < 4; c++)
                g_co[(r*4 + c)*16 + i] = 0.f;
        return;
    }
    float kn[15];
    for (int j = 0; j < 15; j++) kn[j] = knots[j];
    float P[14][4];
    for (int j = 0; j < 14; j++)
        for (int c = 0; c < 4; c++) P[j][c] = 0.f;
    P[i][0] = 1.f;
    for (int k = 1; k <= 3; k++) {
        for (int j = 0; j + k < 14; j++) {
            float r1  = 1.f / (kn[j+k]   - kn[j]);
            float l0  = -kn[j] * r1,      l1 = r1;
            float r2i = 1.f / (kn[j+k+1] - kn[j+1]);
            float q0  = kn[j+k+1] * r2i,  q1 = -r2i;
            float nb[4];
            for (int c = 0; c < 4; c++) {
                float v = l0 * P[j][c] + q0 * P[j+1][c];
                if (c > 0) v += l1 * P[j][c-1] + q1 * P[j+1][c-1];
                nb[c] = v;
            }
            for (int c = 0; c < 4; c++) P[j][c] = nb[c];
        }
    }
    for (int r = 0; r < 4; r++) {
        int idx = i - 3 + r;
        for (int c = 0; c < 4; c++)
            g_co[(r*4 + c)*16 + i] = (idx >= 0 && idx <= 10) ? P[idx][c] : 0.f;
    }
}

__global__ void cs_kernel(const float* __restrict__ pf) {
    int i = blockIdx.x * blockDim.x + threadIdx.x;
    if (i < Sn * 32) {
        float a = pf[i];
        g_cs[2*i]   = cosf(a);
        g_cs[2*i+1] = sinf(a);
    }
}

// ---------------- fp32 -> bf16 hi/lo split (vectorized) --------------------------
__global__ void __launch_bounds__(256) conv_kernel(
    const float* __restrict__ s, __nv_bfloat16* __restrict__ h,
    __nv_bfloat16* __restrict__ l, int n)
{
    int i = (blockIdx.x * 256 + threadIdx.x) * 4;
    if (i < n) {
        float4 v = *(const float4*)(s + i);
        __nv_bfloat16 hh[4], ll[4];
        float vv[4] = {v.x, v.y, v.z, v.w};
        #pragma unroll
        for (int j = 0; j < 4; j++) {
            hh[j] = __float2bfloat16(vv[j]);
            ll[j] = __float2bfloat16(vv[j] - __bfloat162float(hh[j]));
        }
        *(uint2*)(h + i) = *(uint2*)hh;
        *(uint2*)(l + i) = *(uint2*)ll;
    }
}

// ---------------- eta ------------------------------------------------------------
__global__ void __launch_bounds__(128) eta_kernel(
    const float* __restrict__ x, const float* __restrict__ lrW,
    const float* __restrict__ lrb, const float* __restrict__ gsc)
{
    __shared__ float xs[1024];
    int t = blockIdx.x;
    const float* xr = x + (size_t)t * 1024;
    for (int i = threadIdx.x; i < 1024; i += 128) xs[i] = xr[i];
    __syncthreads();
    int w = threadIdx.x >> 5, lane = threadIdx.x & 31;
    int bb = t >> 11, s = t & 2047, k = s & 15;
    float g = 1.f / (float)(k + 1) + gsc[k];
    g = fmaxf(g, 0.f);
    for (int hh = 0; hh < 4; hh++) {
        int h = w * 4 + hh;
        const float* wr = lrW + h * 1024;
        float acc = 0.f;
        for (int j = lane; j < 1024; j += 32) acc += xs[j] * __ldg(wr + j);
        #pragma unroll
        for (int off = 16; off; off >>= 1) acc += __shfl_xor_sync(0xffffffffu, acc, off);
        if (lane == 0) {
            float v = 1.f / (1.f + __expf(-(acc + lrb[h])));
            g_eta[((size_t)(bb * Hn + h)) * Sn + s] = v * (1.f / 64.f) * g;
        }
    }
}

// ================= HMMA bf16x3 GEMM =============================================
#define STRB   80
#define TILEB  (128*STRB)
#define BUFB   (4*TILEB)
#define MG_SMEM (2*BUFB)                 // 81920

__device__ __forceinline__ void ldmA(uint32_t r[4], uint32_t addr){
    asm volatile("ldmatrix.sync.aligned.m8n8.x4.shared.b16 {%0,%1,%2,%3}, [%4];"
        : "=r"(r[0]), "=r"(r[1]), "=r"(r[2]), "=r"(r[3]) : "r"(addr));
}
__device__ __forceinline__ void ldmB4(uint32_t r[4], uint32_t addr){
    asm volatile("ldmatrix.sync.aligned.m8n8.x4.shared.b16 {%0,%1,%2,%3}, [%4];"
        : "=r"(r[0]), "=r"(r[1]), "=r"(r[2]), "=r"(r[3]) : "r"(addr));
}
__device__ __forceinline__ void mma16816(float c[4], const uint32_t a[4], const uint32_t b[2]){
    asm volatile("mma.sync.aligned.m16n8k16.row.col.f32.bf16.bf16.f32 "
        "{%0,%1,%2,%3}, {%4,%5,%6,%7}, {%8,%9}, {%0,%1,%2,%3};"
        : "+f"(c[0]), "+f"(c[1]), "+f"(c[2]), "+f"(c[3])
        : "r"(a[0]), "r"(a[1]), "r"(a[2]), "r"(a[3]), "r"(b[0]), "r"(b[1]));
}

// mode 0: plain fp32 [t,1024] write.  mode 1: rope + scatter to g_QKV (out=QKV base,
// matrix selected by output column block: col/1024)
__global__ void __launch_bounds__(256, 2) mma_gemm(
    const __nv_bfloat16* __restrict__ Ah, const __nv_bfloat16* __restrict__ Al,
    const __nv_bfloat16* __restrict__ Bh, const __nv_bfloat16* __restrict__ Bl,
    float* __restrict__ out, int mode)
{
    extern __shared__ char sm[];
    int tid = threadIdx.x, wid = tid >> 5, lane = tid & 31;
    int bm = blockIdx.y, bn = blockIdx.x;
    int wm = wid >> 2, wn = wid & 3;

    float acc[4][4][4];
    #pragma unroll
    for (int mt = 0; mt < 4; mt++)
        #pragma unroll
        for (int nt = 0; nt < 4; nt++)
            #pragma unroll
            for (int k = 0; k < 4; k++) acc[mt][nt][k] = 0.f;

    int lrow = tid >> 2, lcol = tid & 3;
    const __nv_bfloat16* pAh = Ah + (size_t)(bm*128 + lrow) * 1024 + lcol * 8;
    const __nv_bfloat16* pAl = Al + (size_t)(bm*128 + lrow) * 1024 + lcol * 8;
    const __nv_bfloat16* pBh = Bh + (size_t)(bn*128 + lrow) * 1024 + lcol * 8;
    const __nv_bfloat16* pBl = Bl + (size_t)(bn*128 + lrow) * 1024 + lcol * 8;

    uint32_t smb = smem_u32(sm);
    uint32_t sdst = smb + lrow * STRB + lcol * 16;

    uint32_t a_row = wm * 64 + (lane & 15);
    uint32_t a_coff = ((lane >> 4) & 1) * 16;
    // B x4: lanes 0-7: n0-7 k0-7; 8-15: n0-7 k8-15; 16-23: n8-15 k0-7; 24-31: n8-15 k8-15
    uint32_t b_row = wn * 32 + (lane & 7) + (((lane >> 4) & 1) << 3);
    uint32_t b_koff = ((lane >> 3) & 1) * 16;

    #define ISSUE_LOADS(chunk, buf) do { \
        uint32_t d0_ = sdst + (buf) * BUFB; \
        const __nv_bfloat16* s0_; \
        s0_ = pAh + (chunk) * 32; \
        asm volatile("cp.async.cg.shared.global [%0], [%1], 16;" :: "r"(d0_), "l"(s0_)); \
        asm volatile("cp.async.cg.shared.global [%0], [%1], 16;" :: "r"(d0_ + 64*STRB), "l"(s0_ + 64*1024)); \
        s0_ = pAl + (chunk) * 32; \
        asm volatile("cp.async.cg.shared.global [%0], [%1], 16;" :: "r"(d0_ + TILEB), "l"(s0_)); \
        asm volatile("cp.async.cg.shared.global [%0], [%1], 16;" :: "r"(d0_ + TILEB + 64*STRB), "l"(s0_ + 64*1024)); \
        s0_ = pBh + (chunk) * 32; \
        asm volatile("cp.async.cg.shared.global [%0], [%1], 16;" :: "r"(d0_ + 2*TILEB), "l"(s0_)); \
        asm volatile("cp.async.cg.shared.global [%0], [%1], 16;" :: "r"(d0_ + 2*TILEB + 64*STRB), "l"(s0_ + 64*1024)); \
        s0_ = pBl + (chunk) * 32; \
        asm volatile("cp.async.cg.shared.global [%0], [%1], 16;" :: "r"(d0_ + 3*TILEB), "l"(s0_)); \
        asm volatile("cp.async.cg.shared.global [%0], [%1], 16;" :: "r"(d0_ + 3*TILEB + 64*STRB), "l"(s0_ + 64*1024)); \
        asm volatile("cp.async.commit_group;"); \
    } while (0)

    ISSUE_LOADS(0, 0);

    for (int i = 0; i < 32; i++) {
        int buf = i & 1;
        __syncthreads();
        if (i + 1 < 32) {
            ISSUE_LOADS(i + 1, (i + 1) & 1);
            asm volatile("cp.async.wait_group 1;");
        } else {
            asm volatile("cp.async.wait_group 0;");
        }
        __syncthreads();

        uint32_t base = smb + buf * BUFB;
        #pragma unroll
        for (int ks = 0; ks < 2; ks++) {
            uint32_t ahf[4][4], bhf[4][2], blf[4][2];
            #pragma unroll
            for (int mt = 0; mt < 4; mt++)
                ldmA(ahf[mt], base + (a_row + mt * 16) * STRB + ks * 32 + a_coff);
            #pragma unroll
            for (int np = 0; np < 2; np++) {
                uint32_t ba = base + 2 * TILEB + (b_row + np * 16) * STRB + ks * 32 + b_koff;
                uint32_t r4[4];
                ldmB4(r4, ba);
                bhf[np*2][0] = r4[0]; bhf[np*2][1] = r4[1];
                bhf[np*2+1][0] = r4[2]; bhf[np*2+1][1] = r4[3];
                ldmB4(r4, ba + TILEB);
                blf[np*2][0] = r4[0]; blf[np*2][1] = r4[1];
                blf[np*2+1][0] = r4[2]; blf[np*2+1][1] = r4[3];
            }
            #pragma unroll
            for (int mt = 0; mt < 4; mt++)
                #pragma unroll
                for (int nt = 0; nt < 4; nt++) {
                    mma16816(acc[mt][nt], ahf[mt], bhf[nt]);
                    mma16816(acc[mt][nt], ahf[mt], blf[nt]);
                }
            uint32_t alf[4][4];
            #pragma unroll
            for (int mt = 0; mt < 4; mt++)
                ldmA(alf[mt], base + TILEB + (a_row + mt * 16) * STRB + ks * 32 + a_coff);
            #pragma unroll
            for (int mt = 0; mt < 4; mt++)
                #pragma unroll
                for (int nt = 0; nt < 4; nt++)
                    mma16816(acc[mt][nt], alf[mt], bhf[nt]);
        }
    }

    // -------- epilogue --------
    int r0 = lane >> 2, c0 = (lane & 3) * 2;
    #pragma unroll
    for (int mt = 0; mt < 4; mt++) {
        #pragma unroll
        for (int half = 0; half < 2; half++) {
            int t = bm * 128 + wm * 64 + mt * 16 + r0 + half * 8;
            int b = t >> 11, s = t & 2047;
            #pragma unroll
            for (int nt = 0; nt < 4; nt++) {
                float v1 = acc[mt][nt][half * 2];
                float v2 = acc[mt][nt][half * 2 + 1];
                int o = bn * 128 + wn * 32 + nt * 8 + c0;
                if (mode == 0) {
                    float2 w; w.x = v1; w.y = v2;
                    *(float2*)(out + (size_t)t * 1024 + o) = w;
                } else {
                    int mat = o >> 10, oin = o & 1023;
                    int h = oin >> 6, hd = oin & 63;
                    float2 cs = *(const float2*)&g_cs[(s * 32 + (hd >> 1)) * 2];
                    float2 w;
                    w.x = v1 * cs.x - v2 * cs.y;
                    w.y = v1 * cs.y + v2 * cs.x;
                    *(float2*)(out + (size_t)mat * SZQ
                               + ((size_t)((b * Hn + h) * Sn + s)) * 64 + hd) = w;
                }
            }
        }
    }
}

// ---------------- scan helpers --------------------------------------------------
__device__ __forceinline__ void warpsum2(float& a, float& b) {
    #pragma unroll
    for (int off = 16; off; off >>= 1) {
        a += __shfl_xor_sync(0xffffffffu, a, off);
        b += __shfl_xor_sync(0xffffffffu, b, off);
    }
}
__device__ __forceinline__ float siluf(float x) {
    return x / (1.f + __expf(-x));
}
// uniform-knot interval + 4 basis values from per-interval cubic polys
__device__ __forceinline__ void spline4u(float x, float k0, float invh,
                                         const float* co, int& ib, float bas[4]) {
    int i = (int)floorf((x - k0) * invh);
    bool valid = (i >= 0) && (i < 14);
    int ii = valid ? i : 0;
    float x2 = x * x, x3 = x2 * x;
    #pragma unroll
    for (int r = 0; r < 4; r++) {
        const float* c = co + r * 64 + ii;
        float v = c[0] + c[16] * x + c[32] * x2 + c[48] * x3;
        bas[r] = valid ? v : 0.f;
    }
    ib = ii - 3;
}

// ---------------- sequential TTT scan: 1 block per (b,h) ------------------------
__global__ void __launch_bounds__(512) scan_kernel(
    const float* __restrict__ knots, const float* __restrict__ coefficients,
    const float* __restrict__ tgamma, const float* __restrict__ tbeta)
{
    __shared__ float Wsh[704];
    __shared__ float cum[16 * 704];
    __shared__ float co[256];

    const float* Qg = g_QKV;
    const float* Kg = g_QKV + SZQ;
    const float* Vg = g_QKV + 2*SZQ;

    int bh = blockIdx.x;
    int b = bh >> 4, h = bh & 15;
    int tid = threadIdx.x, m = tid >> 5, lane = tid & 31;

    for (int e = tid; e < 704; e += 512) Wsh[e] = coefficients[h * 704 + e];
    for (int e = tid; e < 256; e += 512) co[e] = g_co[e];

    float k0 = knots[0];
    float invh = 1.f / (knots[1] - knots[0]);

    int d0 = lane, d1 = lane + 32;
    float ga0 = tgamma[h * 64 + d0], ga1 = tgamma[h * 64 + d1];
    float be0 = tbeta[h * 64 + d0],  be1 = tbeta[h * 64 + d1];
    __syncthreads();

    const size_t bhS = (size_t)bh * Sn;
    const float* cm15 = cum + 15 * 704;

    // prime the pipeline: loads for first minibatch
    int s = m;
    size_t base = (bhS + s) * 64;
    float K0 = Kg[base + d0], K1 = Kg[base + d1];
    float V0 = Vg[base + d0], V1 = Vg[base + d1];
    float Q0 = Qg[base + d0], Q1 = Qg[base + d1];
    float et = g_eta[bhS + s];

    for (int nmb = 0; nmb < NMBn; nmb++) {
        // ---- prefetch next minibatch ----
        float nK0 = 0.f, nK1 = 0.f, nV0 = 0.f, nV1 = 0.f, nQ0 = 0.f, nQ1 = 0.f, nEt = 0.f;
        if (nmb + 1 < NMBn) {
            size_t nb = (bhS + s + 16) * 64;
            nK0 = Kg[nb + d0]; nK1 = Kg[nb + d1];
            nV0 = Vg[nb + d0]; nV1 = Vg[nb + d1];
            nQ0 = Qg[nb + d0]; nQ1 = Qg[nb + d1];
            nEt = g_eta[bhS + s + 16];
        }

        // ---- Phase A: Zk, LN-l2-bwd, tok ----
        int ib0, ib1; float bk0[4], bk1[4];
        spline4u(K0, k0, invh, co, ib0, bk0);
        spline4u(K1, k0, invh, co, ib1, bk1);
        float Zk0 = siluf(K0), Zk1 = siluf(K1);
        #pragma unroll
        for (int r = 0; r < 4; r++) {
            int i0 = min(max(ib0 + r, 0), 10);
            int i1 = min(max(ib1 + r, 0), 10);
            Zk0 += bk0[r] * Wsh[i0 * 64 + d0];
            Zk1 += bk1[r] * Wsh[i1 * 64 + d1];
        }
        float s1 = Zk0 + Zk1, s2 = Zk0 * Zk0 + Zk1 * Zk1;
        warpsum2(s1, s2);
        float mu = s1 * (1.f / 64.f);
        float var = s2 * (1.f / 64.f) - mu * mu;
        float rstd = rsqrtf(var + EPSc);
        float xh0 = (Zk0 - mu) * rstd, xh1 = (Zk1 - mu) * rstd;
        float gr0 = (ga0 * xh0 + be0 - (V0 - K0)) * ga0;
        float gr1 = (ga1 * xh1 + be1 - (V1 - K1)) * ga1;
        float t1 = gr0 + gr1, t2 = gr0 * xh0 + gr1 * xh1;
        warpsum2(t1, t2);
        float mg = t1 * (1.f / 64.f), mgx = t2 * (1.f / 64.f);
        float e0 = et * (gr0 - mg - xh0 * mgx) * rstd;
        float e1 = et * (gr1 - mg - xh1 * mgx) * rstd;

        float* cm = cum + m * 704;
        #pragma unroll
        for (int n = 0; n < 11; n++) {
            cm[n * 64 + d0] = 0.f;
            cm[n * 64 + d1] = 0.f;
        }
        #pragma unroll
        for (int r = 0; r < 4; r++) {
            int i0 = ib0 + r;
            if (i0 >= 0 && i0 <= 10) cm[i0 * 64 + d0] = bk0[r] * e0;
            int i1 = ib1 + r;
            if (i1 >= 0 && i1 <= 10) cm[i1 * 64 + d1] = bk1[r] * e1;
        }
        __syncthreads();

        // ---- Phase B: inclusive cumsum over m, fused W update ----
        for (int e = tid; e < 704; e += 512) {
            float acc = 0.f;
            #pragma unroll
            for (int mm = 0; mm < 16; mm++) {
                acc += cum[mm * 704 + e];
                cum[mm * 704 + e] = acc;
            }
            Wsh[e] -= acc;           // W_new = W_old - cum[15]
        }
        __syncthreads();

        // ---- Phase C: Zq with W_old - cum[m] = Wsh_new + cum15 - cum[m] ----
        int iq0, iq1; float bq0[4], bq1[4];
        spline4u(Q0, k0, invh, co, iq0, bq0);
        spline4u(Q1, k0, invh, co, iq1, bq1);
        float Zq0 = siluf(Q0), Zq1 = siluf(Q1);
        #pragma unroll
        for (int r = 0; r < 4; r++) {
            int i0 = min(max(iq0 + r, 0), 10);
            int i1 = min(max(iq1 + r, 0), 10);
            int e0i = i0 * 64 + d0, e1i = i1 * 64 + d1;
            Zq0 += bq0[r] * (Wsh[e0i] + cm15[e0i] - cm[e0i]);
            Zq1 += bq1[r] * (Wsh[e1i] + cm15[e1i] - cm[e1i]);
        }
        float u1 = Zq0 + Zq1, u2 = Zq0 * Zq0 + Zq1 * Zq1;
        warpsum2(u1, u2);
        float mu2 = u1 * (1.f / 64.f);
        float var2 = u2 * (1.f / 64.f) - mu2 * mu2;
        float rstd2 = rsqrtf(var2 + EPSc);
        float y0 = Q0 + ga0 * (Zq0 - mu2) * rstd2 + be0;
        float y1 = Q1 + ga1 * (Zq1 - mu2) * rstd2 + be1;
        float* yp = g_y + ((size_t)b * Sn + s) * DIMn + h * 64;
        yp[d0] = y0;
        yp[d1] = y1;
        __syncthreads();

        K0 = nK0; K1 = nK1; V0 = nV0; V1 = nV1; Q0 = nQ0; Q1 = nQ1; et = nEt;
        s += 16;
    }
}

// ---------------- post layernorm -> bf16 hi/lo ----------------------------------
__global__ void __launch_bounds__(256) postln_kernel(
    const float* __restrict__ pw, const float* __restrict__ pb)
{
    __shared__ float r1[8], r2[8];
    int t = blockIdx.x;
    const float* xr = g_y + (size_t)t * 1024;
    int d = threadIdx.x * 4;
    float4 v = *(const float4*)(xr + d);
    float s1 = v.x + v.y + v.z + v.w;
    float s2 = v.x * v.x + v.y * v.y + v.z * v.z + v.w * v.w;
    #pragma unroll
    for (int off = 16; off; off >>= 1) {
        s1 += __shfl_xor_sync(0xffffffffu, s1, off);
        s2 += __shfl_xor_sync(0xffffffffu, s2, off);
    }
    int w = threadIdx.x >> 5, lane = threadIdx.x & 31;
    if (lane == 0) { r1[w] = s1; r2[w] = s2; }
    __syncthreads();
    float S1 = 0.f, S2 = 0.f;
    #pragma unroll
    for (int i = 0; i < 8; i++) { S1 += r1[i]; S2 += r2[i]; }
    float mu = S1 * (1.f / 1024.f);
    float var = S2 * (1.f / 1024.f) - mu * mu;
    float rstd = rsqrtf(var + EPSc);
    float4 w4 = *(const float4*)(pw + d);
    float4 b4 = *(const float4*)(pb + d);
    float o[4];
    o[0] = (v.x - mu) * rstd * w4.x + b4.x;
    o[1] = (v.y - mu) * rstd * w4.y + b4.y;
    o[2] = (v.z - mu) * rstd * w4.z + b4.z;
    o[3] = (v.w - mu) * rstd * w4.w + b4.w;
    size_t ob = (size_t)t * 1024 + d;
    __nv_bfloat16 hh[4], ll[4];
    #pragma unroll
    for (int i = 0; i < 4; i++) {
        hh[i] = __float2bfloat16(o[i]);
        ll[i] = __float2bfloat16(o[i] - __bfloat162float(hh[i]));
    }
    *(uint2*)(g_lh + ob) = *(uint2*)hh;
    *(uint2*)(g_ll + ob) = *(uint2*)ll;
}

// ---------------- launch --------------------------------------------------------
extern "C" void kernel_launch(void* const* d_in, const int* in_sizes, int n_in,
                              void* d_out, int out_size)
{
    const float* x     = (const float*)d_in[0];
    const float* pf    = (const float*)d_in[1];
    const float* Wq    = (const float*)d_in[2];
    const float* Wk    = (const float*)d_in[3];
    const float* Wv    = (const float*)d_in[4];
    const float* Wo    = (const float*)d_in[5];
    const float* lrW   = (const float*)d_in[6];
    const float* lrb   = (const float*)d_in[7];
    const float* gsc   = (const float*)d_in[8];
    const float* tg    = (const float*)d_in[9];
    const float* tb    = (const float*)d_in[10];
    const float* pw    = (const float*)d_in[11];
    const float* pb    = (const float*)d_in[12];
    const float* coefs = (const float*)d_in[13];
    const float* knots = (const float*)d_in[14];
    float* out = (float*)d_out;

    float *QKVp;
    __nv_bfloat16 *xh, *xl, *wh, *wl, *lh, *ll;
    cudaGetSymbolAddress((void**)&QKVp, g_QKV);
    cudaGetSymbolAddress((void**)&xh, g_xh);
    cudaGetSymbolAddress((void**)&xl, g_xl);
    cudaGetSymbolAddress((void**)&wh, g_wh);
    cudaGetSymbolAddress((void**)&wl, g_wl);
    cudaGetSymbolAddress((void**)&lh, g_lh);
    cudaGetSymbolAddress((void**)&ll, g_ll);

    cudaFuncSetAttribute(mma_gemm, cudaFuncAttributeMaxDynamicSharedMemorySize,
                         MG_SMEM);

    coef_kernel<<<1, 32>>>(knots);
    cs_kernel<<<(Sn * 32 + 255) / 256, 256>>>(pf);

    conv_kernel<<<NX / 1024, 256>>>(x, xh, xl, NX);
    const float* Ws[4] = {Wq, Wk, Wv, Wo};
    for (int i = 0; i < 4; i++)
        conv_kernel<<<(DIMn * DIMn) / 1024, 256>>>(Ws[i], wh + (size_t)i * DIMn * DIMn,
                                                   wl + (size_t)i * DIMn * DIMn, DIMn * DIMn);

    eta_kernel<<<NTOK, 128>>>(x, lrW, lrb, gsc);

    // fused QKV GEMM: B = concatenated [3072 x 1024] weights, out -> g_QKV
    dim3 gq(24, 64);
    mma_gemm<<<gq, 256, MG_SMEM>>>(xh, xl, wh, wl, QKVp, 1);

    scan_kernel<<<Bn * Hn, 512>>>(knots, coefs, tg, tb);

    postln_kernel<<<NTOK, 256>>>(pw, pb);
    dim3 go(8, 64);
    mma_gemm<<<go, 256, MG_SMEM>>>(lh, ll, wh + (size_t)3*DIMn*DIMn,
                                   wl + (size_t)3*DIMn*DIMn, out, 0);
}

// round 11
// speedup vs baseline: 2.6904x; 1.2185x over previous
#include <cuda_runtime.h>
#include <cuda_fp16.h>
#include <math.h>
#include <stdint.h>

#define Bn   4
#define Sn   2048
#define DIMn 1024
#define Hn   16
#define HDn  64
#define MBn  16
#define NMBn 128
#define NBn  11
#define EPSc 1e-6f
#define NTOK (Bn*Sn)              // 8192
#define NX   (Bn*Sn*DIMn)         // 8388608
#define SZQ  (Bn*Hn*Sn*HDn)       // 8388608

// ---------------- scratch (device globals; no allocation allowed) ----------------
__device__ float g_QKV[3*SZQ];          // [mat][b,h,s,hd]
__device__ float g_eta[Bn*Hn*Sn];
__device__ float g_y[NX];
__device__ float g_cs[Sn*32*2];
__device__ float g_co[256];
__device__ __half g_xh[NX];
__device__ __half g_xl[NX];
__device__ __half g_lh[NX];
__device__ __half g_ll[NX];
__device__ __half g_wh[4*DIMn*DIMn];    // Wq,Wk,Wv,Wo (fp16 hi only)

__device__ __forceinline__ uint32_t smem_u32(const void* p){
    uint32_t a;
    asm("{ .reg .u64 t; cvta.to.shared.u64 t, %1; cvt.u32.u64 %0, t; }" : "=r"(a) : "l"(p));
    return a;
}

// ---------------- setup: B-spline per-interval cubic poly coefficients ----------
__global__ void coef_kernel(const float* __restrict__ knots) {
    int i = threadIdx.x;
    if (i >= 16) return;
    if (i >= 14) {
        for (int r = 0; r < 4; r++)
            for (int c = 0; c < 4; c++)
                g_co[(r*4 + c)*16 + i] = 0.f;
        return;
    }
    float kn[15];
    for (int j = 0; j < 15; j++) kn[j] = knots[j];
    float P[14][4];
    for (int j = 0; j < 14; j++)
        for (int c = 0; c < 4; c++) P[j][c] = 0.f;
    P[i][0] = 1.f;
    for (int k = 1; k <= 3; k++) {
        for (int j = 0; j + k < 14; j++) {
            float r1  = 1.f / (kn[j+k]   - kn[j]);
            float l0  = -kn[j] * r1,      l1 = r1;
            float r2i = 1.f / (kn[j+k+1] - kn[j+1]);
            float q0  = kn[j+k+1] * r2i,  q1 = -r2i;
            float nb[4];
            for (int c = 0; c < 4; c++) {
                float v = l0 * P[j][c] + q0 * P[j+1][c];
                if (c > 0) v += l1 * P[j][c-1] + q1 * P[j+1][c-1];
                nb[c] = v;
            }
            for (int c = 0; c < 4; c++) P[j][c] = nb[c];
        }
    }
    for (int r = 0; r < 4; r++) {
        int idx = i - 3 + r;
        for (int c = 0; c < 4; c++)
            g_co[(r*4 + c)*16 + i] = (idx >= 0 && idx <= 10) ? P[idx][c] : 0.f;
    }
}

__global__ void cs_kernel(const float* __restrict__ pf) {
    int i = blockIdx.x * blockDim.x + threadIdx.x;
    if (i < Sn * 32) {
        float a = pf[i];
        g_cs[2*i]   = cosf(a);
        g_cs[2*i+1] = sinf(a);
    }
}

// ---------------- fp32 -> fp16 hi/lo split --------------------------------------
__global__ void __launch_bounds__(256) conv2_kernel(
    const float* __restrict__ s, __half* __restrict__ h,
    __half* __restrict__ l, int n)
{
    int i = (blockIdx.x * 256 + threadIdx.x) * 4;
    if (i < n) {
        float4 v = *(const float4*)(s + i);
        float vv[4] = {v.x, v.y, v.z, v.w};
        __half hh[4], ll[4];
        #pragma unroll
        for (int j = 0; j < 4; j++) {
            hh[j] = __float2half(vv[j]);
            ll[j] = __float2half(vv[j] - __half2float(hh[j]));
        }
        *(uint2*)(h + i) = *(uint2*)hh;
        *(uint2*)(l + i) = *(uint2*)ll;
    }
}

// fp32 -> fp16 (hi only, for weights)
__global__ void __launch_bounds__(256) conv1_kernel(
    const float* __restrict__ s, __half* __restrict__ h, int n)
{
    int i = (blockIdx.x * 256 + threadIdx.x) * 4;
    if (i < n) {
        float4 v = *(const float4*)(s + i);
        __half hh[4];
        hh[0] = __float2half(v.x); hh[1] = __float2half(v.y);
        hh[2] = __float2half(v.z); hh[3] = __float2half(v.w);
        *(uint2*)(h + i) = *(uint2*)hh;
    }
}

// ---------------- eta ------------------------------------------------------------
__global__ void __launch_bounds__(128) eta_kernel(
    const float* __restrict__ x, const float* __restrict__ lrW,
    const float* __restrict__ lrb, const float* __restrict__ gsc)
{
    __shared__ float xs[1024];
    int t = blockIdx.x;
    const float* xr = x + (size_t)t * 1024;
    for (int i = threadIdx.x; i < 1024; i += 128) xs[i] = xr[i];
    __syncthreads();
    int w = threadIdx.x >> 5, lane = threadIdx.x & 31;
    int bb = t >> 11, s = t & 2047, k = s & 15;
    float g = 1.f / (float)(k + 1) + gsc[k];
    g = fmaxf(g, 0.f);
    for (int hh = 0; hh < 4; hh++) {
        int h = w * 4 + hh;
        const float* wr = lrW + h * 1024;
        float acc = 0.f;
        for (int j = lane; j < 1024; j += 32) acc += xs[j] * __ldg(wr + j);
        #pragma unroll
        for (int off = 16; off; off >>= 1) acc += __shfl_xor_sync(0xffffffffu, acc, off);
        if (lane == 0) {
            float v = 1.f / (1.f + __expf(-(acc + lrb[h])));
            g_eta[((size_t)(bb * Hn + h)) * Sn + s] = v * (1.f / 64.f) * g;
        }
    }
}

// ================= HMMA fp16x2 GEMM =============================================
// out[t,o] = sum_d A[t,d]*W[o,d] as AhBh + AlBh in fp32 accumulators
// (A split fp16 hi/lo, B single fp16; dropped A*Bl term ~2^-11 relative).
// 128x128 CTA tile, 8 warps (2x4 -> 64x32 warp tiles), BK=32, cp.async dbl-buf.
#define STRB   80
#define TILEB  (128*STRB)                // 10240
#define BUFB   (3*TILEB)                 // Ah, Al, Bh
#define MG_SMEM (2*BUFB)                 // 61440

__device__ __forceinline__ void ldmA(uint32_t r[4], uint32_t addr){
    asm volatile("ldmatrix.sync.aligned.m8n8.x4.shared.b16 {%0,%1,%2,%3}, [%4];"
        : "=r"(r[0]), "=r"(r[1]), "=r"(r[2]), "=r"(r[3]) : "r"(addr));
}
__device__ __forceinline__ void ldmB4(uint32_t r[4], uint32_t addr){
    asm volatile("ldmatrix.sync.aligned.m8n8.x4.shared.b16 {%0,%1,%2,%3}, [%4];"
        : "=r"(r[0]), "=r"(r[1]), "=r"(r[2]), "=r"(r[3]) : "r"(addr));
}
__device__ __forceinline__ void mma16816(float c[4], const uint32_t a[4], const uint32_t b[2]){
    asm volatile("mma.sync.aligned.m16n8k16.row.col.f32.f16.f16.f32 "
        "{%0,%1,%2,%3}, {%4,%5,%6,%7}, {%8,%9}, {%0,%1,%2,%3};"
        : "+f"(c[0]), "+f"(c[1]), "+f"(c[2]), "+f"(c[3])
        : "r"(a[0]), "r"(a[1]), "r"(a[2]), "r"(a[3]), "r"(b[0]), "r"(b[1]));
}

// mode 0: plain fp32 [t,1024] write.  mode 1: rope + scatter to g_QKV
__global__ void __launch_bounds__(256, 2) mma_gemm(
    const __half* __restrict__ Ah, const __half* __restrict__ Al,
    const __half* __restrict__ Bh,
    float* __restrict__ out, int mode)
{
    extern __shared__ char sm[];
    int tid = threadIdx.x, wid = tid >> 5, lane = tid & 31;
    int bm = blockIdx.y, bn = blockIdx.x;
    int wm = wid >> 2, wn = wid & 3;

    float acc[4][4][4];
    #pragma unroll
    for (int mt = 0; mt < 4; mt++)
        #pragma unroll
        for (int nt = 0; nt < 4; nt++)
            #pragma unroll
            for (int k = 0; k < 4; k++) acc[mt][nt][k] = 0.f;

    int lrow = tid >> 2, lcol = tid & 3;
    const __half* pAh = Ah + (size_t)(bm*128 + lrow) * 1024 + lcol * 8;
    const __half* pAl = Al + (size_t)(bm*128 + lrow) * 1024 + lcol * 8;
    const __half* pBh = Bh + (size_t)(bn*128 + lrow) * 1024 + lcol * 8;

    uint32_t smb = smem_u32(sm);
    uint32_t sdst = smb + lrow * STRB + lcol * 16;

    uint32_t a_row = wm * 64 + (lane & 15);
    uint32_t a_coff = ((lane >> 4) & 1) * 16;
    uint32_t b_row = wn * 32 + (lane & 7) + (((lane >> 4) & 1) << 3);
    uint32_t b_koff = ((lane >> 3) & 1) * 16;

    #define ISSUE_LOADS(chunk, buf) do { \
        uint32_t d0_ = sdst + (buf) * BUFB; \
        const __half* s0_; \
        s0_ = pAh + (chunk) * 32; \
        asm volatile("cp.async.cg.shared.global [%0], [%1], 16;" :: "r"(d0_), "l"(s0_)); \
        asm volatile("cp.async.cg.shared.global [%0], [%1], 16;" :: "r"(d0_ + 64*STRB), "l"(s0_ + 64*1024)); \
        s0_ = pAl + (chunk) * 32; \
        asm volatile("cp.async.cg.shared.global [%0], [%1], 16;" :: "r"(d0_ + TILEB), "l"(s0_)); \
        asm volatile("cp.async.cg.shared.global [%0], [%1], 16;" :: "r"(d0_ + TILEB + 64*STRB), "l"(s0_ + 64*1024)); \
        s0_ = pBh + (chunk) * 32; \
        asm volatile("cp.async.cg.shared.global [%0], [%1], 16;" :: "r"(d0_ + 2*TILEB), "l"(s0_)); \
        asm volatile("cp.async.cg.shared.global [%0], [%1], 16;" :: "r"(d0_ + 2*TILEB + 64*STRB), "l"(s0_ + 64*1024)); \
        asm volatile("cp.async.commit_group;"); \
    } while (0)

    ISSUE_LOADS(0, 0);

    for (int i = 0; i < 32; i++) {
        int buf = i & 1;
        __syncthreads();
        if (i + 1 < 32) {
            ISSUE_LOADS(i + 1, (i + 1) & 1);
            asm volatile("cp.async.wait_group 1;");
        } else {
            asm volatile("cp.async.wait_group 0;");
        }
        __syncthreads();

        uint32_t base = smb + buf * BUFB;
        #pragma unroll
        for (int ks = 0; ks < 2; ks++) {
            uint32_t ahf[4][4], bhf[4][2];
            #pragma unroll
            for (int mt = 0; mt < 4; mt++)
                ldmA(ahf[mt], base + (a_row + mt * 16) * STRB + ks * 32 + a_coff);
            #pragma unroll
            for (int np = 0; np < 2; np++) {
                uint32_t ba = base + 2 * TILEB + (b_row + np * 16) * STRB + ks * 32 + b_koff;
                uint32_t r4[4];
                ldmB4(r4, ba);
                bhf[np*2][0] = r4[0]; bhf[np*2][1] = r4[1];
                bhf[np*2+1][0] = r4[2]; bhf[np*2+1][1] = r4[3];
            }
            #pragma unroll
            for (int mt = 0; mt < 4; mt++)
                #pragma unroll
                for (int nt = 0; nt < 4; nt++)
                    mma16816(acc[mt][nt], ahf[mt], bhf[nt]);
            uint32_t alf[4][4];
            #pragma unroll
            for (int mt = 0; mt < 4; mt++)
                ldmA(alf[mt], base + TILEB + (a_row + mt * 16) * STRB + ks * 32 + a_coff);
            #pragma unroll
            for (int mt = 0; mt < 4; mt++)
                #pragma unroll
                for (int nt = 0; nt < 4; nt++)
                    mma16816(acc[mt][nt], alf[mt], bhf[nt]);
        }
    }

    // -------- epilogue --------
    int r0 = lane >> 2, c0 = (lane & 3) * 2;
    #pragma unroll
    for (int mt = 0; mt < 4; mt++) {
        #pragma unroll
        for (int half = 0; half < 2; half++) {
            int t = bm * 128 + wm * 64 + mt * 16 + r0 + half * 8;
            int b = t >> 11, s = t & 2047;
            #pragma unroll
            for (int nt = 0; nt < 4; nt++) {
                float v1 = acc[mt][nt][half * 2];
                float v2 = acc[mt][nt][half * 2 + 1];
                int o = bn * 128 + wn * 32 + nt * 8 + c0;
                if (mode == 0) {
                    float2 w; w.x = v1; w.y = v2;
                    *(float2*)(out + (size_t)t * 1024 + o) = w;
                } else {
                    int mat = o >> 10, oin = o & 1023;
                    int h = oin >> 6, hd = oin & 63;
                    float2 cs = *(const float2*)&g_cs[(s * 32 + (hd >> 1)) * 2];
                    float2 w;
                    w.x = v1 * cs.x - v2 * cs.y;
                    w.y = v1 * cs.y + v2 * cs.x;
                    *(float2*)(out + (size_t)mat * SZQ
                               + ((size_t)((b * Hn + h) * Sn + s)) * 64 + hd) = w;
                }
            }
        }
    }
}

// ---------------- scan helpers --------------------------------------------------
__device__ __forceinline__ void warpsum2(float& a, float& b) {
    #pragma unroll
    for (int off = 16; off; off >>= 1) {
        a += __shfl_xor_sync(0xffffffffu, a, off);
        b += __shfl_xor_sync(0xffffffffu, b, off);
    }
}
__device__ __forceinline__ float siluf(float x) {
    return x / (1.f + __expf(-x));
}
__device__ __forceinline__ void spline4u(float x, float k0, float invh,
                                         const float* co, int& ib, float bas[4]) {
    int i = (int)floorf((x - k0) * invh);
    bool valid = (i >= 0) && (i < 14);
    int ii = valid ? i : 0;
    float x2 = x * x, x3 = x2 * x;
    #pragma unroll
    for (int r = 0; r < 4; r++) {
        const float* c = co + r * 64 + ii;
        float v = c[0] + c[16] * x + c[32] * x2 + c[48] * x3;
        bas[r] = valid ? v : 0.f;
    }
    ib = ii - 3;
}

// ---------------- sequential TTT scan: 1 block per (b,h) ------------------------
// dynamic smem: Wsh[704] | co[256] | cum[2][16*704]  (double-buffered -> 2 barriers/iter)
#define SCAN_SMEM ((704 + 256 + 2*16*704) * 4)

__global__ void __launch_bounds__(512) scan_kernel(
    const float* __restrict__ knots, const float* __restrict__ coefficients,
    const float* __restrict__ tgamma, const float* __restrict__ tbeta)
{
    extern __shared__ float smem[];
    float* Wsh = smem;              // 704
    float* co  = smem + 704;        // 256
    float* cumA = smem + 960;       // 2 buffers of 16*704

    const float* Qg = g_QKV;
    const float* Kg = g_QKV + SZQ;
    const float* Vg = g_QKV + 2*SZQ;

    int bh = blockIdx.x;
    int b = bh >> 4, h = bh & 15;
    int tid = threadIdx.x, m = tid >> 5, lane = tid & 31;

    for (int e = tid; e < 704; e += 512) Wsh[e] = coefficients[h * 704 + e];
    for (int e = tid; e < 256; e += 512) co[e] = g_co[e];

    float k0 = knots[0];
    float invh = 1.f / (knots[1] - knots[0]);

    int d0 = lane, d1 = lane + 32;
    float ga0 = tgamma[h * 64 + d0], ga1 = tgamma[h * 64 + d1];
    float be0 = tbeta[h * 64 + d0],  be1 = tbeta[h * 64 + d1];
    __syncthreads();

    const size_t bhS = (size_t)bh * Sn;

    int s = m;
    size_t base = (bhS + s) * 64;
    float K0 = Kg[base + d0], K1 = Kg[base + d1];
    float V0 = Vg[base + d0], V1 = Vg[base + d1];
    float Q0 = Qg[base + d0], Q1 = Qg[base + d1];
    float et = g_eta[bhS + s];

    for (int nmb = 0; nmb < NMBn; nmb++) {
        int buf = nmb & 1;
        float* cumB = cumA + buf * (16 * 704);
        float* cm   = cumB + m * 704;
        const float* cm15 = cumB + 15 * 704;

        // ---- prefetch next minibatch ----
        float nK0 = 0.f, nK1 = 0.f, nV0 = 0.f, nV1 = 0.f, nQ0 = 0.f, nQ1 = 0.f, nEt = 0.f;
        if (nmb + 1 < NMBn) {
            size_t nb = (bhS + s + 16) * 64;
            nK0 = Kg[nb + d0]; nK1 = Kg[nb + d1];
            nV0 = Vg[nb + d0]; nV1 = Vg[nb + d1];
            nQ0 = Qg[nb + d0]; nQ1 = Qg[nb + d1];
            nEt = g_eta[bhS + s + 16];
        }

        // ---- Phase A: Zk, LN-l2-bwd, tok ----
        int ib0, ib1; float bk0[4], bk1[4];
        spline4u(K0, k0, invh, co, ib0, bk0);
        spline4u(K1, k0, invh, co, ib1, bk1);
        float Zk0 = siluf(K0), Zk1 = siluf(K1);
        #pragma unroll
        for (int r = 0; r < 4; r++) {
            int i0 = min(max(ib0 + r, 0), 10);
            int i1 = min(max(ib1 + r, 0), 10);
            Zk0 += bk0[r] * Wsh[i0 * 64 + d0];
            Zk1 += bk1[r] * Wsh[i1 * 64 + d1];
        }
        float s1 = Zk0 + Zk1, s2 = Zk0 * Zk0 + Zk1 * Zk1;
        warpsum2(s1, s2);
        float mu = s1 * (1.f / 64.f);
        float var = s2 * (1.f / 64.f) - mu * mu;
        float rstd = rsqrtf(var + EPSc);
        float xh0 = (Zk0 - mu) * rstd, xh1 = (Zk1 - mu) * rstd;
        float gr0 = (ga0 * xh0 + be0 - (V0 - K0)) * ga0;
        float gr1 = (ga1 * xh1 + be1 - (V1 - K1)) * ga1;
        float t1 = gr0 + gr1, t2 = gr0 * xh0 + gr1 * xh1;
        warpsum2(t1, t2);
        float mg = t1 * (1.f / 64.f), mgx = t2 * (1.f / 64.f);
        float e0 = et * (gr0 - mg - xh0 * mgx) * rstd;
        float e1 = et * (gr1 - mg - xh1 * mgx) * rstd;

        #pragma unroll
        for (int n = 0; n < 11; n++) {
            cm[n * 64 + d0] = 0.f;
            cm[n * 64 + d1] = 0.f;
        }
        #pragma unroll
        for (int r = 0; r < 4; r++) {
            int i0 = ib0 + r;
            if (i0 >= 0 && i0 <= 10) cm[i0 * 64 + d0] = bk0[r] * e0;
            int i1 = ib1 + r;
            if (i1 >= 0 && i1 <= 10) cm[i1 * 64 + d1] = bk1[r] * e1;
        }
        __syncthreads();               // A writes -> B reads

        // ---- Phase B: inclusive cumsum over m, fused W update ----
        for (int e = tid; e < 704; e += 512) {
            float acc = 0.f;
            #pragma unroll
            for (int mm = 0; mm < 16; mm++) {
                acc += cumB[mm * 704 + e];
                cumB[mm * 704 + e] = acc;
            }
            Wsh[e] -= acc;
        }
        __syncthreads();               // B writes -> C reads

        // ---- Phase C: Zq with W_old - cum[m] = Wsh_new + cum15 - cum[m] ----
        int iq0, iq1; float bq0[4], bq1[4];
        spline4u(Q0, k0, invh, co, iq0, bq0);
        spline4u(Q1, k0, invh, co, iq1, bq1);
        float Zq0 = siluf(Q0), Zq1 = siluf(Q1);
        #pragma unroll
        for (int r = 0; r < 4; r++) {
            int i0 = min(max(iq0 + r, 0), 10);
            int i1 = min(max(iq1 + r, 0), 10);
            int e0i = i0 * 64 + d0, e1i = i1 * 64 + d1;
            Zq0 += bq0[r] * (Wsh[e0i] + cm15[e0i] - cm[e0i]);
            Zq1 += bq1[r] * (Wsh[e1i] + cm15[e1i] - cm[e1i]);
        }
        float u1 = Zq0 + Zq1, u2 = Zq0 * Zq0 + Zq1 * Zq1;
        warpsum2(u1, u2);
        float mu2 = u1 * (1.f / 64.f);
        float var2 = u2 * (1.f / 64.f) - mu2 * mu2;
        float rstd2 = rsqrtf(var2 + EPSc);
        float y0 = Q0 + ga0 * (Zq0 - mu2) * rstd2 + be0;
        float y1 = Q1 + ga1 * (Zq1 - mu2) * rstd2 + be1;
        float* yp = g_y + ((size_t)b * Sn + s) * DIMn + h * 64;
        yp[d0] = y0;
        yp[d1] = y1;
        // no barrier: next phase A writes the other cum buffer; the A->B
        // barrier next iteration orders this C's Wsh reads before B's writes.

        K0 = nK0; K1 = nK1; V0 = nV0; V1 = nV1; Q0 = nQ0; Q1 = nQ1; et = nEt;
        s += 16;
    }
}

// ---------------- post layernorm -> fp16 hi/lo ----------------------------------
__global__ void __launch_bounds__(256) postln_kernel(
    const float* __restrict__ pw, const float* __restrict__ pb)
{
    __shared__ float r1[8], r2[8];
    int t = blockIdx.x;
    const float* xr = g_y + (size_t)t * 1024;
    int d = threadIdx.x * 4;
    float4 v = *(const float4*)(xr + d);
    float s1 = v.x + v.y + v.z + v.w;
    float s2 = v.x * v.x + v.y * v.y + v.z * v.z + v.w * v.w;
    #pragma unroll
    for (int off = 16; off; off >>= 1) {
        s1 += __shfl_xor_sync(0xffffffffu, s1, off);
        s2 += __shfl_xor_sync(0xffffffffu, s2, off);
    }
    int w = threadIdx.x >> 5, lane = threadIdx.x & 31;
    if (lane == 0) { r1[w] = s1; r2[w] = s2; }
    __syncthreads();
    float S1 = 0.f, S2 = 0.f;
    #pragma unroll
    for (int i = 0; i < 8; i++) { S1 += r1[i]; S2 += r2[i]; }
    float mu = S1 * (1.f / 1024.f);
    float var = S2 * (1.f / 1024.f) - mu * mu;
    float rstd = rsqrtf(var + EPSc);
    float4 w4 = *(const float4*)(pw + d);
    float4 b4 = *(const float4*)(pb + d);
    float o[4];
    o[0] = (v.x - mu) * rstd * w4.x + b4.x;
    o[1] = (v.y - mu) * rstd * w4.y + b4.y;
    o[2] = (v.z - mu) * rstd * w4.z + b4.z;
    o[3] = (v.w - mu) * rstd * w4.w + b4.w;
    size_t ob = (size_t)t * 1024 + d;
    __half hh[4], ll[4];
    #pragma unroll
    for (int i = 0; i < 4; i++) {
        hh[i] = __float2half(o[i]);
        ll[i] = __float2half(o[i] - __half2float(hh[i]));
    }
    *(uint2*)(g_lh + ob) = *(uint2*)hh;
    *(uint2*)(g_ll + ob) = *(uint2*)ll;
}

// ---------------- launch --------------------------------------------------------
extern "C" void kernel_launch(void* const* d_in, const int* in_sizes, int n_in,
                              void* d_out, int out_size)
{
    const float* x     = (const float*)d_in[0];
    const float* pf    = (const float*)d_in[1];
    const float* Wq    = (const float*)d_in[2];
    const float* Wk    = (const float*)d_in[3];
    const float* Wv    = (const float*)d_in[4];
    const float* Wo    = (const float*)d_in[5];
    const float* lrW   = (const float*)d_in[6];
    const float* lrb   = (const float*)d_in[7];
    const float* gsc   = (const float*)d_in[8];
    const float* tg    = (const float*)d_in[9];
    const float* tb    = (const float*)d_in[10];
    const float* pw    = (const float*)d_in[11];
    const float* pb    = (const float*)d_in[12];
    const float* coefs = (const float*)d_in[13];
    const float* knots = (const float*)d_in[14];
    float* out = (float*)d_out;

    float *QKVp;
    __half *xh, *xl, *wh, *lh, *ll;
    cudaGetSymbolAddress((void**)&QKVp, g_QKV);
    cudaGetSymbolAddress((void**)&xh, g_xh);
    cudaGetSymbolAddress((void**)&xl, g_xl);
    cudaGetSymbolAddress((void**)&wh, g_wh);
    cudaGetSymbolAddress((void**)&lh, g_lh);
    cudaGetSymbolAddress((void**)&ll, g_ll);

    cudaFuncSetAttribute(mma_gemm, cudaFuncAttributeMaxDynamicSharedMemorySize,
                         MG_SMEM);
    cudaFuncSetAttribute(scan_kernel, cudaFuncAttributeMaxDynamicSharedMemorySize,
                         SCAN_SMEM);

    coef_kernel<<<1, 32>>>(knots);
    cs_kernel<<<(Sn * 32 + 255) / 256, 256>>>(pf);

    conv2_kernel<<<NX / 1024, 256>>>(x, xh, xl, NX);
    const float* Ws[4] = {Wq, Wk, Wv, Wo};
    for (int i = 0; i < 4; i++)
        conv1_kernel<<<(DIMn * DIMn) / 1024, 256>>>(Ws[i], wh + (size_t)i * DIMn * DIMn,
                                                    DIMn * DIMn);

    eta_kernel<<<NTOK, 128>>>(x, lrW, lrb, gsc);

    // fused QKV GEMM: B = concatenated [3072 x 1024] weights, out -> g_QKV
    dim3 gq(24, 64);
    mma_gemm<<<gq, 256, MG_SMEM>>>(xh, xl, wh, QKVp, 1);

    scan_kernel<<<Bn * Hn, 512, SCAN_SMEM>>>(knots, coefs, tg, tb);

    postln_kernel<<<NTOK, 256>>>(pw, pb);
    dim3 go(8, 64);
    mma_gemm<<<go, 256, MG_SMEM>>>(lh, ll, wh + (size_t)3*DIMn*DIMn, out, 0);
}

// round 12
// speedup vs baseline: 2.8462x; 1.0579x over previous
#include <cuda_runtime.h>
#include <cuda_fp16.h>
#include <math.h>
#include <stdint.h>

#define Bn   4
#define Sn   2048
#define DIMn 1024
#define Hn   16
#define HDn  64
#define MBn  16
#define NMBn 128
#define NBn  11
#define EPSc 1e-6f
#define NTOK (Bn*Sn)              // 8192
#define NX   (Bn*Sn*DIMn)         // 8388608
#define SZQ  (Bn*Hn*Sn*HDn)       // 8388608

// ---------------- scratch (device globals; no allocation allowed) ----------------
__device__ float g_QKV[3*SZQ];          // [mat][b,h,s,hd]
__device__ float g_eta[Bn*Hn*Sn];
__device__ float g_y[NX];
__device__ float g_cs[Sn*32*2];
__device__ float g_co[256];
__device__ __half g_xh[NX];             // x single fp16
__device__ __half g_lh[NX];             // ln out single fp16
__device__ __half g_wh[4*DIMn*DIMn];    // weights hi
__device__ __half g_wl[4*DIMn*DIMn];    // weights lo

__device__ __forceinline__ uint32_t smem_u32(const void* p){
    uint32_t a;
    asm("{ .reg .u64 t; cvta.to.shared.u64 t, %1; cvt.u32.u64 %0, t; }" : "=r"(a) : "l"(p));
    return a;
}

// ---------------- fused setup: x conv1 | weights conv2 | cos/sin | spline coefs --
// grid: [0,8192) x-conv, [8192,12288) weight-conv, [12288,12544) cs, 12544 coef
__global__ void __launch_bounds__(256) setup_kernel(
    const float* __restrict__ x,
    const float* __restrict__ W0, const float* __restrict__ W1,
    const float* __restrict__ W2, const float* __restrict__ W3,
    const float* __restrict__ pf, const float* __restrict__ knots)
{
    int b = blockIdx.x;
    if (b < 8192) {
        int i = b * 1024 + threadIdx.x * 4;
        float4 v = *(const float4*)(x + i);
        __half hh[4];
        hh[0] = __float2half(v.x); hh[1] = __float2half(v.y);
        hh[2] = __float2half(v.z); hh[3] = __float2half(v.w);
        *(uint2*)(g_xh + i) = *(uint2*)hh;
    } else if (b < 12288) {
        int r = b - 8192;
        int wi = r >> 10;
        const float* W = (wi == 0) ? W0 : (wi == 1) ? W1 : (wi == 2) ? W2 : W3;
        int off = (r & 1023) * 1024 + threadIdx.x * 4;
        float4 v = *(const float4*)(W + off);
        float vv[4] = {v.x, v.y, v.z, v.w};
        __half hh[4], ll[4];
        #pragma unroll
        for (int j = 0; j < 4; j++) {
            hh[j] = __float2half(vv[j]);
            ll[j] = __float2half(vv[j] - __half2float(hh[j]));
        }
        size_t o = (size_t)wi * DIMn * DIMn + off;
        *(uint2*)(g_wh + o) = *(uint2*)hh;
        *(uint2*)(g_wl + o) = *(uint2*)ll;
    } else if (b < 12544) {
        int i = (b - 12288) * 256 + threadIdx.x;
        float a = pf[i];
        g_cs[2*i]   = cosf(a);
        g_cs[2*i+1] = sinf(a);
    } else {
        int i = threadIdx.x;
        if (i >= 16) return;
        if (i >= 14) {
            for (int r = 0; r < 4; r++)
                for (int c = 0; c < 4; c++)
                    g_co[(r*4 + c)*16 + i] = 0.f;
            return;
        }
        float kn[15];
        for (int j = 0; j < 15; j++) kn[j] = knots[j];
        float P[14][4];
        for (int j = 0; j < 14; j++)
            for (int c = 0; c < 4; c++) P[j][c] = 0.f;
        P[i][0] = 1.f;
        for (int k = 1; k <= 3; k++) {
            for (int j = 0; j + k < 14; j++) {
                float r1  = 1.f / (kn[j+k]   - kn[j]);
                float l0  = -kn[j] * r1,      l1 = r1;
                float r2i = 1.f / (kn[j+k+1] - kn[j+1]);
                float q0  = kn[j+k+1] * r2i,  q1 = -r2i;
                float nb[4];
                for (int c = 0; c < 4; c++) {
                    float v = l0 * P[j][c] + q0 * P[j+1][c];
                    if (c > 0) v += l1 * P[j][c-1] + q1 * P[j+1][c-1];
                    nb[c] = v;
                }
                for (int c = 0; c < 4; c++) P[j][c] = nb[c];
            }
        }
        for (int r = 0; r < 4; r++) {
            int idx = i - 3 + r;
            for (int c = 0; c < 4; c++)
                g_co[(r*4 + c)*16 + i] = (idx >= 0 && idx <= 10) ? P[idx][c] : 0.f;
        }
    }
}

// ---------------- eta ------------------------------------------------------------
__global__ void __launch_bounds__(128) eta_kernel(
    const float* __restrict__ x, const float* __restrict__ lrW,
    const float* __restrict__ lrb, const float* __restrict__ gsc)
{
    __shared__ float xs[1024];
    int t = blockIdx.x;
    const float* xr = x + (size_t)t * 1024;
    for (int i = threadIdx.x; i < 1024; i += 128) xs[i] = xr[i];
    __syncthreads();
    int w = threadIdx.x >> 5, lane = threadIdx.x & 31;
    int bb = t >> 11, s = t & 2047, k = s & 15;
    float g = 1.f / (float)(k + 1) + gsc[k];
    g = fmaxf(g, 0.f);
    for (int hh = 0; hh < 4; hh++) {
        int h = w * 4 + hh;
        const float* wr = lrW + h * 1024;
        float acc = 0.f;
        for (int j = lane; j < 1024; j += 32) acc += xs[j] * __ldg(wr + j);
        #pragma unroll
        for (int off = 16; off; off >>= 1) acc += __shfl_xor_sync(0xffffffffu, acc, off);
        if (lane == 0) {
            float v = 1.f / (1.f + __expf(-(acc + lrb[h])));
            g_eta[((size_t)(bb * Hn + h)) * Sn + s] = v * (1.f / 64.f) * g;
        }
    }
}

// ================= HMMA fp16x2 GEMM (split-B) ===================================
// out[t,o] = sum_d A[t,d]*W[o,d] as A*Bh + A*Bl, A single fp16, B split hi/lo.
#define STRB   80
#define TILEB  (128*STRB)                // 10240
#define BUFB   (3*TILEB)                 // A, Bh, Bl
#define MG_SMEM (2*BUFB)                 // 61440

__device__ __forceinline__ void ldmA(uint32_t r[4], uint32_t addr){
    asm volatile("ldmatrix.sync.aligned.m8n8.x4.shared.b16 {%0,%1,%2,%3}, [%4];"
        : "=r"(r[0]), "=r"(r[1]), "=r"(r[2]), "=r"(r[3]) : "r"(addr));
}
__device__ __forceinline__ void mma16816(float c[4], const uint32_t a[4], const uint32_t b[2]){
    asm volatile("mma.sync.aligned.m16n8k16.row.col.f32.f16.f16.f32 "
        "{%0,%1,%2,%3}, {%4,%5,%6,%7}, {%8,%9}, {%0,%1,%2,%3};"
        : "+f"(c[0]), "+f"(c[1]), "+f"(c[2]), "+f"(c[3])
        : "r"(a[0]), "r"(a[1]), "r"(a[2]), "r"(a[3]), "r"(b[0]), "r"(b[1]));
}

__global__ void __launch_bounds__(256, 2) mma_gemm(
    const __half* __restrict__ Ah,
    const __half* __restrict__ Bh, const __half* __restrict__ Bl,
    float* __restrict__ out, int mode)
{
    extern __shared__ char sm[];
    int tid = threadIdx.x, wid = tid >> 5, lane = tid & 31;
    int bm = blockIdx.y, bn = blockIdx.x;
    int wm = wid >> 2, wn = wid & 3;

    float acc[4][4][4];
    #pragma unroll
    for (int mt = 0; mt < 4; mt++)
        #pragma unroll
        for (int nt = 0; nt < 4; nt++)
            #pragma unroll
            for (int k = 0; k < 4; k++) acc[mt][nt][k] = 0.f;

    int lrow = tid >> 2, lcol = tid & 3;
    const __half* pA  = Ah + (size_t)(bm*128 + lrow) * 1024 + lcol * 8;
    const __half* pBh = Bh + (size_t)(bn*128 + lrow) * 1024 + lcol * 8;
    const __half* pBl = Bl + (size_t)(bn*128 + lrow) * 1024 + lcol * 8;

    uint32_t smb = smem_u32(sm);
    uint32_t sdst = smb + lrow * STRB + lcol * 16;

    uint32_t a_row = wm * 64 + (lane & 15);
    uint32_t a_coff = ((lane >> 4) & 1) * 16;
    uint32_t b_row = wn * 32 + (lane & 7) + (((lane >> 4) & 1) << 3);
    uint32_t b_koff = ((lane >> 3) & 1) * 16;

    #define ISSUE_LOADS(chunk, buf) do { \
        uint32_t d0_ = sdst + (buf) * BUFB; \
        const __half* s0_; \
        s0_ = pA + (chunk) * 32; \
        asm volatile("cp.async.cg.shared.global [%0], [%1], 16;" :: "r"(d0_), "l"(s0_)); \
        asm volatile("cp.async.cg.shared.global [%0], [%1], 16;" :: "r"(d0_ + 64*STRB), "l"(s0_ + 64*1024)); \
        s0_ = pBh + (chunk) * 32; \
        asm volatile("cp.async.cg.shared.global [%0], [%1], 16;" :: "r"(d0_ + TILEB), "l"(s0_)); \
        asm volatile("cp.async.cg.shared.global [%0], [%1], 16;" :: "r"(d0_ + TILEB + 64*STRB), "l"(s0_ + 64*1024)); \
        s0_ = pBl + (chunk) * 32; \
        asm volatile("cp.async.cg.shared.global [%0], [%1], 16;" :: "r"(d0_ + 2*TILEB), "l"(s0_)); \
        asm volatile("cp.async.cg.shared.global [%0], [%1], 16;" :: "r"(d0_ + 2*TILEB + 64*STRB), "l"(s0_ + 64*1024)); \
        asm volatile("cp.async.commit_group;"); \
    } while (0)

    ISSUE_LOADS(0, 0);

    for (int i = 0; i < 32; i++) {
        int buf = i & 1;
        __syncthreads();
        if (i + 1 < 32) {
            ISSUE_LOADS(i + 1, (i + 1) & 1);
            asm volatile("cp.async.wait_group 1;");
        } else {
            asm volatile("cp.async.wait_group 0;");
        }
        __syncthreads();

        uint32_t base = smb + buf * BUFB;
        #pragma unroll
        for (int ks = 0; ks < 2; ks++) {
            uint32_t ahf[4][4], bf[4][2];
            #pragma unroll
            for (int mt = 0; mt < 4; mt++)
                ldmA(ahf[mt], base + (a_row + mt * 16) * STRB + ks * 32 + a_coff);
            // B hi
            #pragma unroll
            for (int np = 0; np < 2; np++) {
                uint32_t r4[4];
                ldmA(r4, base + TILEB + (b_row + np * 16) * STRB + ks * 32 + b_koff);
                bf[np*2][0] = r4[0]; bf[np*2][1] = r4[1];
                bf[np*2+1][0] = r4[2]; bf[np*2+1][1] = r4[3];
            }
            #pragma unroll
            for (int mt = 0; mt < 4; mt++)
                #pragma unroll
                for (int nt = 0; nt < 4; nt++)
                    mma16816(acc[mt][nt], ahf[mt], bf[nt]);
            // B lo
            #pragma unroll
            for (int np = 0; np < 2; np++) {
                uint32_t r4[4];
                ldmA(r4, base + 2*TILEB + (b_row + np * 16) * STRB + ks * 32 + b_koff);
                bf[np*2][0] = r4[0]; bf[np*2][1] = r4[1];
                bf[np*2+1][0] = r4[2]; bf[np*2+1][1] = r4[3];
            }
            #pragma unroll
            for (int mt = 0; mt < 4; mt++)
                #pragma unroll
                for (int nt = 0; nt < 4; nt++)
                    mma16816(acc[mt][nt], ahf[mt], bf[nt]);
        }
    }

    // -------- epilogue --------
    int r0 = lane >> 2, c0 = (lane & 3) * 2;
    #pragma unroll
    for (int mt = 0; mt < 4; mt++) {
        #pragma unroll
        for (int half = 0; half < 2; half++) {
            int t = bm * 128 + wm * 64 + mt * 16 + r0 + half * 8;
            int b = t >> 11, s = t & 2047;
            #pragma unroll
            for (int nt = 0; nt < 4; nt++) {
                float v1 = acc[mt][nt][half * 2];
                float v2 = acc[mt][nt][half * 2 + 1];
                int o = bn * 128 + wn * 32 + nt * 8 + c0;
                if (mode == 0) {
                    float2 w; w.x = v1; w.y = v2;
                    *(float2*)(out + (size_t)t * 1024 + o) = w;
                } else {
                    int mat = o >> 10, oin = o & 1023;
                    int h = oin >> 6, hd = oin & 63;
                    float2 cs = *(const float2*)&g_cs[(s * 32 + (hd >> 1)) * 2];
                    float2 w;
                    w.x = v1 * cs.x - v2 * cs.y;
                    w.y = v1 * cs.y + v2 * cs.x;
                    *(float2*)(out + (size_t)mat * SZQ
                               + ((size_t)((b * Hn + h) * Sn + s)) * 64 + hd) = w;
                }
            }
        }
    }
}

// ---------------- scan helpers --------------------------------------------------
__device__ __forceinline__ void warpsum2(float& a, float& b) {
    #pragma unroll
    for (int off = 16; off; off >>= 1) {
        a += __shfl_xor_sync(0xffffffffu, a, off);
        b += __shfl_xor_sync(0xffffffffu, b, off);
    }
}
__device__ __forceinline__ float siluf(float x) {
    return x / (1.f + __expf(-x));
}
// returns padded row base ii (interval index, 0..13); bas zero outside valid range
__device__ __forceinline__ void spline4u(float x, float k0, float invh,
                                         const float* co, int& ii, float bas[4]) {
    int i = (int)floorf((x - k0) * invh);
    bool valid = (i >= 0) && (i < 14);
    ii = valid ? i : 0;
    float x2 = x * x, x3 = x2 * x;
    #pragma unroll
    for (int r = 0; r < 4; r++) {
        const float* c = co + r * 64 + ii;
        float v = c[0] + c[16] * x + c[32] * x2 + c[48] * x3;
        bas[r] = valid ? v : 0.f;
    }
}

// ---------------- sequential TTT scan: 1 block per (b,h) ------------------------
// Padded layout: rows 0..16 (= basis index n+3, valid n rows at 3..13).
// Pad rows hold exact 0.0 forever (bas=0 writes deposit 0), so unclamped
// unguarded indexing is safe.
#define ROWS17 (17*64)                   // 1088 floats per m-slice / W
#define SCAN_SMEM ((ROWS17 + 256 + 2*16*ROWS17) * 4)   // 144640 B

__global__ void __launch_bounds__(512) scan_kernel(
    const float* __restrict__ knots, const float* __restrict__ coefficients,
    const float* __restrict__ tgamma, const float* __restrict__ tbeta)
{
    extern __shared__ float smem[];
    float* Wsh = smem;                   // 17*64, rows 3..13 hold W
    float* co  = smem + ROWS17;          // 256
    float* cumA = co + 256;              // 2 buffers of 16*17*64

    const float* Qg = g_QKV;
    const float* Kg = g_QKV + SZQ;
    const float* Vg = g_QKV + 2*SZQ;

    int bh = blockIdx.x;
    int b = bh >> 4, h = bh & 15;
    int tid = threadIdx.x, m = tid >> 5, lane = tid & 31;

    // init: W rows 3..13 from coefficients, pad rows zero; zero all cum pad rows
    for (int e = tid; e < ROWS17; e += 512) {
        int n = (e >> 6) - 3;
        Wsh[e] = (n >= 0 && n <= 10) ? coefficients[h * 704 + n * 64 + (e & 63)] : 0.f;
    }
    for (int e = tid; e < 256; e += 512) co[e] = g_co[e];
    for (int mm = 0; mm < 16; mm++) {
        for (int e = tid; e < ROWS17; e += 512) {
            cumA[mm * ROWS17 + e] = 0.f;
            cumA[16 * ROWS17 + mm * ROWS17 + e] = 0.f;
        }
    }

    float k0 = knots[0];
    float invh = 1.f / (knots[1] - knots[0]);

    int d0 = lane, d1 = lane + 32;
    float ga0 = tgamma[h * 64 + d0], ga1 = tgamma[h * 64 + d1];
    float be0 = tbeta[h * 64 + d0],  be1 = tbeta[h * 64 + d1];
    __syncthreads();

    const size_t bhS = (size_t)bh * Sn;

    int s = m;
    size_t base = (bhS + s) * 64;
    float K0 = Kg[base + d0], K1 = Kg[base + d1];
    float V0 = Vg[base + d0], V1 = Vg[base + d1];
    float Q0 = Qg[base + d0], Q1 = Qg[base + d1];
    float et = g_eta[bhS + s];

    for (int nmb = 0; nmb < NMBn; nmb++) {
        int buf = nmb & 1;
        float* cumB = cumA + buf * (16 * ROWS17);
        float* cm   = cumB + m * ROWS17;
        const float* cm15 = cumB + 15 * ROWS17;

        // ---- prefetch next minibatch ----
        float nK0 = 0.f, nK1 = 0.f, nV0 = 0.f, nV1 = 0.f, nQ0 = 0.f, nQ1 = 0.f, nEt = 0.f;
        if (nmb + 1 < NMBn) {
            size_t nb = (bhS + s + 16) * 64;
            nK0 = Kg[nb + d0]; nK1 = Kg[nb + d1];
            nV0 = Vg[nb + d0]; nV1 = Vg[nb + d1];
            nQ0 = Qg[nb + d0]; nQ1 = Qg[nb + d1];
            nEt = g_eta[bhS + s + 16];
        }

        // ---- Phase A ----
        int ii0, ii1; float bk0[4], bk1[4];
        spline4u(K0, k0, invh, co, ii0, bk0);
        spline4u(K1, k0, invh, co, ii1, bk1);
        float Zk0 = siluf(K0), Zk1 = siluf(K1);
        #pragma unroll
        for (int r = 0; r < 4; r++) {
            Zk0 += bk0[r] * Wsh[(ii0 + r) * 64 + d0];
            Zk1 += bk1[r] * Wsh[(ii1 + r) * 64 + d1];
        }
        float s1 = Zk0 + Zk1, s2 = Zk0 * Zk0 + Zk1 * Zk1;
        warpsum2(s1, s2);
        float mu = s1 * (1.f / 64.f);
        float var = s2 * (1.f / 64.f) - mu * mu;
        float rstd = rsqrtf(var + EPSc);
        float xh0 = (Zk0 - mu) * rstd, xh1 = (Zk1 - mu) * rstd;
        float gr0 = (ga0 * xh0 + be0 - (V0 - K0)) * ga0;
        float gr1 = (ga1 * xh1 + be1 - (V1 - K1)) * ga1;
        float t1 = gr0 + gr1, t2 = gr0 * xh0 + gr1 * xh1;
        warpsum2(t1, t2);
        float mg = t1 * (1.f / 64.f), mgx = t2 * (1.f / 64.f);
        float e0 = et * (gr0 - mg - xh0 * mgx) * rstd;
        float e1 = et * (gr1 - mg - xh1 * mgx) * rstd;

        // zero valid rows (3..13), then unguarded sparse writes
        #pragma unroll
        for (int n = 3; n < 14; n++) {
            cm[n * 64 + d0] = 0.f;
            cm[n * 64 + d1] = 0.f;
        }
        #pragma unroll
        for (int r = 0; r < 4; r++) {
            cm[(ii0 + r) * 64 + d0] = bk0[r] * e0;
            cm[(ii1 + r) * 64 + d1] = bk1[r] * e1;
        }
        __syncthreads();               // A -> B

        // ---- Phase B: cumsum over m (valid rows only), fused W update ----
        for (int e = 192 + tid; e < 896; e += 512) {
            float acc = 0.f;
            #pragma unroll
            for (int mm = 0; mm < 16; mm++) {
                acc += cumB[mm * ROWS17 + e];
                cumB[mm * ROWS17 + e] = acc;
            }
            Wsh[e] -= acc;
        }
        __syncthreads();               // B -> C

        // ---- Phase C ----
        int iq0, iq1; float bq0[4], bq1[4];
        spline4u(Q0, k0, invh, co, iq0, bq0);
        spline4u(Q1, k0, invh, co, iq1, bq1);
        float Zq0 = siluf(Q0), Zq1 = siluf(Q1);
        #pragma unroll
        for (int r = 0; r < 4; r++) {
            int e0i = (iq0 + r) * 64 + d0, e1i = (iq1 + r) * 64 + d1;
            Zq0 += bq0[r] * (Wsh[e0i] + cm15[e0i] - cm[e0i]);
            Zq1 += bq1[r] * (Wsh[e1i] + cm15[e1i] - cm[e1i]);
        }
        float u1 = Zq0 + Zq1, u2 = Zq0 * Zq0 + Zq1 * Zq1;
        warpsum2(u1, u2);
        float mu2 = u1 * (1.f / 64.f);
        float var2 = u2 * (1.f / 64.f) - mu2 * mu2;
        float rstd2 = rsqrtf(var2 + EPSc);
        float y0 = Q0 + ga0 * (Zq0 - mu2) * rstd2 + be0;
        float y1 = Q1 + ga1 * (Zq1 - mu2) * rstd2 + be1;
        float* yp = g_y + ((size_t)b * Sn + s) * DIMn + h * 64;
        yp[d0] = y0;
        yp[d1] = y1;

        K0 = nK0; K1 = nK1; V0 = nV0; V1 = nV1; Q0 = nQ0; Q1 = nQ1; et = nEt;
        s += 16;
    }
}

// ---------------- post layernorm -> fp16 (hi only) ------------------------------
__global__ void __launch_bounds__(256) postln_kernel(
    const float* __restrict__ pw, const float* __restrict__ pb)
{
    __shared__ float r1[8], r2[8];
    int t = blockIdx.x;
    const float* xr = g_y + (size_t)t * 1024;
    int d = threadIdx.x * 4;
    float4 v = *(const float4*)(xr + d);
    float s1 = v.x + v.y + v.z + v.w;
    float s2 = v.x * v.x + v.y * v.y + v.z * v.z + v.w * v.w;
    #pragma unroll
    for (int off = 16; off; off >>= 1) {
        s1 += __shfl_xor_sync(0xffffffffu, s1, off);
        s2 += __shfl_xor_sync(0xffffffffu, s2, off);
    }
    int w = threadIdx.x >> 5, lane = threadIdx.x & 31;
    if (lane == 0) { r1[w] = s1; r2[w] = s2; }
    __syncthreads();
    float S1 = 0.f, S2 = 0.f;
    #pragma unroll
    for (int i = 0; i < 8; i++) { S1 += r1[i]; S2 += r2[i]; }
    float mu = S1 * (1.f / 1024.f);
    float var = S2 * (1.f / 1024.f) - mu * mu;
    float rstd = rsqrtf(var + EPSc);
    float4 w4 = *(const float4*)(pw + d);
    float4 b4 = *(const float4*)(pb + d);
    __half hh[4];
    hh[0] = __float2half((v.x - mu) * rstd * w4.x + b4.x);
    hh[1] = __float2half((v.y - mu) * rstd * w4.y + b4.y);
    hh[2] = __float2half((v.z - mu) * rstd * w4.z + b4.z);
    hh[3] = __float2half((v.w - mu) * rstd * w4.w + b4.w);
    *(uint2*)(g_lh + (size_t)t * 1024 + d) = *(uint2*)hh;
}

// ---------------- launch --------------------------------------------------------
extern "C" void kernel_launch(void* const* d_in, const int* in_sizes, int n_in,
                              void* d_out, int out_size)
{
    const float* x     = (const float*)d_in[0];
    const float* pf    = (const float*)d_in[1];
    const float* Wq    = (const float*)d_in[2];
    const float* Wk    = (const float*)d_in[3];
    const float* Wv    = (const float*)d_in[4];
    const float* Wo    = (const float*)d_in[5];
    const float* lrW   = (const float*)d_in[6];
    const float* lrb   = (const float*)d_in[7];
    const float* gsc   = (const float*)d_in[8];
    const float* tg    = (const float*)d_in[9];
    const float* tb    = (const float*)d_in[10];
    const float* pw    = (const float*)d_in[11];
    const float* pb    = (const float*)d_in[12];
    const float* coefs = (const float*)d_in[13];
    const float* knots = (const float*)d_in[14];
    float* out = (float*)d_out;

    float *QKVp;
    __half *xh, *wh, *wl, *lh;
    cudaGetSymbolAddress((void**)&QKVp, g_QKV);
    cudaGetSymbolAddress((void**)&xh, g_xh);
    cudaGetSymbolAddress((void**)&wh, g_wh);
    cudaGetSymbolAddress((void**)&wl, g_wl);
    cudaGetSymbolAddress((void**)&lh, g_lh);

    cudaFuncSetAttribute(mma_gemm, cudaFuncAttributeMaxDynamicSharedMemorySize,
                         MG_SMEM);
    cudaFuncSetAttribute(scan_kernel, cudaFuncAttributeMaxDynamicSharedMemorySize,
                         SCAN_SMEM);

    setup_kernel<<<12545, 256>>>(x, Wq, Wk, Wv, Wo, pf, knots);
    eta_kernel<<<NTOK, 128>>>(x, lrW, lrb, gsc);

    // fused QKV GEMM: B = concatenated [3072 x 1024] weights, out -> g_QKV
    dim3 gq(24, 64);
    mma_gemm<<<gq, 256, MG_SMEM>>>(xh, wh, wl, QKVp, 1);

    scan_kernel<<<Bn * Hn, 512, SCAN_SMEM>>>(knots, coefs, tg, tb);

    postln_kernel<<<NTOK, 256>>>(pw, pb);
    dim3 go(8, 64);
    mma_gemm<<<go, 256, MG_SMEM>>>(lh, wh + (size_t)3*DIMn*DIMn,
                                   wl + (size_t)3*DIMn*DIMn, out, 0);
}

// round 14
// speedup vs baseline: 3.2370x; 1.1373x over previous
#include <cuda_runtime.h>
#include <cuda_fp16.h>
#include <math.h>
#include <stdint.h>

#define Bn   4
#define Sn   2048
#define DIMn 1024
#define Hn   16
#define HDn  64
#define MBn  16
#define NMBn 128
#define NBn  11
#define EPSc 1e-6f
#define NTOK (Bn*Sn)              // 8192
#define NX   (Bn*Sn*DIMn)         // 8388608
#define SZQ  (Bn*Hn*Sn*HDn)      // 8388608

// ---------------- scratch (device globals; no allocation allowed) ----------------
__device__ float g_QKV[3*SZQ];          // [mat][b,h,s,hd]
__device__ float g_eta[Bn*Hn*Sn];
__device__ float g_y[NX];
__device__ float g_cs[Sn*32*2];
__device__ float g_co[256];
// tiled, pre-swizzled operand stores for bulk-copy GEMM
__device__ __align__(128) __half g_xt[NX];              // x: [rb 64][ch 32][128][64B]
__device__ __align__(128) __half g_lt[NX];              // ln out, same layout
__device__ __align__(128) __half g_wt[4*DIMn*DIMn*2];   // W: [nb 32][ch 32][hi|lo][128][64B]

__device__ __forceinline__ uint32_t smem_u32(const void* p){
    uint32_t a;
    asm("{ .reg .u64 t; cvta.to.shared.u64 t, %1; cvt.u32.u64 %0, t; }" : "=r"(a) : "l"(p));
    return a;
}

#define MBAR_INIT(a, c) asm volatile("mbarrier.init.shared.b64 [%0], %1;" :: "r"(a), "r"(c) : "memory")
#define MBAR_EXPECT_TX(a, n) asm volatile("mbarrier.arrive.expect_tx.shared.b64 _, [%0], %1;" :: "r"(a), "r"(n) : "memory")
#define MBAR_WAIT(mb, par) do { \
    uint32_t _m = (mb); uint32_t _p = (par); uint32_t _d; \
    asm volatile("{\n\t.reg .pred p;\n\t" \
        "mbarrier.try_wait.parity.acquire.cta.shared::cta.b64 p, [%1], %2;\n\t" \
        "selp.b32 %0, 1, 0, p;\n\t}" : "=r"(_d) : "r"(_m), "r"(_p) : "memory"); \
    if (!_d) { \
        asm volatile("{\n\t.reg .pred P1;\n\t" \
            "WL_%=:\n\t" \
            "mbarrier.try_wait.parity.acquire.cta.shared::cta.b64 P1, [%0], %1, 0x989680;\n\t" \
            "@P1 bra.uni WD_%=;\n\t" \
            "bra.uni WL_%=;\n\t" \
            "WD_%=:\n\t}" :: "r"(_m), "r"(_p) : "memory"); \
    } } while(0)
#define BULK_G2S(dst, src, bytes, mb) \
    asm volatile("cp.async.bulk.shared::cluster.global.mbarrier::complete_tx::bytes [%0], [%1], %2, [%3];" \
        :: "r"(dst), "l"(src), "r"(bytes), "r"(mb) : "memory")

// ---------------- fused setup: x tile | weight tiles | cos/sin | spline coefs ----
// grid: [0,8192) x, [8192,12288) W rows, [12288,12544) cs, 12544 coef
__global__ void __launch_bounds__(256) setup_kernel(
    const float* __restrict__ x,
    const float* __restrict__ W0, const float* __restrict__ W1,
    const float* __restrict__ W2, const float* __restrict__ W3,
    const float* __restrict__ pf, const float* __restrict__ knots)
{
    int b = blockIdx.x;
    if (b < 8192) {
        int t = b, j = threadIdx.x, d = j * 4;
        float4 v = *(const float4*)(x + (size_t)t * 1024 + d);
        __half hh[4];
        hh[0] = __float2half(v.x); hh[1] = __float2half(v.y);
        hh[2] = __float2half(v.z); hh[3] = __float2half(v.w);
        int rb = t >> 7, r = t & 127;
        int ch = d >> 5, c16 = (d >> 3) & 3;
        int sw = c16 ^ ((r >> 1) & 3);
        size_t off = ((size_t)(rb * 32 + ch) * 8192) + r * 64 + sw * 16 + (d & 7) * 2;
        *(uint2*)((char*)g_xt + off) = *(uint2*)hh;
    } else if (b < 12288) {
        int rr = b - 8192;
        int wi = rr >> 10;
        const float* W = (wi == 0) ? W0 : (wi == 1) ? W1 : (wi == 2) ? W2 : W3;
        int d = threadIdx.x * 4;
        float4 v = *(const float4*)(W + (size_t)(rr & 1023) * 1024 + d);
        float vv[4] = {v.x, v.y, v.z, v.w};
        __half hh[4], ll[4];
        #pragma unroll
        for (int j = 0; j < 4; j++) {
            hh[j] = __float2half(vv[j]);
            ll[j] = __float2half(vv[j] - __half2float(hh[j]));
        }
        int nb = rr >> 7, r = rr & 127;
        int ch = d >> 5, c16 = (d >> 3) & 3;
        int sw = c16 ^ ((r >> 1) & 3);
        size_t off = ((size_t)(nb * 32 + ch) * 16384) + r * 64 + sw * 16 + (d & 7) * 2;
        *(uint2*)((char*)g_wt + off) = *(uint2*)hh;
        *(uint2*)((char*)g_wt + off + 8192) = *(uint2*)ll;
    } else if (b < 12544) {
        int i = (b - 12288) * 256 + threadIdx.x;
        float a = pf[i];
        g_cs[2*i]   = cosf(a);
        g_cs[2*i+1] = sinf(a);
    } else {
        int i = threadIdx.x;
        if (i >= 16) return;
        if (i >= 14) {
            for (int r = 0; r < 4; r++)
                for (int c = 0; c < 4; c++)
                    g_co[(r*4 + c)*16 + i] = 0.f;
            return;
        }
        float kn[15];
        for (int j = 0; j < 15; j++) kn[j] = knots[j];
        float P[14][4];
        for (int j = 0; j < 14; j++)
            for (int c = 0; c < 4; c++) P[j][c] = 0.f;
        P[i][0] = 1.f;
        for (int k = 1; k <= 3; k++) {
            for (int j = 0; j + k < 14; j++) {
                float r1  = 1.f / (kn[j+k]   - kn[j]);
                float l0  = -kn[j] * r1,      l1 = r1;
                float r2i = 1.f / (kn[j+k+1] - kn[j+1]);
                float q0  = kn[j+k+1] * r2i,  q1 = -r2i;
                float nb[4];
                for (int c = 0; c < 4; c++) {
                    float v = l0 * P[j][c] + q0 * P[j+1][c];
                    if (c > 0) v += l1 * P[j][c-1] + q1 * P[j+1][c-1];
                    nb[c] = v;
                }
                for (int c = 0; c < 4; c++) P[j][c] = nb[c];
            }
        }
        for (int r = 0; r < 4; r++) {
            int idx = i - 3 + r;
            for (int c = 0; c < 4; c++)
                g_co[(r*4 + c)*16 + i] = (idx >= 0 && idx <= 10) ? P[idx][c] : 0.f;
        }
    }
}

// ---------------- eta ------------------------------------------------------------
__global__ void __launch_bounds__(128) eta_kernel(
    const float* __restrict__ x, const float* __restrict__ lrW,
    const float* __restrict__ lrb, const float* __restrict__ gsc)
{
    __shared__ float xs[1024];
    int t = blockIdx.x;
    const float* xr = x + (size_t)t * 1024;
    for (int i = threadIdx.x; i < 1024; i += 128) xs[i] = xr[i];
    __syncthreads();
    int w = threadIdx.x >> 5, lane = threadIdx.x & 31;
    int bb = t >> 11, s = t & 2047, k = s & 15;
    float g = 1.f / (float)(k + 1) + gsc[k];
    g = fmaxf(g, 0.f);
    for (int hh = 0; hh < 4; hh++) {
        int h = w * 4 + hh;
        const float* wr = lrW + h * 1024;
        float acc = 0.f;
        for (int j = lane; j < 1024; j += 32) acc += xs[j] * __ldg(wr + j);
        #pragma unroll
        for (int off = 16; off; off >>= 1) acc += __shfl_xor_sync(0xffffffffu, acc, off);
        if (lane == 0) {
            float v = 1.f / (1.f + __expf(-(acc + lrb[h])));
            g_eta[((size_t)(bb * Hn + h)) * Sn + s] = v * (1.f / 64.f) * g;
        }
    }
}

// ================= HMMA fp16x2 GEMM, bulk-copy loads ============================
// smem: [0,1024) mbars, then 2 buffers of (A 8KB | Bh 8KB | Bl 8KB)
#define MG_SMEM (1024 + 2*24576)         // 50176

__device__ __forceinline__ void ldmA(uint32_t r[4], uint32_t addr){
    asm volatile("ldmatrix.sync.aligned.m8n8.x4.shared.b16 {%0,%1,%2,%3}, [%4];"
        : "=r"(r[0]), "=r"(r[1]), "=r"(r[2]), "=r"(r[3]) : "r"(addr));
}
__device__ __forceinline__ void mma16816(float c[4], const uint32_t a[4], const uint32_t b[2]){
    asm volatile("mma.sync.aligned.m16n8k16.row.col.f32.f16.f16.f32 "
        "{%0,%1,%2,%3}, {%4,%5,%6,%7}, {%8,%9}, {%0,%1,%2,%3};"
        : "+f"(c[0]), "+f"(c[1]), "+f"(c[2]), "+f"(c[3])
        : "r"(a[0]), "r"(a[1]), "r"(a[2]), "r"(a[3]), "r"(b[0]), "r"(b[1]));
}

__global__ void __launch_bounds__(256, 2) mma_gemm(
    const __half* __restrict__ At,       // tiled A  [rb][ch][128][64B] swizzled
    const __half* __restrict__ Bt,       // tiled B  [nb][ch][hi|lo][128][64B] swizzled
    float* __restrict__ out, int mode)
{
    extern __shared__ char sm[];
    uint32_t smb = smem_u32(sm);
    int tid = threadIdx.x, wid = tid >> 5, lane = tid & 31;
    int bm = blockIdx.y, bn = blockIdx.x;
    int wm = wid >> 2, wn = wid & 3;

    if (tid == 0) { MBAR_INIT(smb + 0, 1); MBAR_INIT(smb + 8, 1); }
    __syncthreads();

    const char* srcA = (const char*)At + (size_t)bm * 32 * 8192;
    const char* srcB = (const char*)Bt + (size_t)bn * 32 * 16384;

    float acc[4][4][4];
    #pragma unroll
    for (int mt = 0; mt < 4; mt++)
        #pragma unroll
        for (int nt = 0; nt < 4; nt++)
            #pragma unroll
            for (int k = 0; k < 4; k++) acc[mt][nt][k] = 0.f;

    uint32_t a_row = wm * 64 + (lane & 15);
    uint32_t a_c   = (lane >> 4) & 1;
    uint32_t sxA   = (a_row >> 1) & 3;
    uint32_t b_row = wn * 32 + (lane & 7) + (((lane >> 4) & 1) << 3);
    uint32_t b_c   = (lane >> 3) & 1;
    uint32_t sxB   = (b_row >> 1) & 3;

    #define ISSUE_BULK(chunk, buf) do { \
        uint32_t mb_ = smb + (buf) * 8; \
        uint32_t dA_ = smb + 1024 + (buf) * 24576; \
        MBAR_EXPECT_TX(mb_, 24576u); \
        BULK_G2S(dA_,        srcA + (size_t)(chunk) * 8192,  8192u,  mb_); \
        BULK_G2S(dA_ + 8192, srcB + (size_t)(chunk) * 16384, 16384u, mb_); \
    } while (0)

    if (tid == 0) ISSUE_BULK(0, 0);

    for (int i = 0; i < 32; i++) {
        int buf = i & 1;
        MBAR_WAIT(smb + buf * 8, (i >> 1) & 1);
        __syncthreads();                     // all threads done with buf^1
        if (i + 1 < 32 && tid == 0) ISSUE_BULK(i + 1, buf ^ 1);

        uint32_t bA  = smb + 1024 + buf * 24576;
        uint32_t bBh = bA + 8192;
        uint32_t bBl = bA + 16384;

        #pragma unroll
        for (int ks = 0; ks < 2; ks++) {
            uint32_t ahf[4][4], bf[4][2];
            uint32_t aoff = ((uint32_t)((ks * 2 + a_c) ^ sxA)) << 4;
            uint32_t boff = ((uint32_t)((ks * 2 + b_c) ^ sxB)) << 4;
            #pragma unroll
            for (int mt = 0; mt < 4; mt++)
                ldmA(ahf[mt], bA + (a_row + mt * 16) * 64 + aoff);
            // B hi
            #pragma unroll
            for (int np = 0; np < 2; np++) {
                uint32_t r4[4];
                ldmA(r4, bBh + (b_row + np * 16) * 64 + boff);
                bf[np*2][0] = r4[0]; bf[np*2][1] = r4[1];
                bf[np*2+1][0] = r4[2]; bf[np*2+1][1] = r4[3];
            }
            #pragma unroll
            for (int mt = 0; mt < 4; mt++)
                #pragma unroll
                for (int nt = 0; nt < 4; nt++)
                    mma16816(acc[mt][nt], ahf[mt], bf[nt]);
            // B lo
            #pragma unroll
            for (int np = 0; np < 2; np++) {
                uint32_t r4[4];
                ldmA(r4, bBl + (b_row + np * 16) * 64 + boff);
                bf[np*2][0] = r4[0]; bf[np*2][1] = r4[1];
                bf[np*2+1][0] = r4[2]; bf[np*2+1][1] = r4[3];
            }
            #pragma unroll
            for (int mt = 0; mt < 4; mt++)
                #pragma unroll
                for (int nt = 0; nt < 4; nt++)
                    mma16816(acc[mt][nt], ahf[mt], bf[nt]);
        }
    }

    // -------- epilogue --------
    int r0 = lane >> 2, c0 = (lane & 3) * 2;
    #pragma unroll
    for (int mt = 0; mt < 4; mt++) {
        #pragma unroll
        for (int half = 0; half < 2; half++) {
            int t = bm * 128 + wm * 64 + mt * 16 + r0 + half * 8;
            int b = t >> 11, s = t & 2047;
            #pragma unroll
            for (int nt = 0; nt < 4; nt++) {
                float v1 = acc[mt][nt][half * 2];
                float v2 = acc[mt][nt][half * 2 + 1];
                int o = bn * 128 + wn * 32 + nt * 8 + c0;
                if (mode == 0) {
                    float2 w; w.x = v1; w.y = v2;
                    *(float2*)(out + (size_t)t * 1024 + o) = w;
                } else {
                    int mat = o >> 10, oin = o & 1023;
                    int h = oin >> 6, hd = oin & 63;
                    float2 cs = *(const float2*)&g_cs[(s * 32 + (hd >> 1)) * 2];
                    float2 w;
                    w.x = v1 * cs.x - v2 * cs.y;
                    w.y = v1 * cs.y + v2 * cs.x;
                    *(float2*)(out + (size_t)mat * SZQ
                               + ((size_t)((b * Hn + h) * Sn + s)) * 64 + hd) = w;
                }
            }
        }
    }
}

// ---------------- scan helpers --------------------------------------------------
__device__ __forceinline__ void warpsum2(float& a, float& b) {
    #pragma unroll
    for (int off = 16; off; off >>= 1) {
        a += __shfl_xor_sync(0xffffffffu, a, off);
        b += __shfl_xor_sync(0xffffffffu, b, off);
    }
}
__device__ __forceinline__ float siluf(float x) {
    return x / (1.f + __expf(-x));
}
__device__ __forceinline__ void spline4u(float x, float k0, float invh,
                                         const float* co, int& ii, float bas[4]) {
    int i = (int)floorf((x - k0) * invh);
    bool valid = (i >= 0) && (i < 14);
    ii = valid ? i : 0;
    float x2 = x * x, x3 = x2 * x;
    #pragma unroll
    for (int r = 0; r < 4; r++) {
        const float* c = co + r * 64 + ii;
        float v = c[0] + c[16] * x + c[32] * x2 + c[48] * x3;
        bas[r] = valid ? v : 0.f;
    }
}

// ---------------- sequential TTT scan: 1 block per (b,h) ------------------------
#define ROWS17 (17*64)
#define SCAN_SMEM ((ROWS17 + 256 + 2*16*ROWS17) * 4)   // 144640 B

__global__ void __launch_bounds__(512) scan_kernel(
    const float* __restrict__ knots, const float* __restrict__ coefficients,
    const float* __restrict__ tgamma, const float* __restrict__ tbeta)
{
    extern __shared__ float smem[];
    float* Wsh = smem;
    float* co  = smem + ROWS17;
    float* cumA = co + 256;

    const float* Qg = g_QKV;
    const float* Kg = g_QKV + SZQ;
    const float* Vg = g_QKV + 2*SZQ;

    int bh = blockIdx.x;
    int b = bh >> 4, h = bh & 15;
    int tid = threadIdx.x, m = tid >> 5, lane = tid & 31;

    for (int e = tid; e < ROWS17; e += 512) {
        int n = (e >> 6) - 3;
        Wsh[e] = (n >= 0 && n <= 10) ? coefficients[h * 704 + n * 64 + (e & 63)] : 0.f;
    }
    for (int e = tid; e < 256; e += 512) co[e] = g_co[e];
    for (int mm = 0; mm < 16; mm++) {
        for (int e = tid; e < ROWS17; e += 512) {
            cumA[mm * ROWS17 + e] = 0.f;
            cumA[16 * ROWS17 + mm * ROWS17 + e] = 0.f;
        }
    }

    float k0 = knots[0];
    float invh = 1.f / (knots[1] - knots[0]);

    int d0 = lane, d1 = lane + 32;
    float ga0 = tgamma[h * 64 + d0], ga1 = tgamma[h * 64 + d1];
    float be0 = tbeta[h * 64 + d0],  be1 = tbeta[h * 64 + d1];
    __syncthreads();

    const size_t bhS = (size_t)bh * Sn;

    int s = m;
    size_t base = (bhS + s) * 64;
    float K0 = Kg[base + d0], K1 = Kg[base + d1];
    float V0 = Vg[base + d0], V1 = Vg[base + d1];
    float Q0 = Qg[base + d0], Q1 = Qg[base + d1];
    float et = g_eta[bhS + s];

    for (int nmb = 0; nmb < NMBn; nmb++) {
        int buf = nmb & 1;
        float* cumB = cumA + buf * (16 * ROWS17);
        float* cm   = cumB + m * ROWS17;
        const float* cm15 = cumB + 15 * ROWS17;

        float nK0 = 0.f, nK1 = 0.f, nV0 = 0.f, nV1 = 0.f, nQ0 = 0.f, nQ1 = 0.f, nEt = 0.f;
        if (nmb + 1 < NMBn) {
            size_t nb = (bhS + s + 16) * 64;
            nK0 = Kg[nb + d0]; nK1 = Kg[nb + d1];
            nV0 = Vg[nb + d0]; nV1 = Vg[nb + d1];
            nQ0 = Qg[nb + d0]; nQ1 = Qg[nb + d1];
            nEt = g_eta[bhS + s + 16];
        }

        // ---- Phase A ----
        int ii0, ii1; float bk0[4], bk1[4];
        spline4u(K0, k0, invh, co, ii0, bk0);
        spline4u(K1, k0, invh, co, ii1, bk1);
        float Zk0 = siluf(K0), Zk1 = siluf(K1);
        #pragma unroll
        for (int r = 0; r < 4; r++) {
            Zk0 += bk0[r] * Wsh[(ii0 + r) * 64 + d0];
            Zk1 += bk1[r] * Wsh[(ii1 + r) * 64 + d1];
        }
        float s1 = Zk0 + Zk1, s2 = Zk0 * Zk0 + Zk1 * Zk1;
        warpsum2(s1, s2);
        float mu = s1 * (1.f / 64.f);
        float var = s2 * (1.f / 64.f) - mu * mu;
        float rstd = rsqrtf(var + EPSc);
        float xh0 = (Zk0 - mu) * rstd, xh1 = (Zk1 - mu) * rstd;
        float gr0 = (ga0 * xh0 + be0 - (V0 - K0)) * ga0;
        float gr1 = (ga1 * xh1 + be1 - (V1 - K1)) * ga1;
        float t1 = gr0 + gr1, t2 = gr0 * xh0 + gr1 * xh1;
        warpsum2(t1, t2);
        float mg = t1 * (1.f / 64.f), mgx = t2 * (1.f / 64.f);
        float e0 = et * (gr0 - mg - xh0 * mgx) * rstd;
        float e1 = et * (gr1 - mg - xh1 * mgx) * rstd;

        #pragma unroll
        for (int n = 3; n < 14; n++) {
            cm[n * 64 + d0] = 0.f;
            cm[n * 64 + d1] = 0.f;
        }
        #pragma unroll
        for (int r = 0; r < 4; r++) {
            cm[(ii0 + r) * 64 + d0] = bk0[r] * e0;
            cm[(ii1 + r) * 64 + d1] = bk1[r] * e1;
        }
        __syncthreads();

        // ---- Phase B ----
        for (int e = 192 + tid; e < 896; e += 512) {
            float acc = 0.f;
            #pragma unroll
            for (int mm = 0; mm < 16; mm++) {
                acc += cumB[mm * ROWS17 + e];
                cumB[mm * ROWS17 + e] = acc;
            }
            Wsh[e] -= acc;
        }
        __syncthreads();

        // ---- Phase C ----
        int iq0, iq1; float bq0[4], bq1[4];
        spline4u(Q0, k0, invh, co, iq0, bq0);
        spline4u(Q1, k0, invh, co, iq1, bq1);
        float Zq0 = siluf(Q0), Zq1 = siluf(Q1);
        #pragma unroll
        for (int r = 0; r < 4; r++) {
            int e0i = (iq0 + r) * 64 + d0, e1i = (iq1 + r) * 64 + d1;
            Zq0 += bq0[r] * (Wsh[e0i] + cm15[e0i] - cm[e0i]);
            Zq1 += bq1[r] * (Wsh[e1i] + cm15[e1i] - cm[e1i]);
        }
        float u1 = Zq0 + Zq1, u2 = Zq0 * Zq0 + Zq1 * Zq1;
        warpsum2(u1, u2);
        float mu2 = u1 * (1.f / 64.f);
        float var2 = u2 * (1.f / 64.f) - mu2 * mu2;
        float rstd2 = rsqrtf(var2 + EPSc);
        float y0 = Q0 + ga0 * (Zq0 - mu2) * rstd2 + be0;
        float y1 = Q1 + ga1 * (Zq1 - mu2) * rstd2 + be1;
        float* yp = g_y + ((size_t)b * Sn + s) * DIMn + h * 64;
        yp[d0] = y0;
        yp[d1] = y1;

        K0 = nK0; K1 = nK1; V0 = nV0; V1 = nV1; Q0 = nQ0; Q1 = nQ1; et = nEt;
        s += 16;
    }
}

// ---------------- post layernorm -> fp16 tiled-swizzled --------------------------
__global__ void __launch_bounds__(256) postln_kernel(
    const float* __restrict__ pw, const float* __restrict__ pb)
{
    __shared__ float r1[8], r2[8];
    int t = blockIdx.x;
    const float* xr = g_y + (size_t)t * 1024;
    int d = threadIdx.x * 4;
    float4 v = *(const float4*)(xr + d);
    float s1 = v.x + v.y + v.z + v.w;
    float s2 = v.x * v.x + v.y * v.y + v.z * v.z + v.w * v.w;
    #pragma unroll
    for (int off = 16; off; off >>= 1) {
        s1 += __shfl_xor_sync(0xffffffffu, s1, off);
        s2 += __shfl_xor_sync(0xffffffffu, s2, off);
    }
    int w = threadIdx.x >> 5, lane = threadIdx.x & 31;
    if (lane == 0) { r1[w] = s1; r2[w] = s2; }
    __syncthreads();
    float S1 = 0.f, S2 = 0.f;
    #pragma unroll
    for (int i = 0; i < 8; i++) { S1 += r1[i]; S2 += r2[i]; }
    float mu = S1 * (1.f / 1024.f);
    float var = S2 * (1.f / 1024.f) - mu * mu;
    float rstd = rsqrtf(var + EPSc);
    float4 w4 = *(const float4*)(pw + d);
    float4 b4 = *(const float4*)(pb + d);
    __half hh[4];
    hh[0] = __float2half((v.x - mu) * rstd * w4.x + b4.x);
    hh[1] = __float2half((v.y - mu) * rstd * w4.y + b4.y);
    hh[2] = __float2half((v.z - mu) * rstd * w4.z + b4.z);
    hh[3] = __float2half((v.w - mu) * rstd * w4.w + b4.w);
    int rb = t >> 7, r = t & 127;
    int ch = d >> 5, c16 = (d >> 3) & 3;
    int sw = c16 ^ ((r >> 1) & 3);
    size_t off = ((size_t)(rb * 32 + ch) * 8192) + r * 64 + sw * 16 + (d & 7) * 2;
    *(uint2*)((char*)g_lt + off) = *(uint2*)hh;
}

// ---------------- launch --------------------------------------------------------
extern "C" void kernel_launch(void* const* d_in, const int* in_sizes, int n_in,
                              void* d_out, int out_size)
{
    const float* x     = (const float*)d_in[0];
    const float* pf    = (const float*)d_in[1];
    const float* Wq    = (const float*)d_in[2];
    const float* Wk    = (const float*)d_in[3];
    const float* Wv    = (const float*)d_in[4];
    const float* Wo    = (const float*)d_in[5];
    const float* lrW   = (const float*)d_in[6];
    const float* lrb   = (const float*)d_in[7];
    const float* gsc   = (const float*)d_in[8];
    const float* tg    = (const float*)d_in[9];
    const float* tb    = (const float*)d_in[10];
    const float* pw    = (const float*)d_in[11];
    const float* pb    = (const float*)d_in[12];
    const float* coefs = (const float*)d_in[13];
    const float* knots = (const float*)d_in[14];
    float* out = (float*)d_out;

    float *QKVp;
    __half *xt, *wt, *lt;
    cudaGetSymbolAddress((void**)&QKVp, g_QKV);
    cudaGetSymbolAddress((void**)&xt, g_xt);
    cudaGetSymbolAddress((void**)&wt, g_wt);
    cudaGetSymbolAddress((void**)&lt, g_lt);

    cudaFuncSetAttribute(mma_gemm, cudaFuncAttributeMaxDynamicSharedMemorySize,
                         MG_SMEM);
    cudaFuncSetAttribute(scan_kernel, cudaFuncAttributeMaxDynamicSharedMemorySize,
                         SCAN_SMEM);

    setup_kernel<<<12545, 256>>>(x, Wq, Wk, Wv, Wo, pf, knots);
    eta_kernel<<<NTOK, 128>>>(x, lrW, lrb, gsc);

    // fused QKV GEMM: nb blocks 0..23 (Wq,Wk,Wv rows)
    dim3 gq(24, 64);
    mma_gemm<<<gq, 256, MG_SMEM>>>(xt, wt, QKVp, 1);

    scan_kernel<<<Bn * Hn, 512, SCAN_SMEM>>>(knots, coefs, tg, tb);

    postln_kernel<<<NTOK, 256>>>(pw, pb);
    // Wo GEMM: nb blocks 24..31 -> offset 24*32 tiles of 8192 halfs each
    dim3 go(8, 64);
    mma_gemm<<<go, 256, MG_SMEM>>>(lt, wt + (size_t)24 * 32 * 8192, out, 0);
}

// round 15
// speedup vs baseline: 3.5096x; 1.0842x over previous
#include <cuda_runtime.h>
#include <cuda_fp16.h>
#include <math.h>
#include <stdint.h>

#define Bn   4
#define Sn   2048
#define DIMn 1024
#define Hn   16
#define HDn  64
#define MBn  16
#define NMBn 128
#define NBn  11
#define EPSc 1e-6f
#define NTOK (Bn*Sn)              // 8192
#define NX   (Bn*Sn*DIMn)         // 8388608
#define SZQ  (Bn*Hn*Sn*HDn)      // 8388608

// ---------------- scratch (device globals; no allocation allowed) ----------------
__device__ float g_QKV[3*SZQ];          // [mat][b,h,s,hd]
__device__ float g_eta[Bn*Hn*Sn];
__device__ float g_y[NX];
__device__ float g_cs[Sn*32*2];
// tiled, pre-swizzled operand stores for bulk-copy GEMM
__device__ __align__(128) __half g_xt[NX];              // x: [rb 64][ch 32][128][64B]
__device__ __align__(128) __half g_lt[NX];              // ln out, same layout
__device__ __align__(128) __half g_wt[4*DIMn*DIMn*2];   // W: [nb 32][ch 32][hi|lo][128][64B]

__device__ __forceinline__ uint32_t smem_u32(const void* p){
    uint32_t a;
    asm("{ .reg .u64 t; cvta.to.shared.u64 t, %1; cvt.u32.u64 %0, t; }" : "=r"(a) : "l"(p));
    return a;
}

#define MBAR_INIT(a, c) asm volatile("mbarrier.init.shared.b64 [%0], %1;" :: "r"(a), "r"(c) : "memory")
#define MBAR_EXPECT_TX(a, n) asm volatile("mbarrier.arrive.expect_tx.shared.b64 _, [%0], %1;" :: "r"(a), "r"(n) : "memory")
#define MBAR_WAIT(mb, par) do { \
    uint32_t _m = (mb); uint32_t _p = (par); uint32_t _d; \
    asm volatile("{\n\t.reg .pred p;\n\t" \
        "mbarrier.try_wait.parity.acquire.cta.shared::cta.b64 p, [%1], %2;\n\t" \
        "selp.b32 %0, 1, 0, p;\n\t}" : "=r"(_d) : "r"(_m), "r"(_p) : "memory"); \
    if (!_d) { \
        asm volatile("{\n\t.reg .pred P1;\n\t" \
            "WL_%=:\n\t" \
            "mbarrier.try_wait.parity.acquire.cta.shared::cta.b64 P1, [%0], %1, 0x989680;\n\t" \
            "@P1 bra.uni WD_%=;\n\t" \
            "bra.uni WL_%=;\n\t" \
            "WD_%=:\n\t}" :: "r"(_m), "r"(_p) : "memory"); \
    } } while(0)
#define BULK_G2S(dst, src, bytes, mb) \
    asm volatile("cp.async.bulk.shared::cluster.global.mbarrier::complete_tx::bytes [%0], [%1], %2, [%3];" \
        :: "r"(dst), "l"(src), "r"(bytes), "r"(mb) : "memory")

// ---------------- fused setup: x tile | weight tiles | cos/sin -------------------
// grid: [0,8192) x, [8192,12288) W rows, [12288,12544) cs
__global__ void __launch_bounds__(256) setup_kernel(
    const float* __restrict__ x,
    const float* __restrict__ W0, const float* __restrict__ W1,
    const float* __restrict__ W2, const float* __restrict__ W3,
    const float* __restrict__ pf)
{
    int b = blockIdx.x;
    if (b < 8192) {
        int t = b, d = threadIdx.x * 4;
        float4 v = *(const float4*)(x + (size_t)t * 1024 + d);
        __half hh[4];
        hh[0] = __float2half(v.x); hh[1] = __float2half(v.y);
        hh[2] = __float2half(v.z); hh[3] = __float2half(v.w);
        int rb = t >> 7, r = t & 127;
        int ch = d >> 5, c16 = (d >> 3) & 3;
        int sw = c16 ^ ((r >> 1) & 3);
        size_t off = ((size_t)(rb * 32 + ch) * 8192) + r * 64 + sw * 16 + (d & 7) * 2;
        *(uint2*)((char*)g_xt + off) = *(uint2*)hh;
    } else if (b < 12288) {
        int rr = b - 8192;
        int wi = rr >> 10;
        const float* W = (wi == 0) ? W0 : (wi == 1) ? W1 : (wi == 2) ? W2 : W3;
        int d = threadIdx.x * 4;
        float4 v = *(const float4*)(W + (size_t)(rr & 1023) * 1024 + d);
        float vv[4] = {v.x, v.y, v.z, v.w};
        __half hh[4], ll[4];
        #pragma unroll
        for (int j = 0; j < 4; j++) {
            hh[j] = __float2half(vv[j]);
            ll[j] = __float2half(vv[j] - __half2float(hh[j]));
        }
        int nb = rr >> 7, r = rr & 127;
        int ch = d >> 5, c16 = (d >> 3) & 3;
        int sw = c16 ^ ((r >> 1) & 3);
        size_t off = ((size_t)(nb * 32 + ch) * 16384) + r * 64 + sw * 16 + (d & 7) * 2;
        *(uint2*)((char*)g_wt + off) = *(uint2*)hh;
        *(uint2*)((char*)g_wt + off + 8192) = *(uint2*)ll;
    } else {
        int i = (b - 12288) * 256 + threadIdx.x;
        float a = pf[i];
        g_cs[2*i]   = cosf(a);
        g_cs[2*i+1] = sinf(a);
    }
}

// ---------------- eta: 8 tokens per block ----------------------------------------
__global__ void __launch_bounds__(256) eta_kernel(
    const float* __restrict__ x, const float* __restrict__ lrW,
    const float* __restrict__ lrb, const float* __restrict__ gsc)
{
    __shared__ float xs[8 * 1024];
    int t0 = blockIdx.x * 8;
    const float4* xg = (const float4*)(x + (size_t)t0 * 1024);
    for (int i = threadIdx.x; i < 2048; i += 256)
        ((float4*)xs)[i] = xg[i];
    __syncthreads();
    int w = threadIdx.x >> 5, lane = threadIdx.x & 31;
    int t = t0 + w;
    int bb = t >> 11, s = t & 2047, k = s & 15;
    float g = fmaxf(1.f / (float)(k + 1) + gsc[k], 0.f);
    const float4* xr = (const float4*)(xs + w * 1024);
    for (int h = 0; h < 16; h++) {
        const float4* wr = (const float4*)(lrW + h * 1024);
        float acc = 0.f;
        #pragma unroll
        for (int j = 0; j < 8; j++) {
            float4 xv = xr[lane + j * 32];
            float4 wv = __ldg(wr + lane + j * 32);
            acc += xv.x * wv.x + xv.y * wv.y + xv.z * wv.z + xv.w * wv.w;
        }
        #pragma unroll
        for (int off = 16; off; off >>= 1) acc += __shfl_xor_sync(0xffffffffu, acc, off);
        if (lane == 0) {
            float v = 1.f / (1.f + __expf(-(acc + lrb[h])));
            g_eta[((size_t)(bb * Hn + h)) * Sn + s] = v * (1.f / 64.f) * g;
        }
    }
}

// ================= HMMA fp16x2 GEMM, bulk-copy loads, 3-stage ===================
// smem: [0,1024) mbars, then 3 buffers of (A 8KB | Bh 8KB | Bl 8KB)
#define MG_SMEM (1024 + 3*24576)         // 74752

__device__ __forceinline__ void ldmA(uint32_t r[4], uint32_t addr){
    asm volatile("ldmatrix.sync.aligned.m8n8.x4.shared.b16 {%0,%1,%2,%3}, [%4];"
        : "=r"(r[0]), "=r"(r[1]), "=r"(r[2]), "=r"(r[3]) : "r"(addr));
}
__device__ __forceinline__ void mma16816(float c[4], const uint32_t a[4], const uint32_t b[2]){
    asm volatile("mma.sync.aligned.m16n8k16.row.col.f32.f16.f16.f32 "
        "{%0,%1,%2,%3}, {%4,%5,%6,%7}, {%8,%9}, {%0,%1,%2,%3};"
        : "+f"(c[0]), "+f"(c[1]), "+f"(c[2]), "+f"(c[3])
        : "r"(a[0]), "r"(a[1]), "r"(a[2]), "r"(a[3]), "r"(b[0]), "r"(b[1]));
}

__global__ void __launch_bounds__(256, 2) mma_gemm(
    const __half* __restrict__ At,
    const __half* __restrict__ Bt,
    float* __restrict__ out, int mode)
{
    extern __shared__ char sm[];
    uint32_t smb = smem_u32(sm);
    int tid = threadIdx.x, wid = tid >> 5, lane = tid & 31;
    int bm = blockIdx.y, bn = blockIdx.x;
    int wm = wid >> 2, wn = wid & 3;

    if (tid == 0) { MBAR_INIT(smb + 0, 1); MBAR_INIT(smb + 8, 1); MBAR_INIT(smb + 16, 1); }
    __syncthreads();

    const char* srcA = (const char*)At + (size_t)bm * 32 * 8192;
    const char* srcB = (const char*)Bt + (size_t)bn * 32 * 16384;

    float acc[4][4][4];
    #pragma unroll
    for (int mt = 0; mt < 4; mt++)
        #pragma unroll
        for (int nt = 0; nt < 4; nt++)
            #pragma unroll
            for (int k = 0; k < 4; k++) acc[mt][nt][k] = 0.f;

    uint32_t a_row = wm * 64 + (lane & 15);
    uint32_t a_c   = (lane >> 4) & 1;
    uint32_t sxA   = (a_row >> 1) & 3;
    uint32_t b_row = wn * 32 + (lane & 7) + (((lane >> 4) & 1) << 3);
    uint32_t b_c   = (lane >> 3) & 1;
    uint32_t sxB   = (b_row >> 1) & 3;

    #define ISSUE_BULK(chunk, buf) do { \
        uint32_t mb_ = smb + (buf) * 8; \
        uint32_t dA_ = smb + 1024 + (buf) * 24576; \
        MBAR_EXPECT_TX(mb_, 24576u); \
        BULK_G2S(dA_,        srcA + (size_t)(chunk) * 8192,  8192u,  mb_); \
        BULK_G2S(dA_ + 8192, srcB + (size_t)(chunk) * 16384, 16384u, mb_); \
    } while (0)

    if (tid == 0) { ISSUE_BULK(0, 0); ISSUE_BULK(1, 1); }

    for (int i = 0; i < 32; i++) {
        int buf = i % 3;
        if (tid == 0 && i + 2 < 32) ISSUE_BULK(i + 2, (i + 2) % 3);
        MBAR_WAIT(smb + buf * 8, (i / 3) & 1);

        uint32_t bA  = smb + 1024 + buf * 24576;
        uint32_t bBh = bA + 8192;
        uint32_t bBl = bA + 16384;

        #pragma unroll
        for (int ks = 0; ks < 2; ks++) {
            uint32_t ahf[4][4], bf[4][2];
            uint32_t aoff = ((uint32_t)((ks * 2 + a_c) ^ sxA)) << 4;
            uint32_t boff = ((uint32_t)((ks * 2 + b_c) ^ sxB)) << 4;
            #pragma unroll
            for (int mt = 0; mt < 4; mt++)
                ldmA(ahf[mt], bA + (a_row + mt * 16) * 64 + aoff);
            #pragma unroll
            for (int np = 0; np < 2; np++) {
                uint32_t r4[4];
                ldmA(r4, bBh + (b_row + np * 16) * 64 + boff);
                bf[np*2][0] = r4[0]; bf[np*2][1] = r4[1];
                bf[np*2+1][0] = r4[2]; bf[np*2+1][1] = r4[3];
            }
            #pragma unroll
            for (int mt = 0; mt < 4; mt++)
                #pragma unroll
                for (int nt = 0; nt < 4; nt++)
                    mma16816(acc[mt][nt], ahf[mt], bf[nt]);
            #pragma unroll
            for (int np = 0; np < 2; np++) {
                uint32_t r4[4];
                ldmA(r4, bBl + (b_row + np * 16) * 64 + boff);
                bf[np*2][0] = r4[0]; bf[np*2][1] = r4[1];
                bf[np*2+1][0] = r4[2]; bf[np*2+1][1] = r4[3];
            }
            #pragma unroll
            for (int mt = 0; mt < 4; mt++)
                #pragma unroll
                for (int nt = 0; nt < 4; nt++)
                    mma16816(acc[mt][nt], ahf[mt], bf[nt]);
        }
        __syncthreads();          // all threads done with this buffer before reissue
    }

    // -------- epilogue --------
    int r0 = lane >> 2, c0 = (lane & 3) * 2;
    #pragma unroll
    for (int mt = 0; mt < 4; mt++) {
        #pragma unroll
        for (int half = 0; half < 2; half++) {
            int t = bm * 128 + wm * 64 + mt * 16 + r0 + half * 8;
            int b = t >> 11, s = t & 2047;
            #pragma unroll
            for (int nt = 0; nt < 4; nt++) {
                float v1 = acc[mt][nt][half * 2];
                float v2 = acc[mt][nt][half * 2 + 1];
                int o = bn * 128 + wn * 32 + nt * 8 + c0;
                if (mode == 0) {
                    float2 w; w.x = v1; w.y = v2;
                    *(float2*)(out + (size_t)t * 1024 + o) = w;
                } else {
                    int mat = o >> 10, oin = o & 1023;
                    int h = oin >> 6, hd = oin & 63;
                    float2 cs = *(const float2*)&g_cs[(s * 32 + (hd >> 1)) * 2];
                    float2 w;
                    w.x = v1 * cs.x - v2 * cs.y;
                    w.y = v1 * cs.y + v2 * cs.x;
                    *(float2*)(out + (size_t)mat * SZQ
                               + ((size_t)((b * Hn + h) * Sn + s)) * 64 + hd) = w;
                }
            }
        }
    }
}

// ---------------- scan helpers --------------------------------------------------
__device__ __forceinline__ void warpsum2(float& a, float& b) {
    #pragma unroll
    for (int off = 16; off; off >>= 1) {
        a += __shfl_xor_sync(0xffffffffu, a, off);
        b += __shfl_xor_sync(0xffffffffu, b, off);
    }
}
__device__ __forceinline__ float siluf(float x) {
    return __fdividef(x, 1.f + __expf(-x));
}
// uniform cubic B-spline (cardinal) basis: knots are uniform linspace(-1,1,15)
__device__ __forceinline__ void spline4c(float x, float k0, float invh,
                                         int& ii, float bas[4]) {
    float u = (x - k0) * invh;
    float fi = floorf(u);
    int i = (int)fi;
    float t = u - fi;
    bool uv = (u >= 0.f) && (i < 14);
    ii = uv ? i : 7;
    float t2 = t * t, t3 = t2 * t;
    float omt = 1.f - t;
    bas[0] = omt * omt * omt * (1.f / 6.f);
    bas[1] = 0.5f * t3 - t2 + (2.f / 3.f);
    bas[2] = -0.5f * t3 + 0.5f * t2 + 0.5f * t + (1.f / 6.f);
    bas[3] = t3 * (1.f / 6.f);
    #pragma unroll
    for (int r = 0; r < 4; r++) {
        int j = i - 3 + r;
        bool v = uv && (j >= 0) && (j <= 10);
        bas[r] = v ? bas[r] : 0.f;
    }
}

// ---------------- sequential TTT scan: 1 block per (b,h) ------------------------
#define ROWS17 (17*64)
#define SCAN_SMEM ((ROWS17 + 2*16*ROWS17) * 4)   // 143616 B

__global__ void __launch_bounds__(512) scan_kernel(
    const float* __restrict__ knots, const float* __restrict__ coefficients,
    const float* __restrict__ tgamma, const float* __restrict__ tbeta)
{
    extern __shared__ float smem[];
    float* Wsh = smem;                   // rows 3..13 hold W
    float* cumA = smem + ROWS17;         // 2 buffers of 16*ROWS17

    const float* Qg = g_QKV;
    const float* Kg = g_QKV + SZQ;
    const float* Vg = g_QKV + 2*SZQ;

    int bh = blockIdx.x;
    int b = bh >> 4, h = bh & 15;
    int tid = threadIdx.x, m = tid >> 5, lane = tid & 31;

    for (int e = tid; e < ROWS17; e += 512) {
        int n = (e >> 6) - 3;
        Wsh[e] = (n >= 0 && n <= 10) ? coefficients[h * 704 + n * 64 + (e & 63)] : 0.f;
    }
    for (int mm = 0; mm < 16; mm++) {
        for (int e = tid; e < ROWS17; e += 512) {
            cumA[mm * ROWS17 + e] = 0.f;
            cumA[16 * ROWS17 + mm * ROWS17 + e] = 0.f;
        }
    }

    float k0 = knots[0];
    float invh = 1.f / (knots[1] - knots[0]);

    int d0 = lane, d1 = lane + 32;
    float ga0 = tgamma[h * 64 + d0], ga1 = tgamma[h * 64 + d1];
    float be0 = tbeta[h * 64 + d0],  be1 = tbeta[h * 64 + d1];
    __syncthreads();

    const size_t bhS = (size_t)bh * Sn;

    int s = m;
    size_t base = (bhS + s) * 64;
    float K0 = Kg[base + d0], K1 = Kg[base + d1];
    float V0 = Vg[base + d0], V1 = Vg[base + d1];
    float Q0 = Qg[base + d0], Q1 = Qg[base + d1];
    float et = g_eta[bhS + s];

    for (int nmb = 0; nmb < NMBn; nmb++) {
        int buf = nmb & 1;
        float* cumB = cumA + buf * (16 * ROWS17);
        float* cm   = cumB + m * ROWS17;

        float nK0 = 0.f, nK1 = 0.f, nV0 = 0.f, nV1 = 0.f, nQ0 = 0.f, nQ1 = 0.f, nEt = 0.f;
        if (nmb + 1 < NMBn) {
            size_t nb = (bhS + s + 16) * 64;
            nK0 = Kg[nb + d0]; nK1 = Kg[nb + d1];
            nV0 = Vg[nb + d0]; nV1 = Vg[nb + d1];
            nQ0 = Qg[nb + d0]; nQ1 = Qg[nb + d1];
            nEt = g_eta[bhS + s + 16];
        }

        // ---- Phase A: Zk, LN-l2-bwd, tok ----
        int ii0, ii1; float bk0[4], bk1[4];
        spline4c(K0, k0, invh, ii0, bk0);
        spline4c(K1, k0, invh, ii1, bk1);
        float Zk0 = siluf(K0), Zk1 = siluf(K1);
        #pragma unroll
        for (int r = 0; r < 4; r++) {
            Zk0 += bk0[r] * Wsh[(ii0 + r) * 64 + d0];
            Zk1 += bk1[r] * Wsh[(ii1 + r) * 64 + d1];
        }
        float s1 = Zk0 + Zk1, s2 = Zk0 * Zk0 + Zk1 * Zk1;
        warpsum2(s1, s2);
        float mu = s1 * (1.f / 64.f);
        float var = s2 * (1.f / 64.f) - mu * mu;
        float rstd = rsqrtf(var + EPSc);
        float xh0 = (Zk0 - mu) * rstd, xh1 = (Zk1 - mu) * rstd;
        float gr0 = (ga0 * xh0 + be0 - (V0 - K0)) * ga0;
        float gr1 = (ga1 * xh1 + be1 - (V1 - K1)) * ga1;
        float t1 = gr0 + gr1, t2 = gr0 * xh0 + gr1 * xh1;
        warpsum2(t1, t2);
        float mg = t1 * (1.f / 64.f), mgx = t2 * (1.f / 64.f);
        float e0 = et * (gr0 - mg - xh0 * mgx) * rstd;
        float e1 = et * (gr1 - mg - xh1 * mgx) * rstd;

        #pragma unroll
        for (int n = 3; n < 14; n++) {
            cm[n * 64 + d0] = 0.f;
            cm[n * 64 + d1] = 0.f;
        }
        #pragma unroll
        for (int r = 0; r < 4; r++) {
            cm[(ii0 + r) * 64 + d0] = bk0[r] * e0;
            cm[(ii1 + r) * 64 + d1] = bk1[r] * e1;
        }
        __syncthreads();               // A -> B

        // ---- Phase B: cumsum over m; store W_old - cum[m]; update W ----
        for (int e = 192 + tid; e < 896; e += 512) {
            float Wv = Wsh[e];
            float acc = 0.f;
            #pragma unroll
            for (int mm = 0; mm < 16; mm++) {
                acc += cumB[mm * ROWS17 + e];
                cumB[mm * ROWS17 + e] = Wv - acc;
            }
            Wsh[e] = Wv - acc;
        }
        __syncthreads();               // B -> C

        // ---- Phase C: Zq = silu(Q) + basQ . (W_old - cum[m]) ----
        int iq0, iq1; float bq0[4], bq1[4];
        spline4c(Q0, k0, invh, iq0, bq0);
        spline4c(Q1, k0, invh, iq1, bq1);
        float Zq0 = siluf(Q0), Zq1 = siluf(Q1);
        #pragma unroll
        for (int r = 0; r < 4; r++) {
            Zq0 += bq0[r] * cm[(iq0 + r) * 64 + d0];
            Zq1 += bq1[r] * cm[(iq1 + r) * 64 + d1];
        }
        float u1 = Zq0 + Zq1, u2 = Zq0 * Zq0 + Zq1 * Zq1;
        warpsum2(u1, u2);
        float mu2 = u1 * (1.f / 64.f);
        float var2 = u2 * (1.f / 64.f) - mu2 * mu2;
        float rstd2 = rsqrtf(var2 + EPSc);
        float y0 = Q0 + ga0 * (Zq0 - mu2) * rstd2 + be0;
        float y1 = Q1 + ga1 * (Zq1 - mu2) * rstd2 + be1;
        float* yp = g_y + ((size_t)b * Sn + s) * DIMn + h * 64;
        yp[d0] = y0;
        yp[d1] = y1;

        K0 = nK0; K1 = nK1; V0 = nV0; V1 = nV1; Q0 = nQ0; Q1 = nQ1; et = nEt;
        s += 16;
    }
}

// ---------------- post layernorm -> fp16 tiled-swizzled --------------------------
__global__ void __launch_bounds__(256) postln_kernel(
    const float* __restrict__ pw, const float* __restrict__ pb)
{
    __shared__ float r1[8], r2[8];
    int t = blockIdx.x;
    const float* xr = g_y + (size_t)t * 1024;
    int d = threadIdx.x * 4;
    float4 v = *(const float4*)(xr + d);
    float s1 = v.x + v.y + v.z + v.w;
    float s2 = v.x * v.x + v.y * v.y + v.z * v.z + v.w * v.w;
    #pragma unroll
    for (int off = 16; off; off >>= 1) {
        s1 += __shfl_xor_sync(0xffffffffu, s1, off);
        s2 += __shfl_xor_sync(0xffffffffu, s2, off);
    }
    int w = threadIdx.x >> 5, lane = threadIdx.x & 31;
    if (lane == 0) { r1[w] = s1; r2[w] = s2; }
    __syncthreads();
    float S1 = 0.f, S2 = 0.f;
    #pragma unroll
    for (int i = 0; i < 8; i++) { S1 += r1[i]; S2 += r2[i]; }
    float mu = S1 * (1.f / 1024.f);
    float var = S2 * (1.f / 1024.f) - mu * mu;
    float rstd = rsqrtf(var + EPSc);
    float4 w4 = *(const float4*)(pw + d);
    float4 b4 = *(const float4*)(pb + d);
    __half hh[4];
    hh[0] = __float2half((v.x - mu) * rstd * w4.x + b4.x);
    hh[1] = __float2half((v.y - mu) * rstd * w4.y + b4.y);
    hh[2] = __float2half((v.z - mu) * rstd * w4.z + b4.z);
    hh[3] = __float2half((v.w - mu) * rstd * w4.w + b4.w);
    int rb = t >> 7, r = t & 127;
    int ch = d >> 5, c16 = (d >> 3) & 3;
    int sw = c16 ^ ((r >> 1) & 3);
    size_t off = ((size_t)(rb * 32 + ch) * 8192) + r * 64 + sw * 16 + (d & 7) * 2;
    *(uint2*)((char*)g_lt + off) = *(uint2*)hh;
}

// ---------------- launch --------------------------------------------------------
extern "C" void kernel_launch(void* const* d_in, const int* in_sizes, int n_in,
                              void* d_out, int out_size)
{
    const float* x     = (const float*)d_in[0];
    const float* pf    = (const float*)d_in[1];
    const float* Wq    = (const float*)d_in[2];
    const float* Wk    = (const float*)d_in[3];
    const float* Wv    = (const float*)d_in[4];
    const float* Wo    = (const float*)d_in[5];
    const float* lrW   = (const float*)d_in[6];
    const float* lrb   = (const float*)d_in[7];
    const float* gsc   = (const float*)d_in[8];
    const float* tg    = (const float*)d_in[9];
    const float* tb    = (const float*)d_in[10];
    const float* pw    = (const float*)d_in[11];
    const float* pb    = (const float*)d_in[12];
    const float* coefs = (const float*)d_in[13];
    const float* knots = (const float*)d_in[14];
    float* out = (float*)d_out;

    float *QKVp;
    __half *xt, *wt, *lt;
    cudaGetSymbolAddress((void**)&QKVp, g_QKV);
    cudaGetSymbolAddress((void**)&xt, g_xt);
    cudaGetSymbolAddress((void**)&wt, g_wt);
    cudaGetSymbolAddress((void**)&lt, g_lt);

    cudaFuncSetAttribute(mma_gemm, cudaFuncAttributeMaxDynamicSharedMemorySize,
                         MG_SMEM);
    cudaFuncSetAttribute(scan_kernel, cudaFuncAttributeMaxDynamicSharedMemorySize,
                         SCAN_SMEM);

    setup_kernel<<<12544, 256>>>(x, Wq, Wk, Wv, Wo, pf);
    eta_kernel<<<NTOK / 8, 256>>>(x, lrW, lrb, gsc);

    // fused QKV GEMM: nb blocks 0..23 (Wq,Wk,Wv rows)
    dim3 gq(24, 64);
    mma_gemm<<<gq, 256, MG_SMEM>>>(xt, wt, QKVp, 1);

    scan_kernel<<<Bn * Hn, 512, SCAN_SMEM>>>(knots, coefs, tg, tb);

    postln_kernel<<<NTOK, 256>>>(pw, pb);
    // Wo GEMM: nb blocks 24..31
    dim3 go(8, 64);
    mma_gemm<<<go, 256, MG_SMEM>>>(lt, wt + (size_t)24 * 32 * 8192, out, 0);
}

// round 17
// speedup vs baseline: 4.4768x; 1.2756x over previous
#include <cuda_runtime.h>
#include <cuda_fp16.h>
#include <math.h>
#include <stdint.h>

#define Bn   4
#define Sn   2048
#define DIMn 1024
#define Hn   16
#define HDn  64
#define MBn  16
#define NMBn 128
#define NBn  11
#define EPSc 1e-6f
#define NTOK (Bn*Sn)              // 8192
#define NX   (Bn*Sn*DIMn)         // 8388608
#define SZQ  (Bn*Hn*Sn*HDn)      // 8388608

// ---------------- scratch (device globals; no allocation allowed) ----------------
__device__ float g_QKV[3*SZQ];          // [mat][b,h,s,hd]
__device__ float g_eta[Bn*Hn*Sn];
__device__ float g_y[NX];
__device__ float g_cs[Sn*32*2];
// tiled, pre-swizzled operand stores for bulk-copy GEMM (single fp16)
__device__ __align__(128) __half g_xt[NX];              // x: [rb 64][ch 32][128][64B]
__device__ __align__(128) __half g_lt[NX];              // ln out, same layout
__device__ __align__(128) __half g_wt[4*DIMn*DIMn];     // W: [nb 32][ch 32][128][64B]

__device__ __forceinline__ uint32_t smem_u32(const void* p){
    uint32_t a;
    asm("{ .reg .u64 t; cvta.to.shared.u64 t, %1; cvt.u32.u64 %0, t; }" : "=r"(a) : "l"(p));
    return a;
}

#define MBAR_INIT(a, c) asm volatile("mbarrier.init.shared.b64 [%0], %1;" :: "r"(a), "r"(c) : "memory")
#define MBAR_EXPECT_TX(a, n) asm volatile("mbarrier.arrive.expect_tx.shared.b64 _, [%0], %1;" :: "r"(a), "r"(n) : "memory")
#define MBAR_WAIT(mb, par) do { \
    uint32_t _m = (mb); uint32_t _p = (par); uint32_t _d; \
    asm volatile("{\n\t.reg .pred p;\n\t" \
        "mbarrier.try_wait.parity.acquire.cta.shared::cta.b64 p, [%1], %2;\n\t" \
        "selp.b32 %0, 1, 0, p;\n\t}" : "=r"(_d) : "r"(_m), "r"(_p) : "memory"); \
    if (!_d) { \
        asm volatile("{\n\t.reg .pred P1;\n\t" \
            "WL_%=:\n\t" \
            "mbarrier.try_wait.parity.acquire.cta.shared::cta.b64 P1, [%0], %1, 0x989680;\n\t" \
            "@P1 bra.uni WD_%=;\n\t" \
            "bra.uni WL_%=;\n\t" \
            "WD_%=:\n\t}" :: "r"(_m), "r"(_p) : "memory"); \
    } } while(0)
#define BULK_G2S(dst, src, bytes, mb) \
    asm volatile("cp.async.bulk.shared::cluster.global.mbarrier::complete_tx::bytes [%0], [%1], %2, [%3];" \
        :: "r"(dst), "l"(src), "r"(bytes), "r"(mb) : "memory")

// ---------------- fused setup: x tile | weight tiles | cos/sin | eta -------------
// grid: [0,8192) x, [8192,12288) W rows, [12288,12544) cs, [12544,13568) eta
__global__ void __launch_bounds__(256) setup_kernel(
    const float* __restrict__ x,
    const float* __restrict__ W0, const float* __restrict__ W1,
    const float* __restrict__ W2, const float* __restrict__ W3,
    const float* __restrict__ pf,
    const float* __restrict__ lrW, const float* __restrict__ lrb,
    const float* __restrict__ gsc)
{
    __shared__ float xs[8 * 1024];
    int b = blockIdx.x;
    if (b < 8192) {
        int t = b, d = threadIdx.x * 4;
        float4 v = *(const float4*)(x + (size_t)t * 1024 + d);
        __half hh[4];
        hh[0] = __float2half(v.x); hh[1] = __float2half(v.y);
        hh[2] = __float2half(v.z); hh[3] = __float2half(v.w);
        int rb = t >> 7, r = t & 127;
        int ch = d >> 5, c16 = (d >> 3) & 3;
        int sw = c16 ^ ((r >> 1) & 3);
        size_t off = ((size_t)(rb * 32 + ch) * 8192) + r * 64 + sw * 16 + (d & 7) * 2;
        *(uint2*)((char*)g_xt + off) = *(uint2*)hh;
    } else if (b < 12288) {
        int rr = b - 8192;
        int wi = rr >> 10;
        const float* W = (wi == 0) ? W0 : (wi == 1) ? W1 : (wi == 2) ? W2 : W3;
        int d = threadIdx.x * 4;
        float4 v = *(const float4*)(W + (size_t)(rr & 1023) * 1024 + d);
        __half hh[4];
        hh[0] = __float2half(v.x); hh[1] = __float2half(v.y);
        hh[2] = __float2half(v.z); hh[3] = __float2half(v.w);
        int nb = rr >> 7, r = rr & 127;
        int ch = d >> 5, c16 = (d >> 3) & 3;
        int sw = c16 ^ ((r >> 1) & 3);
        size_t off = ((size_t)(nb * 32 + ch) * 8192) + r * 64 + sw * 16 + (d & 7) * 2;
        *(uint2*)((char*)g_wt + off) = *(uint2*)hh;
    } else if (b < 12544) {
        int i = (b - 12288) * 256 + threadIdx.x;
        float a = pf[i];
        g_cs[2*i]   = cosf(a);
        g_cs[2*i+1] = sinf(a);
    } else {
        // eta: 8 tokens per block
        int t0 = (b - 12544) * 8;
        const float4* xg = (const float4*)(x + (size_t)t0 * 1024);
        for (int i = threadIdx.x; i < 2048; i += 256)
            ((float4*)xs)[i] = xg[i];
        __syncthreads();
        int w = threadIdx.x >> 5, lane = threadIdx.x & 31;
        int t = t0 + w;
        int bb = t >> 11, s = t & 2047, k = s & 15;
        float g = fmaxf(1.f / (float)(k + 1) + gsc[k], 0.f);
        const float4* xr = (const float4*)(xs + w * 1024);
        for (int h = 0; h < 16; h++) {
            const float4* wr = (const float4*)(lrW + h * 1024);
            float acc = 0.f;
            #pragma unroll
            for (int j = 0; j < 8; j++) {
                float4 xv = xr[lane + j * 32];
                float4 wv = __ldg(wr + lane + j * 32);
                acc += xv.x * wv.x + xv.y * wv.y + xv.z * wv.z + xv.w * wv.w;
            }
            #pragma unroll
            for (int off = 16; off; off >>= 1) acc += __shfl_xor_sync(0xffffffffu, acc, off);
            if (lane == 0) {
                float v = 1.f / (1.f + __expf(-(acc + lrb[h])));
                g_eta[((size_t)(bb * Hn + h)) * Sn + s] = v * (1.f / 64.f) * g;
            }
        }
    }
}

// ================= HMMA fp16 GEMM (single x single), bulk-copy, 3-stage =========
// smem: [0,1024) mbars, then 3 buffers of (A 8KB | B 8KB)
#define MG_SMEM (1024 + 3*16384)         // 50176

__device__ __forceinline__ void ldmA(uint32_t r[4], uint32_t addr){
    asm volatile("ldmatrix.sync.aligned.m8n8.x4.shared.b16 {%0,%1,%2,%3}, [%4];"
        : "=r"(r[0]), "=r"(r[1]), "=r"(r[2]), "=r"(r[3]) : "r"(addr));
}
__device__ __forceinline__ void mma16816(float c[4], const uint32_t a[4], const uint32_t b[2]){
    asm volatile("mma.sync.aligned.m16n8k16.row.col.f32.f16.f16.f32 "
        "{%0,%1,%2,%3}, {%4,%5,%6,%7}, {%8,%9}, {%0,%1,%2,%3};"
        : "+f"(c[0]), "+f"(c[1]), "+f"(c[2]), "+f"(c[3])
        : "r"(a[0]), "r"(a[1]), "r"(a[2]), "r"(a[3]), "r"(b[0]), "r"(b[1]));
}

__global__ void __launch_bounds__(256, 2) mma_gemm(
    const __half* __restrict__ At,
    const __half* __restrict__ Bt,
    float* __restrict__ out, int mode)
{
    extern __shared__ char sm[];
    uint32_t smb = smem_u32(sm);
    int tid = threadIdx.x, wid = tid >> 5, lane = tid & 31;
    int bm = blockIdx.y, bn = blockIdx.x;
    int wm = wid >> 2, wn = wid & 3;

    if (tid == 0) { MBAR_INIT(smb + 0, 1); MBAR_INIT(smb + 8, 1); MBAR_INIT(smb + 16, 1); }
    __syncthreads();

    const char* srcA = (const char*)At + (size_t)bm * 32 * 8192;
    const char* srcB = (const char*)Bt + (size_t)bn * 32 * 8192;

    float acc[4][4][4];
    #pragma unroll
    for (int mt = 0; mt < 4; mt++)
        #pragma unroll
        for (int nt = 0; nt < 4; nt++)
            #pragma unroll
            for (int k = 0; k < 4; k++) acc[mt][nt][k] = 0.f;

    uint32_t a_row = wm * 64 + (lane & 15);
    uint32_t a_c   = (lane >> 4) & 1;
    uint32_t sxA   = (a_row >> 1) & 3;
    uint32_t b_row = wn * 32 + (lane & 7) + (((lane >> 4) & 1) << 3);
    uint32_t b_c   = (lane >> 3) & 1;
    uint32_t sxB   = (b_row >> 1) & 3;

    #define ISSUE_BULK(chunk, buf) do { \
        uint32_t mb_ = smb + (buf) * 8; \
        uint32_t dA_ = smb + 1024 + (buf) * 16384; \
        MBAR_EXPECT_TX(mb_, 16384u); \
        BULK_G2S(dA_,        srcA + (size_t)(chunk) * 8192, 8192u, mb_); \
        BULK_G2S(dA_ + 8192, srcB + (size_t)(chunk) * 8192, 8192u, mb_); \
    } while (0)

    if (tid == 0) { ISSUE_BULK(0, 0); ISSUE_BULK(1, 1); }

    for (int i = 0; i < 32; i++) {
        int buf = i % 3;
        if (tid == 0 && i + 2 < 32) ISSUE_BULK(i + 2, (i + 2) % 3);
        MBAR_WAIT(smb + buf * 8, (i / 3) & 1);

        uint32_t bA = smb + 1024 + buf * 16384;
        uint32_t bB = bA + 8192;

        #pragma unroll
        for (int ks = 0; ks < 2; ks++) {
            uint32_t ahf[4][4], bf[4][2];
            uint32_t aoff = ((uint32_t)((ks * 2 + a_c) ^ sxA)) << 4;
            uint32_t boff = ((uint32_t)((ks * 2 + b_c) ^ sxB)) << 4;
            #pragma unroll
            for (int mt = 0; mt < 4; mt++)
                ldmA(ahf[mt], bA + (a_row + mt * 16) * 64 + aoff);
            #pragma unroll
            for (int np = 0; np < 2; np++) {
                uint32_t r4[4];
                ldmA(r4, bB + (b_row + np * 16) * 64 + boff);
                bf[np*2][0] = r4[0]; bf[np*2][1] = r4[1];
                bf[np*2+1][0] = r4[2]; bf[np*2+1][1] = r4[3];
            }
            #pragma unroll
            for (int mt = 0; mt < 4; mt++)
                #pragma unroll
                for (int nt = 0; nt < 4; nt++)
                    mma16816(acc[mt][nt], ahf[mt], bf[nt]);
        }
        __syncthreads();          // all threads done with this buffer before reissue
    }

    // -------- epilogue --------
    int r0 = lane >> 2, c0 = (lane & 3) * 2;
    #pragma unroll
    for (int mt = 0; mt < 4; mt++) {
        #pragma unroll
        for (int half = 0; half < 2; half++) {
            int t = bm * 128 + wm * 64 + mt * 16 + r0 + half * 8;
            int b = t >> 11, s = t & 2047;
            #pragma unroll
            for (int nt = 0; nt < 4; nt++) {
                float v1 = acc[mt][nt][half * 2];
                float v2 = acc[mt][nt][half * 2 + 1];
                int o = bn * 128 + wn * 32 + nt * 8 + c0;
                if (mode == 0) {
                    float2 w; w.x = v1; w.y = v2;
                    *(float2*)(out + (size_t)t * 1024 + o) = w;
                } else {
                    int mat = o >> 10, oin = o & 1023;
                    int h = oin >> 6, hd = oin & 63;
                    float2 cs = *(const float2*)&g_cs[(s * 32 + (hd >> 1)) * 2];
                    float2 w;
                    w.x = v1 * cs.x - v2 * cs.y;
                    w.y = v1 * cs.y + v2 * cs.x;
                    *(float2*)(out + (size_t)mat * SZQ
                               + ((size_t)((b * Hn + h) * Sn + s)) * 64 + hd) = w;
                }
            }
        }
    }
}

// ---------------- scan helpers --------------------------------------------------
__device__ __forceinline__ void warpsum2(float& a, float& b) {
    #pragma unroll
    for (int off = 16; off; off >>= 1) {
        a += __shfl_xor_sync(0xffffffffu, a, off);
        b += __shfl_xor_sync(0xffffffffu, b, off);
    }
}
__device__ __forceinline__ float siluf(float x) {
    return __fdividef(x, 1.f + __expf(-x));
}
// uniform cubic B-spline (cardinal) basis: knots are uniform linspace(-1,1,15)
__device__ __forceinline__ void spline4c(float x, float k0, float invh,
                                         int& ii, float bas[4]) {
    float u = (x - k0) * invh;
    float fi = floorf(u);
    int i = (int)fi;
    float t = u - fi;
    bool uv = (u >= 0.f) && (i < 14);
    ii = uv ? i : 7;
    float t2 = t * t, t3 = t2 * t;
    float omt = 1.f - t;
    bas[0] = omt * omt * omt * (1.f / 6.f);
    bas[1] = 0.5f * t3 - t2 + (2.f / 3.f);
    bas[2] = -0.5f * t3 + 0.5f * t2 + 0.5f * t + (1.f / 6.f);
    bas[3] = t3 * (1.f / 6.f);
    #pragma unroll
    for (int r = 0; r < 4; r++) {
        int j = i - 3 + r;
        bool v = uv && (j >= 0) && (j <= 10);
        bas[r] = v ? bas[r] : 0.f;
    }
}

// ---------------- sequential TTT scan: 1 block per (b,h) ------------------------
#define ROWS17 (17*64)
#define SCAN_SMEM ((ROWS17 + 2*16*ROWS17) * 4)   // 143616 B

__global__ void __launch_bounds__(512) scan_kernel(
    const float* __restrict__ knots, const float* __restrict__ coefficients,
    const float* __restrict__ tgamma, const float* __restrict__ tbeta)
{
    extern __shared__ float smem[];
    float* Wsh = smem;                   // rows 3..13 hold W
    float* cumA = smem + ROWS17;         // 2 buffers of 16*ROWS17

    const float* Qg = g_QKV;
    const float* Kg = g_QKV + SZQ;
    const float* Vg = g_QKV + 2*SZQ;

    int bh = blockIdx.x;
    int b = bh >> 4, h = bh & 15;
    int tid = threadIdx.x, m = tid >> 5, lane = tid & 31;

    for (int e = tid; e < ROWS17; e += 512) {
        int n = (e >> 6) - 3;
        Wsh[e] = (n >= 0 && n <= 10) ? coefficients[h * 704 + n * 64 + (e & 63)] : 0.f;
    }
    for (int mm = 0; mm < 16; mm++) {
        for (int e = tid; e < ROWS17; e += 512) {
            cumA[mm * ROWS17 + e] = 0.f;
            cumA[16 * ROWS17 + mm * ROWS17 + e] = 0.f;
        }
    }

    float k0 = knots[0];
    float invh = 1.f / (knots[1] - knots[0]);

    int d0 = lane, d1 = lane + 32;
    float ga0 = tgamma[h * 64 + d0], ga1 = tgamma[h * 64 + d1];
    float be0 = tbeta[h * 64 + d0],  be1 = tbeta[h * 64 + d1];
    __syncthreads();

    const size_t bhS = (size_t)bh * Sn;

    int s = m;
    size_t base = (bhS + s) * 64;
    float K0 = Kg[base + d0], K1 = Kg[base + d1];
    float V0 = Vg[base + d0], V1 = Vg[base + d1];
    float Q0 = Qg[base + d0], Q1 = Qg[base + d1];
    float et = g_eta[bhS + s];

    for (int nmb = 0; nmb < NMBn; nmb++) {
        int buf = nmb & 1;
        float* cumB = cumA + buf * (16 * ROWS17);
        float* cm   = cumB + m * ROWS17;

        float nK0 = 0.f, nK1 = 0.f, nV0 = 0.f, nV1 = 0.f, nQ0 = 0.f, nQ1 = 0.f, nEt = 0.f;
        if (nmb + 1 < NMBn) {
            size_t nb = (bhS + s + 16) * 64;
            nK0 = Kg[nb + d0]; nK1 = Kg[nb + d1];
            nV0 = Vg[nb + d0]; nV1 = Vg[nb + d1];
            nQ0 = Qg[nb + d0]; nQ1 = Qg[nb + d1];
            nEt = g_eta[bhS + s + 16];
        }

        // ---- Phase A: Zk, LN-l2-bwd, tok ----
        int ii0, ii1; float bk0[4], bk1[4];
        spline4c(K0, k0, invh, ii0, bk0);
        spline4c(K1, k0, invh, ii1, bk1);
        float Zk0 = siluf(K0), Zk1 = siluf(K1);
        #pragma unroll
        for (int r = 0; r < 4; r++) {
            Zk0 += bk0[r] * Wsh[(ii0 + r) * 64 + d0];
            Zk1 += bk1[r] * Wsh[(ii1 + r) * 64 + d1];
        }
        float s1 = Zk0 + Zk1, s2 = Zk0 * Zk0 + Zk1 * Zk1;
        warpsum2(s1, s2);
        float mu = s1 * (1.f / 64.f);
        float var = s2 * (1.f / 64.f) - mu * mu;
        float rstd = rsqrtf(var + EPSc);
        float xh0 = (Zk0 - mu) * rstd, xh1 = (Zk1 - mu) * rstd;
        float gr0 = (ga0 * xh0 + be0 - (V0 - K0)) * ga0;
        float gr1 = (ga1 * xh1 + be1 - (V1 - K1)) * ga1;
        float t1 = gr0 + gr1, t2 = gr0 * xh0 + gr1 * xh1;
        warpsum2(t1, t2);
        float mg = t1 * (1.f / 64.f), mgx = t2 * (1.f / 64.f);
        float e0 = et * (gr0 - mg - xh0 * mgx) * rstd;
        float e1 = et * (gr1 - mg - xh1 * mgx) * rstd;

        #pragma unroll
        for (int n = 3; n < 14; n++) {
            cm[n * 64 + d0] = 0.f;
            cm[n * 64 + d1] = 0.f;
        }
        #pragma unroll
        for (int r = 0; r < 4; r++) {
            cm[(ii0 + r) * 64 + d0] = bk0[r] * e0;
            cm[(ii1 + r) * 64 + d1] = bk1[r] * e1;
        }
        __syncthreads();               // A -> B

        // ---- Phase B: float4 cumsum over m; store W_old - cum[m]; update W ----
        if (tid < 176) {
            int e = 192 + tid * 4;
            float4 Wv = *(float4*)&Wsh[e];
            float4 acc = make_float4(0.f, 0.f, 0.f, 0.f);
            #pragma unroll
            for (int mm = 0; mm < 16; mm++) {
                float4 v = *(float4*)&cumB[mm * ROWS17 + e];
                acc.x += v.x; acc.y += v.y; acc.z += v.z; acc.w += v.w;
                float4 w;
                w.x = Wv.x - acc.x; w.y = Wv.y - acc.y;
                w.z = Wv.z - acc.z; w.w = Wv.w - acc.w;
                *(float4*)&cumB[mm * ROWS17 + e] = w;
            }
            Wv.x -= acc.x; Wv.y -= acc.y; Wv.z -= acc.z; Wv.w -= acc.w;
            *(float4*)&Wsh[e] = Wv;
        }
        __syncthreads();               // B -> C

        // ---- Phase C: Zq = silu(Q) + basQ . (W_old - cum[m]) ----
        int iq0, iq1; float bq0[4], bq1[4];
        spline4c(Q0, k0, invh, iq0, bq0);
        spline4c(Q1, k0, invh, iq1, bq1);
        float Zq0 = siluf(Q0), Zq1 = siluf(Q1);
        #pragma unroll
        for (int r = 0; r < 4; r++) {
            Zq0 += bq0[r] * cm[(iq0 + r) * 64 + d0];
            Zq1 += bq1[r] * cm[(iq1 + r) * 64 + d1];
        }
        float u1 = Zq0 + Zq1, u2 = Zq0 * Zq0 + Zq1 * Zq1;
        warpsum2(u1, u2);
        float mu2 = u1 * (1.f / 64.f);
        float var2 = u2 * (1.f / 64.f) - mu2 * mu2;
        float rstd2 = rsqrtf(var2 + EPSc);
        float y0 = Q0 + ga0 * (Zq0 - mu2) * rstd2 + be0;
        float y1 = Q1 + ga1 * (Zq1 - mu2) * rstd2 + be1;
        float* yp = g_y + ((size_t)b * Sn + s) * DIMn + h * 64;
        yp[d0] = y0;
        yp[d1] = y1;

        K0 = nK0; K1 = nK1; V0 = nV0; V1 = nV1; Q0 = nQ0; Q1 = nQ1; et = nEt;
        s += 16;
    }
}

// ---------------- post layernorm -> fp16 tiled-swizzled --------------------------
__global__ void __launch_bounds__(256) postln_kernel(
    const float* __restrict__ pw, const float* __restrict__ pb)
{
    __shared__ float r1[8], r2[8];
    int t = blockIdx.x;
    const float* xr = g_y + (size_t)t * 1024;
    int d = threadIdx.x * 4;
    float4 v = *(const float4*)(xr + d);
    float s1 = v.x + v.y + v.z + v.w;
    float s2 = v.x * v.x + v.y * v.y + v.z * v.z + v.w * v.w;
    #pragma unroll
    for (int off = 16; off; off >>= 1) {
        s1 += __shfl_xor_sync(0xffffffffu, s1, off);
        s2 += __shfl_xor_sync(0xffffffffu, s2, off);
    }
    int w = threadIdx.x >> 5, lane = threadIdx.x & 31;
    if (lane == 0) { r1[w] = s1; r2[w] = s2; }
    __syncthreads();
    float S1 = 0.f, S2 = 0.f;
    #pragma unroll
    for (int i = 0; i < 8; i++) { S1 += r1[i]; S2 += r2[i]; }
    float mu = S1 * (1.f / 1024.f);
    float var = S2 * (1.f / 1024.f) - mu * mu;
    float rstd = rsqrtf(var + EPSc);
    float4 w4 = *(const float4*)(pw + d);
    float4 b4 = *(const float4*)(pb + d);
    __half hh[4];
    hh[0] = __float2half((v.x - mu) * rstd * w4.x + b4.x);
    hh[1] = __float2half((v.y - mu) * rstd * w4.y + b4.y);
    hh[2] = __float2half((v.z - mu) * rstd * w4.z + b4.z);
    hh[3] = __float2half((v.w - mu) * rstd * w4.w + b4.w);
    int rb = t >> 7, r = t & 127;
    int ch = d >> 5, c16 = (d >> 3) & 3;
    int sw = c16 ^ ((r >> 1) & 3);
    size_t off = ((size_t)(rb * 32 + ch) * 8192) + r * 64 + sw * 16 + (d & 7) * 2;
    *(uint2*)((char*)g_lt + off) = *(uint2*)hh;
}

// ---------------- launch --------------------------------------------------------
extern "C" void kernel_launch(void* const* d_in, const int* in_sizes, int n_in,
                              void* d_out, int out_size)
{
    const float* x     = (const float*)d_in[0];
    const float* pf    = (const float*)d_in[1];
    const float* Wq    = (const float*)d_in[2];
    const float* Wk    = (const float*)d_in[3];
    const float* Wv    = (const float*)d_in[4];
    const float* Wo    = (const float*)d_in[5];
    const float* lrW   = (const float*)d_in[6];
    const float* lrb   = (const float*)d_in[7];
    const float* gsc   = (const float*)d_in[8];
    const float* tg    = (const float*)d_in[9];
    const float* tb    = (const float*)d_in[10];
    const float* pw    = (const float*)d_in[11];
    const float* pb    = (const float*)d_in[12];
    const float* coefs = (const float*)d_in[13];
    const float* knots = (const float*)d_in[14];
    float* out = (float*)d_out;

    float *QKVp;
    __half *xt, *wt, *lt;
    cudaGetSymbolAddress((void**)&QKVp, g_QKV);
    cudaGetSymbolAddress((void**)&xt, g_xt);
    cudaGetSymbolAddress((void**)&wt, g_wt);
    cudaGetSymbolAddress((void**)&lt, g_lt);

    cudaFuncSetAttribute(mma_gemm, cudaFuncAttributeMaxDynamicSharedMemorySize,
                         MG_SMEM);
    cudaFuncSetAttribute(scan_kernel, cudaFuncAttributeMaxDynamicSharedMemorySize,
                         SCAN_SMEM);

    setup_kernel<<<13568, 256>>>(x, Wq, Wk, Wv, Wo, pf, lrW, lrb, gsc);

    // fused QKV GEMM: nb blocks 0..23 (Wq,Wk,Wv rows)
    dim3 gq(24, 64);
    mma_gemm<<<gq, 256, MG_SMEM>>>(xt, wt, QKVp, 1);

    scan_kernel<<<Bn * Hn, 512, SCAN_SMEM>>>(knots, coefs, tg, tb);

    postln_kernel<<<NTOK, 256>>>(pw, pb);
    // Wo GEMM: nb blocks 24..31 (tile = 4096 halfs)
    dim3 go(8, 64);
    mma_gemm<<<go, 256, MG_SMEM>>>(lt, wt + (size_t)24 * 32 * 4096, out, 0);
}